// round 1
// baseline (speedup 1.0000x reference)
#include <cuda_runtime.h>
#include <math.h>

#define BB 4
#define SS 2048
#define DD 512
#define HH 8
#define DKV 64
#define BSN (BB*SS)

// ---------------- scratch (device globals; no allocation allowed) ----------
__device__ float g_qh[BB*HH*SS*DKV];   // 16 MB, [b,h,s,dk]
__device__ float g_kh[BB*HH*SS*DKV];
__device__ float g_vh[BB*HH*SS*DKV];
__device__ float g_rowsum[BB*HH*SS];
__device__ float g_oh[BB*HH*SS*DKV];   // attn@V, head layout
__device__ float g_y[BB*SS*DD];        // pre-layernorm

// ---------------- kernel 1: fused QKV projections ---------------------------
// X[8192,512] @ W[512,512] -> head layout [b,h,s,64]. z selects q/k/v.
__global__ void proj_kernel(const float* __restrict__ q, const float* __restrict__ k,
                            const float* __restrict__ v, const float* __restrict__ Wq,
                            const float* __restrict__ Wk, const float* __restrict__ Wv) {
    __shared__ float As[64][17];
    __shared__ float Bs[16][68];

    const float* X; const float* W; float* Y;
    if (blockIdx.z == 0)      { X = q; W = Wq; Y = g_qh; }
    else if (blockIdx.z == 1) { X = k; W = Wk; Y = g_kh; }
    else                      { X = v; W = Wv; Y = g_vh; }

    const int row0 = blockIdx.y * 64;
    const int col0 = blockIdx.x * 64;
    const int tx = threadIdx.x, ty = threadIdx.y;
    const int tid = ty * 16 + tx;

    float acc[4][4] = {};
    for (int k0 = 0; k0 < DD; k0 += 16) {
        {   // A: 64 rows x 16 k
            int r  = tid >> 2;
            int kk = (tid & 3) << 2;
            float4 a = *reinterpret_cast<const float4*>(X + (size_t)(row0 + r) * DD + k0 + kk);
            As[r][kk] = a.x; As[r][kk+1] = a.y; As[r][kk+2] = a.z; As[r][kk+3] = a.w;
        }
        {   // B: 16 k x 64 cols
            int kk = tid >> 4;
            int c  = (tid & 15) << 2;
            float4 b = *reinterpret_cast<const float4*>(W + (size_t)(k0 + kk) * DD + col0 + c);
            Bs[kk][c] = b.x; Bs[kk][c+1] = b.y; Bs[kk][c+2] = b.z; Bs[kk][c+3] = b.w;
        }
        __syncthreads();
        #pragma unroll
        for (int kk = 0; kk < 16; kk++) {
            float a[4], bvals[4];
            #pragma unroll
            for (int i = 0; i < 4; i++) a[i] = As[ty*4 + i][kk];
            #pragma unroll
            for (int j = 0; j < 4; j++) bvals[j] = Bs[kk][tx*4 + j];
            #pragma unroll
            for (int i = 0; i < 4; i++)
                #pragma unroll
                for (int j = 0; j < 4; j++)
                    acc[i][j] = fmaf(a[i], bvals[j], acc[i][j]);
        }
        __syncthreads();
    }
    #pragma unroll
    for (int i = 0; i < 4; i++) {
        int row = row0 + ty*4 + i;
        int b   = row / SS, s = row % SS;
        #pragma unroll
        for (int j = 0; j < 4; j++) {
            int col = col0 + tx*4 + j;
            int h = col >> 6, dk = col & 63;
            Y[(((size_t)(b*HH + h) * SS + s) << 6) + dk] = acc[i][j];
        }
    }
}

// ---------------- kernel 2: scores -> exp -> attn(unnorm) + rowsums ---------
__global__ void score_kernel(const int* __restrict__ mask, float* __restrict__ attn) {
    __shared__ float Qs[64][65];
    __shared__ float Ks[64][65];
    __shared__ float red[64][17];
    __shared__ int   mrow[64];
    __shared__ int   mcol[64];

    const int bh   = blockIdx.y;
    const int b    = bh / HH;
    const int row0 = blockIdx.x * 64;
    const int tx = threadIdx.x, ty = threadIdx.y;
    const int tid = ty * 16 + tx;

    const float* qbase = g_qh + (size_t)bh * SS * DKV;
    const float* kbase = g_kh + (size_t)bh * SS * DKV;

    #pragma unroll
    for (int it = 0; it < 4; it++) {
        int r = (tid >> 4) + it * 16;
        int c = (tid & 15) << 2;
        float4 a = *reinterpret_cast<const float4*>(qbase + (size_t)(row0 + r) * DKV + c);
        Qs[r][c] = a.x; Qs[r][c+1] = a.y; Qs[r][c+2] = a.z; Qs[r][c+3] = a.w;
    }
    if (tid < 64) mrow[tid] = mask[b * SS + row0 + tid];

    float sums[4] = {0.f, 0.f, 0.f, 0.f};

    for (int j0 = 0; j0 < SS; j0 += 64) {
        __syncthreads();   // previous tile's compute done (and Qs ready on iter 0)
        if (tid < 64) mcol[tid] = mask[b * SS + j0 + tid];
        #pragma unroll
        for (int it = 0; it < 4; it++) {
            int r = (tid >> 4) + it * 16;
            int c = (tid & 15) << 2;
            float4 a = *reinterpret_cast<const float4*>(kbase + (size_t)(j0 + r) * DKV + c);
            Ks[r][c] = a.x; Ks[r][c+1] = a.y; Ks[r][c+2] = a.z; Ks[r][c+3] = a.w;
        }
        __syncthreads();

        float acc[4][4] = {};
        #pragma unroll
        for (int d = 0; d < 64; d++) {
            float a[4], bvals[4];
            #pragma unroll
            for (int i = 0; i < 4; i++) a[i] = Qs[ty*4 + i][d];
            #pragma unroll
            for (int j = 0; j < 4; j++) bvals[j] = Ks[tx*4 + j][d];
            #pragma unroll
            for (int i = 0; i < 4; i++)
                #pragma unroll
                for (int j = 0; j < 4; j++)
                    acc[i][j] = fmaf(a[i], bvals[j], acc[i][j]);
        }

        #pragma unroll
        for (int i = 0; i < 4; i++) {
            int ig = row0 + ty*4 + i;
            float p[4];
            #pragma unroll
            for (int j = 0; j < 4; j++) {
                int jg = j0 + tx*4 + j;
                bool ok = ((mrow[ty*4 + i] != 0) && (mcol[tx*4 + j] != 0)) || (ig == jg);
                float sc = ok ? acc[i][j] * 0.125f : -1e-9f;
                p[j] = expf(sc);
                sums[i] += p[j];
            }
            float4 pv = make_float4(p[0], p[1], p[2], p[3]);
            *reinterpret_cast<float4*>(attn + ((size_t)bh * SS + ig) * SS + j0 + tx*4) = pv;
        }
    }
    __syncthreads();
    #pragma unroll
    for (int i = 0; i < 4; i++) red[ty*4 + i][tx] = sums[i];
    __syncthreads();
    if (tid < 64) {
        float s = 0.f;
        #pragma unroll
        for (int t = 0; t < 16; t++) s += red[tid][t];
        g_rowsum[(size_t)bh * SS + row0 + tid] = s;
    }
}

// ---------------- kernel 3: normalize attn in-place + attn@V ----------------
__global__ void pv_kernel(float* __restrict__ attn) {
    __shared__ float Ps[64][65];
    __shared__ float Vs[64][65];
    __shared__ float inv[64];

    const int bh   = blockIdx.y;
    const int row0 = blockIdx.x * 64;
    const int tx = threadIdx.x, ty = threadIdx.y;
    const int tid = ty * 16 + tx;

    const float* vbase = g_vh + (size_t)bh * SS * DKV;

    if (tid < 64) inv[tid] = 1.0f / g_rowsum[(size_t)bh * SS + row0 + tid];
    __syncthreads();

    float acc[4][4] = {};
    for (int j0 = 0; j0 < SS; j0 += 64) {
        __syncthreads();
        #pragma unroll
        for (int it = 0; it < 4; it++) {
            int r = (tid >> 4) + it * 16;
            int c = (tid & 15) << 2;
            size_t g = ((size_t)bh * SS + row0 + r) * SS + j0 + c;
            float4 p = *reinterpret_cast<const float4*>(attn + g);
            float iv = inv[r];
            p.x *= iv; p.y *= iv; p.z *= iv; p.w *= iv;
            *reinterpret_cast<float4*>(attn + g) = p;   // write normalized attn output
            Ps[r][c] = p.x; Ps[r][c+1] = p.y; Ps[r][c+2] = p.z; Ps[r][c+3] = p.w;
        }
        #pragma unroll
        for (int it = 0; it < 4; it++) {
            int r = (tid >> 4) + it * 16;
            int c = (tid & 15) << 2;
            float4 a = *reinterpret_cast<const float4*>(vbase + (size_t)(j0 + r) * DKV + c);
            Vs[r][c] = a.x; Vs[r][c+1] = a.y; Vs[r][c+2] = a.z; Vs[r][c+3] = a.w;
        }
        __syncthreads();

        #pragma unroll
        for (int kk = 0; kk < 64; kk++) {
            float a[4], bvals[4];
            #pragma unroll
            for (int i = 0; i < 4; i++) a[i] = Ps[ty*4 + i][kk];
            #pragma unroll
            for (int j = 0; j < 4; j++) bvals[j] = Vs[kk][tx*4 + j];
            #pragma unroll
            for (int i = 0; i < 4; i++)
                #pragma unroll
                for (int j = 0; j < 4; j++)
                    acc[i][j] = fmaf(a[i], bvals[j], acc[i][j]);
        }
    }
    #pragma unroll
    for (int i = 0; i < 4; i++) {
        float4 o = make_float4(acc[i][0], acc[i][1], acc[i][2], acc[i][3]);
        *reinterpret_cast<float4*>(g_oh + ((size_t)bh * SS + row0 + ty*4 + i) * DKV + tx*4) = o;
    }
}

// ---------------- kernel 4: O @ Wo + residual -------------------------------
__global__ void out_proj_kernel(const float* __restrict__ q, const float* __restrict__ Wo) {
    __shared__ float As[64][17];
    __shared__ float Bs[16][68];

    const int row0 = blockIdx.y * 64;
    const int col0 = blockIdx.x * 64;
    const int tx = threadIdx.x, ty = threadIdx.y;
    const int tid = ty * 16 + tx;

    float acc[4][4] = {};
    for (int k0 = 0; k0 < DD; k0 += 16) {
        {   // gather A from head layout: k index -> (h, dv)
            int r  = tid >> 2;
            int kk = (tid & 3) << 2;
            int row = row0 + r;
            int b = row / SS, s = row % SS;
            int kc = k0 + kk;
            int h = kc >> 6, dv = kc & 63;
            float4 a = *reinterpret_cast<const float4*>(
                g_oh + (((size_t)(b*HH + h) * SS + s) << 6) + dv);
            As[r][kk] = a.x; As[r][kk+1] = a.y; As[r][kk+2] = a.z; As[r][kk+3] = a.w;
        }
        {
            int kk = tid >> 4;
            int c  = (tid & 15) << 2;
            float4 b = *reinterpret_cast<const float4*>(Wo + (size_t)(k0 + kk) * DD + col0 + c);
            Bs[kk][c] = b.x; Bs[kk][c+1] = b.y; Bs[kk][c+2] = b.z; Bs[kk][c+3] = b.w;
        }
        __syncthreads();
        #pragma unroll
        for (int kk = 0; kk < 16; kk++) {
            float a[4], bvals[4];
            #pragma unroll
            for (int i = 0; i < 4; i++) a[i] = As[ty*4 + i][kk];
            #pragma unroll
            for (int j = 0; j < 4; j++) bvals[j] = Bs[kk][tx*4 + j];
            #pragma unroll
            for (int i = 0; i < 4; i++)
                #pragma unroll
                for (int j = 0; j < 4; j++)
                    acc[i][j] = fmaf(a[i], bvals[j], acc[i][j]);
        }
        __syncthreads();
    }
    #pragma unroll
    for (int i = 0; i < 4; i++) {
        int row = row0 + ty*4 + i;
        size_t base = (size_t)row * DD + col0 + tx*4;
        float4 r = *reinterpret_cast<const float4*>(q + base);   // residual
        r.x += acc[i][0]; r.y += acc[i][1]; r.z += acc[i][2]; r.w += acc[i][3];
        *reinterpret_cast<float4*>(g_y + base) = r;
    }
}

// ---------------- kernel 5: LayerNorm ---------------------------------------
__global__ void ln_kernel(const float* __restrict__ gamma, const float* __restrict__ beta,
                          float* __restrict__ out) {
    const int row = blockIdx.x;
    const float* x = g_y + (size_t)row * DD;
    const int t = threadIdx.x;   // 256 threads, 2 elems each

    float v0 = x[t], v1 = x[t + 256];
    float s  = v0 + v1;
    float sq = v0*v0 + v1*v1;

    __shared__ float ssum[8], ssq[8];
    #pragma unroll
    for (int off = 16; off > 0; off >>= 1) {
        s  += __shfl_down_sync(0xffffffffu, s,  off);
        sq += __shfl_down_sync(0xffffffffu, sq, off);
    }
    if ((t & 31) == 0) { ssum[t >> 5] = s; ssq[t >> 5] = sq; }
    __syncthreads();
    if (t < 32) {
        float a = (t < 8) ? ssum[t] : 0.f;
        float b = (t < 8) ? ssq[t]  : 0.f;
        #pragma unroll
        for (int off = 4; off > 0; off >>= 1) {
            a += __shfl_down_sync(0xffffffffu, a, off);
            b += __shfl_down_sync(0xffffffffu, b, off);
        }
        if (t == 0) { ssum[0] = a; ssq[0] = b; }
    }
    __syncthreads();
    float mean = ssum[0] * (1.0f / DD);
    float var  = ssq[0]  * (1.0f / DD) - mean * mean;
    float rs   = rsqrtf(var + 1e-6f);

    out[(size_t)row * DD + t]       = (v0 - mean) * rs * gamma[t]       + beta[t];
    out[(size_t)row * DD + t + 256] = (v1 - mean) * rs * gamma[t + 256] + beta[t + 256];
}

// ---------------- launch -----------------------------------------------------
extern "C" void kernel_launch(void* const* d_in, const int* in_sizes, int n_in,
                              void* d_out, int out_size) {
    const float* q     = (const float*)d_in[0];
    const float* k     = (const float*)d_in[1];
    const float* v     = (const float*)d_in[2];
    const int*   mask  = (const int*)  d_in[3];
    const float* Wq    = (const float*)d_in[4];
    const float* Wk    = (const float*)d_in[5];
    const float* Wv    = (const float*)d_in[6];
    const float* Wo    = (const float*)d_in[7];
    const float* gamma = (const float*)d_in[8];
    const float* beta  = (const float*)d_in[9];

    float* out  = (float*)d_out;                  // [B,S,D]
    float* attn = out + (size_t)BB * SS * DD;     // [B,H,S,S]

    dim3 blk(16, 16);

    proj_kernel<<<dim3(DD/64, BSN/64, 3), blk>>>(q, k, v, Wq, Wk, Wv);
    score_kernel<<<dim3(SS/64, BB*HH), blk>>>(mask, attn);
    pv_kernel<<<dim3(SS/64, BB*HH), blk>>>(attn);
    out_proj_kernel<<<dim3(DD/64, BSN/64), blk>>>(q, Wo);
    ln_kernel<<<BSN, 256>>>(gamma, beta, out);
}

// round 2
// speedup vs baseline: 1.3299x; 1.3299x over previous
#include <cuda_runtime.h>
#include <math.h>

#define BB 4
#define SS 2048
#define DD 512
#define HH 8
#define BH (BB*HH)
#define BSN (BB*SS)

// ---------------- scratch (device globals; no allocation allowed) ----------
__device__ float g_qh[(size_t)BH*SS*64];   // [bh, s, 64]
__device__ float g_kh[(size_t)BH*SS*64];
__device__ float g_vh[(size_t)BH*SS*64];
__device__ float g_oh[(size_t)BH*SS*64];
__device__ float g_y[(size_t)BSN*DD];

// ---------------- tf32 helpers ----------------------------------------------
__device__ __forceinline__ float tf32r(float x) {
    unsigned u;
    asm("cvt.rna.tf32.f32 %0, %1;" : "=r"(u) : "f"(x));
    return __uint_as_float(u);
}

__device__ __forceinline__ void mma_tf32(float c[4],
        float a0, float a1, float a2, float a3, float b0, float b1) {
    asm("mma.sync.aligned.m16n8k8.row.col.f32.tf32.tf32.f32 "
        "{%0,%1,%2,%3},{%4,%5,%6,%7},{%8,%9},{%0,%1,%2,%3};"
        : "+f"(c[0]), "+f"(c[1]), "+f"(c[2]), "+f"(c[3])
        : "r"(__float_as_uint(a0)), "r"(__float_as_uint(a1)),
          "r"(__float_as_uint(a2)), "r"(__float_as_uint(a3)),
          "r"(__float_as_uint(b0)), "r"(__float_as_uint(b1)));
}

// ---------------- kernel 1: fused QKV projections (split-tf32) --------------
// X[8192,512] @ W[512,512] -> head layout [bh, s, 64]. 128x128 block tile.
__global__ __launch_bounds__(256) void proj_kernel(
        const float* __restrict__ q, const float* __restrict__ k,
        const float* __restrict__ v, const float* __restrict__ Wq,
        const float* __restrict__ Wk, const float* __restrict__ Wv) {
    __shared__ float Ash[128][20];
    __shared__ float Asl[128][20];
    __shared__ float Bsh[16][136];
    __shared__ float Bsl[16][136];

    const float* X; const float* W; float* Y;
    if (blockIdx.z == 0)      { X = q; W = Wq; Y = g_qh; }
    else if (blockIdx.z == 1) { X = k; W = Wk; Y = g_kh; }
    else                      { X = v; W = Wv; Y = g_vh; }

    const int row0 = blockIdx.y * 128, col0 = blockIdx.x * 128;
    const int tid = threadIdx.x, lane = tid & 31, warp = tid >> 5;
    const int g = lane >> 2, t = lane & 3;
    const int wm = warp & 3, wn = warp >> 2;

    float acc[2][8][4] = {};

    const int ar = tid >> 1, acb = (tid & 1) << 3;
    const int bkr = tid >> 4, bcb = (tid & 15) << 3;

    for (int k0 = 0; k0 < DD; k0 += 16) {
        __syncthreads();
        {
            const float* src = X + (size_t)(row0 + ar) * DD + k0 + acb;
            float4 v0 = *(const float4*)src;
            float4 v1 = *(const float4*)(src + 4);
            float xs[8] = {v0.x, v0.y, v0.z, v0.w, v1.x, v1.y, v1.z, v1.w};
            #pragma unroll
            for (int i = 0; i < 8; i++) {
                float hi = tf32r(xs[i]);
                Ash[ar][acb + i] = hi;
                Asl[ar][acb + i] = tf32r(xs[i] - hi);
            }
        }
        {
            const float* src = W + (size_t)(k0 + bkr) * DD + col0 + bcb;
            float4 v0 = *(const float4*)src;
            float4 v1 = *(const float4*)(src + 4);
            float xs[8] = {v0.x, v0.y, v0.z, v0.w, v1.x, v1.y, v1.z, v1.w};
            #pragma unroll
            for (int i = 0; i < 8; i++) {
                float hi = tf32r(xs[i]);
                Bsh[bkr][bcb + i] = hi;
                Bsl[bkr][bcb + i] = tf32r(xs[i] - hi);
            }
        }
        __syncthreads();
        #pragma unroll
        for (int s = 0; s < 2; s++) {
            const int kb = s * 8;
            float ah[2][4], al[2][4];
            #pragma unroll
            for (int mt = 0; mt < 2; mt++) {
                int r = wm * 32 + mt * 16 + g;
                ah[mt][0] = Ash[r][kb + t];       al[mt][0] = Asl[r][kb + t];
                ah[mt][1] = Ash[r + 8][kb + t];   al[mt][1] = Asl[r + 8][kb + t];
                ah[mt][2] = Ash[r][kb + t + 4];   al[mt][2] = Asl[r][kb + t + 4];
                ah[mt][3] = Ash[r + 8][kb + t + 4]; al[mt][3] = Asl[r + 8][kb + t + 4];
            }
            #pragma unroll
            for (int nt = 0; nt < 8; nt++) {
                int c = wn * 64 + nt * 8 + g;
                float bh0 = Bsh[kb + t][c], bh1 = Bsh[kb + t + 4][c];
                float bl0 = Bsl[kb + t][c], bl1 = Bsl[kb + t + 4][c];
                #pragma unroll
                for (int mt = 0; mt < 2; mt++) {
                    mma_tf32(acc[mt][nt], ah[mt][0], ah[mt][1], ah[mt][2], ah[mt][3], bh0, bh1);
                    mma_tf32(acc[mt][nt], ah[mt][0], ah[mt][1], ah[mt][2], ah[mt][3], bl0, bl1);
                    mma_tf32(acc[mt][nt], al[mt][0], al[mt][1], al[mt][2], al[mt][3], bh0, bh1);
                }
            }
        }
    }
    const int bidx = row0 >> 11;    // 128-row tile never crosses a batch boundary
    #pragma unroll
    for (int mt = 0; mt < 2; mt++) {
        int r0 = row0 + wm * 32 + mt * 16 + g;
        int s0 = r0 & 2047;
        #pragma unroll
        for (int nt = 0; nt < 8; nt++) {
            int col = col0 + wn * 64 + nt * 8 + 2 * t;
            int h = col >> 6, dk = col & 63;
            float* dst0 = Y + (((size_t)(bidx * HH + h) * SS + s0) << 6) + dk;
            float* dst1 = Y + (((size_t)(bidx * HH + h) * SS + s0 + 8) << 6) + dk;
            *(float2*)dst0 = make_float2(acc[mt][nt][0], acc[mt][nt][1]);
            *(float2*)dst1 = make_float2(acc[mt][nt][2], acc[mt][nt][3]);
        }
    }
}

// ---------------- kernel 2: fused scores+softmax+attn-write+PV --------------
// Per block: 128 q-rows of one (b,h). Pass 1: rowsums. Pass 2: normalized attn
// written once + O = P@V accumulated on tensor pipe.
#define ATTN_SMEM ((128*72*3 + 128*136 + 128 + 128)*4 + 256*4)

__global__ __launch_bounds__(256) void attn_kernel(const int* __restrict__ mask,
                                                   float* __restrict__ attn) {
    extern __shared__ float sm[];
    float* Qs     = sm;                    // 128*72, tf32
    float* Ks     = Qs + 128 * 72;         // 128*72, tf32
    float* Vs     = Ks + 128 * 72;         // 128*72, tf32
    float* Ps     = Vs + 128 * 72;         // 128*136, tf32
    float* invs   = Ps + 128 * 136;        // 128
    float* rowsum = invs + 128;            // 128
    int*   mrow   = (int*)(rowsum + 128);  // 128
    int*   mcol   = mrow + 128;            // 128

    const int bh = blockIdx.y, b = bh >> 3;
    const int row0 = blockIdx.x * 128;
    const int tid = threadIdx.x, lane = tid & 31, warp = tid >> 5;
    const int g = lane >> 2, t = lane & 3;
    const int wm = warp & 3, wn = warp >> 2;

    const float* qbase = g_qh + (size_t)bh * SS * 64;
    const float* kbase = g_kh + (size_t)bh * SS * 64;
    const float* vbase = g_vh + (size_t)bh * SS * 64;

    #pragma unroll
    for (int e = tid; e < 128 * 16; e += 256) {
        int r = e >> 4, c = (e & 15) << 2;
        float4 x = *(const float4*)(qbase + ((size_t)(row0 + r) << 6) + c);
        Qs[r*72+c] = tf32r(x.x); Qs[r*72+c+1] = tf32r(x.y);
        Qs[r*72+c+2] = tf32r(x.z); Qs[r*72+c+3] = tf32r(x.w);
    }
    if (tid < 128) { mrow[tid] = mask[b * SS + row0 + tid]; rowsum[tid] = 0.f; }

    float rp0[2] = {0.f, 0.f};
    float rp1[2] = {0.f, 0.f};

    // ---------------- PASS 1: rowsums -------------------------------------
    #pragma unroll 1
    for (int j0 = 0; j0 < SS; j0 += 128) {
        __syncthreads();
        #pragma unroll
        for (int e = tid; e < 128 * 16; e += 256) {
            int r = e >> 4, c = (e & 15) << 2;
            float4 x = *(const float4*)(kbase + ((size_t)(j0 + r) << 6) + c);
            Ks[r*72+c] = tf32r(x.x); Ks[r*72+c+1] = tf32r(x.y);
            Ks[r*72+c+2] = tf32r(x.z); Ks[r*72+c+3] = tf32r(x.w);
        }
        if (tid < 128) mcol[tid] = mask[b * SS + j0 + tid];
        __syncthreads();

        float acc[2][8][4] = {};
        #pragma unroll
        for (int s = 0; s < 8; s++) {
            int kb = s * 8;
            float a[2][4];
            #pragma unroll
            for (int mt = 0; mt < 2; mt++) {
                int r = wm * 32 + mt * 16 + g;
                a[mt][0] = Qs[r*72 + kb + t];       a[mt][1] = Qs[(r+8)*72 + kb + t];
                a[mt][2] = Qs[r*72 + kb + t + 4];   a[mt][3] = Qs[(r+8)*72 + kb + t + 4];
            }
            #pragma unroll
            for (int nt = 0; nt < 8; nt++) {
                int c = wn * 64 + nt * 8 + g;
                float b0 = Ks[c*72 + kb + t], b1 = Ks[c*72 + kb + t + 4];
                #pragma unroll
                for (int mt = 0; mt < 2; mt++)
                    mma_tf32(acc[mt][nt], a[mt][0], a[mt][1], a[mt][2], a[mt][3], b0, b1);
            }
        }
        #pragma unroll
        for (int mt = 0; mt < 2; mt++) {
            int lr0 = wm * 32 + mt * 16 + g, lr1 = lr0 + 8;
            int m0 = mrow[lr0], m1 = mrow[lr1];
            int gr0 = row0 + lr0, gr1 = row0 + lr1;
            #pragma unroll
            for (int nt = 0; nt < 8; nt++) {
                int lc = wn * 64 + nt * 8 + 2 * t;
                int gc = j0 + lc;
                int mc0 = mcol[lc], mc1 = mcol[lc + 1];
                float p00 = ((m0 && mc0) || (gr0 == gc))     ? __expf(acc[mt][nt][0] * 0.125f) : 1.0f;
                float p01 = ((m0 && mc1) || (gr0 == gc + 1)) ? __expf(acc[mt][nt][1] * 0.125f) : 1.0f;
                float p10 = ((m1 && mc0) || (gr1 == gc))     ? __expf(acc[mt][nt][2] * 0.125f) : 1.0f;
                float p11 = ((m1 && mc1) || (gr1 == gc + 1)) ? __expf(acc[mt][nt][3] * 0.125f) : 1.0f;
                rp0[mt] += p00 + p01;
                rp1[mt] += p10 + p11;
            }
        }
    }
    #pragma unroll
    for (int mt = 0; mt < 2; mt++) {
        float s0 = rp0[mt], s1 = rp1[mt];
        s0 += __shfl_xor_sync(0xffffffffu, s0, 1); s0 += __shfl_xor_sync(0xffffffffu, s0, 2);
        s1 += __shfl_xor_sync(0xffffffffu, s1, 1); s1 += __shfl_xor_sync(0xffffffffu, s1, 2);
        if (t == 0) {
            atomicAdd(&rowsum[wm * 32 + mt * 16 + g], s0);
            atomicAdd(&rowsum[wm * 32 + mt * 16 + g + 8], s1);
        }
    }
    __syncthreads();
    if (tid < 128) invs[tid] = 1.0f / rowsum[tid];

    float oacc[2][4][4] = {};
    float* arow = attn + ((size_t)bh * SS + row0) * SS;

    // ---------------- PASS 2: attn write + P@V ----------------------------
    #pragma unroll 1
    for (int j0 = 0; j0 < SS; j0 += 128) {
        __syncthreads();
        #pragma unroll
        for (int e = tid; e < 128 * 16; e += 256) {
            int r = e >> 4, c = (e & 15) << 2;
            float4 x = *(const float4*)(kbase + ((size_t)(j0 + r) << 6) + c);
            Ks[r*72+c] = tf32r(x.x); Ks[r*72+c+1] = tf32r(x.y);
            Ks[r*72+c+2] = tf32r(x.z); Ks[r*72+c+3] = tf32r(x.w);
            float4 y = *(const float4*)(vbase + ((size_t)(j0 + r) << 6) + c);
            Vs[r*72+c] = tf32r(y.x); Vs[r*72+c+1] = tf32r(y.y);
            Vs[r*72+c+2] = tf32r(y.z); Vs[r*72+c+3] = tf32r(y.w);
        }
        if (tid < 128) mcol[tid] = mask[b * SS + j0 + tid];
        __syncthreads();

        float acc[2][8][4] = {};
        #pragma unroll
        for (int s = 0; s < 8; s++) {
            int kb = s * 8;
            float a[2][4];
            #pragma unroll
            for (int mt = 0; mt < 2; mt++) {
                int r = wm * 32 + mt * 16 + g;
                a[mt][0] = Qs[r*72 + kb + t];       a[mt][1] = Qs[(r+8)*72 + kb + t];
                a[mt][2] = Qs[r*72 + kb + t + 4];   a[mt][3] = Qs[(r+8)*72 + kb + t + 4];
            }
            #pragma unroll
            for (int nt = 0; nt < 8; nt++) {
                int c = wn * 64 + nt * 8 + g;
                float b0 = Ks[c*72 + kb + t], b1 = Ks[c*72 + kb + t + 4];
                #pragma unroll
                for (int mt = 0; mt < 2; mt++)
                    mma_tf32(acc[mt][nt], a[mt][0], a[mt][1], a[mt][2], a[mt][3], b0, b1);
            }
        }
        #pragma unroll
        for (int mt = 0; mt < 2; mt++) {
            int lr0 = wm * 32 + mt * 16 + g, lr1 = lr0 + 8;
            int m0 = mrow[lr0], m1 = mrow[lr1];
            int gr0 = row0 + lr0, gr1 = row0 + lr1;
            float iv0 = invs[lr0], iv1 = invs[lr1];
            #pragma unroll
            for (int nt = 0; nt < 8; nt++) {
                int lc = wn * 64 + nt * 8 + 2 * t;
                int gc = j0 + lc;
                int mc0 = mcol[lc], mc1 = mcol[lc + 1];
                float p00 = ((m0 && mc0) || (gr0 == gc))     ? __expf(acc[mt][nt][0] * 0.125f) : 1.0f;
                float p01 = ((m0 && mc1) || (gr0 == gc + 1)) ? __expf(acc[mt][nt][1] * 0.125f) : 1.0f;
                float p10 = ((m1 && mc0) || (gr1 == gc))     ? __expf(acc[mt][nt][2] * 0.125f) : 1.0f;
                float p11 = ((m1 && mc1) || (gr1 == gc + 1)) ? __expf(acc[mt][nt][3] * 0.125f) : 1.0f;
                p00 *= iv0; p01 *= iv0; p10 *= iv1; p11 *= iv1;
                *(float2*)(arow + (size_t)lr0 * SS + gc) = make_float2(p00, p01);
                *(float2*)(arow + (size_t)lr1 * SS + gc) = make_float2(p10, p11);
                Ps[lr0*136 + lc] = tf32r(p00); Ps[lr0*136 + lc + 1] = tf32r(p01);
                Ps[lr1*136 + lc] = tf32r(p10); Ps[lr1*136 + lc + 1] = tf32r(p11);
            }
        }
        __syncthreads();
        #pragma unroll
        for (int s = 0; s < 16; s++) {
            int kb = s * 8;
            float a[2][4];
            #pragma unroll
            for (int mt = 0; mt < 2; mt++) {
                int r = wm * 32 + mt * 16 + g;
                a[mt][0] = Ps[r*136 + kb + t];       a[mt][1] = Ps[(r+8)*136 + kb + t];
                a[mt][2] = Ps[r*136 + kb + t + 4];   a[mt][3] = Ps[(r+8)*136 + kb + t + 4];
            }
            #pragma unroll
            for (int nt = 0; nt < 4; nt++) {
                int c = wn * 32 + nt * 8 + g;
                float b0 = Vs[(kb + t)*72 + c], b1 = Vs[(kb + t + 4)*72 + c];
                #pragma unroll
                for (int mt = 0; mt < 2; mt++)
                    mma_tf32(oacc[mt][nt], a[mt][0], a[mt][1], a[mt][2], a[mt][3], b0, b1);
            }
        }
    }
    float* obase = g_oh + ((size_t)bh * SS + row0) * 64;
    #pragma unroll
    for (int mt = 0; mt < 2; mt++) {
        int lr0 = wm * 32 + mt * 16 + g, lr1 = lr0 + 8;
        #pragma unroll
        for (int nt = 0; nt < 4; nt++) {
            int lc = wn * 32 + nt * 8 + 2 * t;
            *(float2*)(obase + (size_t)lr0 * 64 + lc) = make_float2(oacc[mt][nt][0], oacc[mt][nt][1]);
            *(float2*)(obase + (size_t)lr1 * 64 + lc) = make_float2(oacc[mt][nt][2], oacc[mt][nt][3]);
        }
    }
}

// ---------------- kernel 3: O @ Wo + residual (plain tf32) -------------------
__global__ __launch_bounds__(256) void out_proj_kernel(const float* __restrict__ q,
                                                       const float* __restrict__ Wo) {
    __shared__ float As_[128][40];
    __shared__ float Bs_[32][136];

    const int row0 = blockIdx.y * 128, col0 = blockIdx.x * 128;
    const int tid = threadIdx.x, lane = tid & 31, warp = tid >> 5;
    const int g = lane >> 2, t = lane & 3;
    const int wm = warp & 3, wn = warp >> 2;

    const int bidx = row0 >> 11, srow0 = row0 & 2047;

    float acc[2][8][4] = {};

    for (int k0 = 0; k0 < DD; k0 += 32) {
        __syncthreads();
        {
            int h = k0 >> 6, dv0 = k0 & 63;
            const float* abase = g_oh + (((size_t)(bidx * HH + h) * SS + srow0) << 6) + dv0;
            #pragma unroll
            for (int i = 0; i < 4; i++) {
                int e = tid + i * 256;
                int r = e >> 3, c = (e & 7) << 2;
                float4 x = *(const float4*)(abase + ((size_t)r << 6) + c);
                As_[r][c] = tf32r(x.x); As_[r][c+1] = tf32r(x.y);
                As_[r][c+2] = tf32r(x.z); As_[r][c+3] = tf32r(x.w);
            }
        }
        #pragma unroll
        for (int i = 0; i < 4; i++) {
            int e = tid + i * 256;
            int kr = e >> 5, c = (e & 31) << 2;
            float4 x = *(const float4*)(Wo + (size_t)(k0 + kr) * DD + col0 + c);
            Bs_[kr][c] = tf32r(x.x); Bs_[kr][c+1] = tf32r(x.y);
            Bs_[kr][c+2] = tf32r(x.z); Bs_[kr][c+3] = tf32r(x.w);
        }
        __syncthreads();
        #pragma unroll
        for (int s = 0; s < 4; s++) {
            int kb = s * 8;
            float a[2][4];
            #pragma unroll
            for (int mt = 0; mt < 2; mt++) {
                int r = wm * 32 + mt * 16 + g;
                a[mt][0] = As_[r][kb + t];       a[mt][1] = As_[r + 8][kb + t];
                a[mt][2] = As_[r][kb + t + 4];   a[mt][3] = As_[r + 8][kb + t + 4];
            }
            #pragma unroll
            for (int nt = 0; nt < 8; nt++) {
                int c = wn * 64 + nt * 8 + g;
                float b0 = Bs_[kb + t][c], b1 = Bs_[kb + t + 4][c];
                #pragma unroll
                for (int mt = 0; mt < 2; mt++)
                    mma_tf32(acc[mt][nt], a[mt][0], a[mt][1], a[mt][2], a[mt][3], b0, b1);
            }
        }
    }
    #pragma unroll
    for (int mt = 0; mt < 2; mt++) {
        int r0 = row0 + wm * 32 + mt * 16 + g;
        #pragma unroll
        for (int nt = 0; nt < 8; nt++) {
            int col = col0 + wn * 64 + nt * 8 + 2 * t;
            size_t off0 = (size_t)r0 * DD + col;
            size_t off1 = (size_t)(r0 + 8) * DD + col;
            float2 q0 = *(const float2*)(q + off0);
            float2 q1 = *(const float2*)(q + off1);
            *(float2*)(g_y + off0) = make_float2(acc[mt][nt][0] + q0.x, acc[mt][nt][1] + q0.y);
            *(float2*)(g_y + off1) = make_float2(acc[mt][nt][2] + q1.x, acc[mt][nt][3] + q1.y);
        }
    }
}

// ---------------- kernel 4: LayerNorm ---------------------------------------
__global__ void ln_kernel(const float* __restrict__ gamma, const float* __restrict__ beta,
                          float* __restrict__ out) {
    const int row = blockIdx.x;
    const float* x = g_y + (size_t)row * DD;
    const int t = threadIdx.x;

    float v0 = x[t], v1 = x[t + 256];
    float s  = v0 + v1;
    float sq = v0 * v0 + v1 * v1;

    __shared__ float ssum[8], ssq[8];
    #pragma unroll
    for (int off = 16; off > 0; off >>= 1) {
        s  += __shfl_down_sync(0xffffffffu, s,  off);
        sq += __shfl_down_sync(0xffffffffu, sq, off);
    }
    if ((t & 31) == 0) { ssum[t >> 5] = s; ssq[t >> 5] = sq; }
    __syncthreads();
    if (t < 32) {
        float a = (t < 8) ? ssum[t] : 0.f;
        float b = (t < 8) ? ssq[t]  : 0.f;
        #pragma unroll
        for (int off = 4; off > 0; off >>= 1) {
            a += __shfl_down_sync(0xffffffffu, a, off);
            b += __shfl_down_sync(0xffffffffu, b, off);
        }
        if (t == 0) { ssum[0] = a; ssq[0] = b; }
    }
    __syncthreads();
    float mean = ssum[0] * (1.0f / DD);
    float var  = ssq[0]  * (1.0f / DD) - mean * mean;
    float rs   = rsqrtf(var + 1e-6f);

    out[(size_t)row * DD + t]       = (v0 - mean) * rs * gamma[t]       + beta[t];
    out[(size_t)row * DD + t + 256] = (v1 - mean) * rs * gamma[t + 256] + beta[t + 256];
}

// ---------------- launch -----------------------------------------------------
extern "C" void kernel_launch(void* const* d_in, const int* in_sizes, int n_in,
                              void* d_out, int out_size) {
    const float* q     = (const float*)d_in[0];
    const float* k     = (const float*)d_in[1];
    const float* v     = (const float*)d_in[2];
    const int*   mask  = (const int*)  d_in[3];
    const float* Wq    = (const float*)d_in[4];
    const float* Wk    = (const float*)d_in[5];
    const float* Wv    = (const float*)d_in[6];
    const float* Wo    = (const float*)d_in[7];
    const float* gamma = (const float*)d_in[8];
    const float* beta  = (const float*)d_in[9];

    float* out  = (float*)d_out;                  // [B,S,D]
    float* attn = out + (size_t)BB * SS * DD;     // [B,H,S,S]

    cudaFuncSetAttribute(attn_kernel, cudaFuncAttributeMaxDynamicSharedMemorySize, ATTN_SMEM);

    proj_kernel<<<dim3(DD/128, BSN/128, 3), 256>>>(q, k, v, Wq, Wk, Wv);
    attn_kernel<<<dim3(SS/128, BH), 256, ATTN_SMEM>>>(mask, attn);
    out_proj_kernel<<<dim3(DD/128, BSN/128), 256>>>(q, Wo);
    ln_kernel<<<BSN, 256>>>(gamma, beta, out);
}

// round 3
// speedup vs baseline: 1.4732x; 1.1077x over previous
#include <cuda_runtime.h>
#include <math.h>

#define BB 4
#define SS 2048
#define DD 512
#define HH 8
#define BH (BB*HH)
#define BSN (BB*SS)

// ---------------- scratch (device globals; no allocation allowed) ----------
__device__ float g_qh[(size_t)BH*SS*64];   // [bh, s, 64]
__device__ float g_kh[(size_t)BH*SS*64];
__device__ float g_vh[(size_t)BH*SS*64];
__device__ float g_oh[(size_t)BH*SS*64];
__device__ float g_y[(size_t)BSN*DD];

// ---------------- tf32 helpers ----------------------------------------------
__device__ __forceinline__ float tf32r(float x) {
    unsigned u;
    asm("cvt.rna.tf32.f32 %0, %1;" : "=r"(u) : "f"(x));
    return __uint_as_float(u);
}

__device__ __forceinline__ void mma_tf32(float c[4],
        float a0, float a1, float a2, float a3, float b0, float b1) {
    asm("mma.sync.aligned.m16n8k8.row.col.f32.tf32.tf32.f32 "
        "{%0,%1,%2,%3},{%4,%5,%6,%7},{%8,%9},{%0,%1,%2,%3};"
        : "+f"(c[0]), "+f"(c[1]), "+f"(c[2]), "+f"(c[3])
        : "r"(__float_as_uint(a0)), "r"(__float_as_uint(a1)),
          "r"(__float_as_uint(a2)), "r"(__float_as_uint(a3)),
          "r"(__float_as_uint(b0)), "r"(__float_as_uint(b1)));
}

// ---------------- kernel 1: fused QKV projections (split-tf32) --------------
__global__ __launch_bounds__(256) void proj_kernel(
        const float* __restrict__ q, const float* __restrict__ k,
        const float* __restrict__ v, const float* __restrict__ Wq,
        const float* __restrict__ Wk, const float* __restrict__ Wv) {
    __shared__ float Ash[128][20];
    __shared__ float Asl[128][20];
    __shared__ float Bsh[16][136];
    __shared__ float Bsl[16][136];

    const float* X; const float* W; float* Y;
    if (blockIdx.z == 0)      { X = q; W = Wq; Y = g_qh; }
    else if (blockIdx.z == 1) { X = k; W = Wk; Y = g_kh; }
    else                      { X = v; W = Wv; Y = g_vh; }

    const int row0 = blockIdx.y * 128, col0 = blockIdx.x * 128;
    const int tid = threadIdx.x, lane = tid & 31, warp = tid >> 5;
    const int g = lane >> 2, t = lane & 3;
    const int wm = warp & 3, wn = warp >> 2;

    float acc[2][8][4] = {};

    const int ar = tid >> 1, acb = (tid & 1) << 3;
    const int bkr = tid >> 4, bcb = (tid & 15) << 3;

    for (int k0 = 0; k0 < DD; k0 += 16) {
        __syncthreads();
        {
            const float* src = X + (size_t)(row0 + ar) * DD + k0 + acb;
            float4 v0 = *(const float4*)src;
            float4 v1 = *(const float4*)(src + 4);
            float xs[8] = {v0.x, v0.y, v0.z, v0.w, v1.x, v1.y, v1.z, v1.w};
            #pragma unroll
            for (int i = 0; i < 8; i++) {
                float hi = tf32r(xs[i]);
                Ash[ar][acb + i] = hi;
                Asl[ar][acb + i] = tf32r(xs[i] - hi);
            }
        }
        {
            const float* src = W + (size_t)(k0 + bkr) * DD + col0 + bcb;
            float4 v0 = *(const float4*)src;
            float4 v1 = *(const float4*)(src + 4);
            float xs[8] = {v0.x, v0.y, v0.z, v0.w, v1.x, v1.y, v1.z, v1.w};
            #pragma unroll
            for (int i = 0; i < 8; i++) {
                float hi = tf32r(xs[i]);
                Bsh[bkr][bcb + i] = hi;
                Bsl[bkr][bcb + i] = tf32r(xs[i] - hi);
            }
        }
        __syncthreads();
        #pragma unroll
        for (int s = 0; s < 2; s++) {
            const int kb = s * 8;
            float ah[2][4], al[2][4];
            #pragma unroll
            for (int mt = 0; mt < 2; mt++) {
                int r = wm * 32 + mt * 16 + g;
                ah[mt][0] = Ash[r][kb + t];       al[mt][0] = Asl[r][kb + t];
                ah[mt][1] = Ash[r + 8][kb + t];   al[mt][1] = Asl[r + 8][kb + t];
                ah[mt][2] = Ash[r][kb + t + 4];   al[mt][2] = Asl[r][kb + t + 4];
                ah[mt][3] = Ash[r + 8][kb + t + 4]; al[mt][3] = Asl[r + 8][kb + t + 4];
            }
            #pragma unroll
            for (int nt = 0; nt < 8; nt++) {
                int c = wn * 64 + nt * 8 + g;
                float bh0 = Bsh[kb + t][c], bh1 = Bsh[kb + t + 4][c];
                float bl0 = Bsl[kb + t][c], bl1 = Bsl[kb + t + 4][c];
                #pragma unroll
                for (int mt = 0; mt < 2; mt++) {
                    mma_tf32(acc[mt][nt], ah[mt][0], ah[mt][1], ah[mt][2], ah[mt][3], bh0, bh1);
                    mma_tf32(acc[mt][nt], ah[mt][0], ah[mt][1], ah[mt][2], ah[mt][3], bl0, bl1);
                    mma_tf32(acc[mt][nt], al[mt][0], al[mt][1], al[mt][2], al[mt][3], bh0, bh1);
                }
            }
        }
    }
    const int bidx = row0 >> 11;
    #pragma unroll
    for (int mt = 0; mt < 2; mt++) {
        int r0 = row0 + wm * 32 + mt * 16 + g;
        int s0 = r0 & 2047;
        #pragma unroll
        for (int nt = 0; nt < 8; nt++) {
            int col = col0 + wn * 64 + nt * 8 + 2 * t;
            int h = col >> 6, dk = col & 63;
            float* dst0 = Y + (((size_t)(bidx * HH + h) * SS + s0) << 6) + dk;
            float* dst1 = Y + (((size_t)(bidx * HH + h) * SS + s0 + 8) << 6) + dk;
            *(float2*)dst0 = make_float2(acc[mt][nt][0], acc[mt][nt][1]);
            *(float2*)dst1 = make_float2(acc[mt][nt][2], acc[mt][nt][3]);
        }
    }
}

// ---------------- kernel 2: fused attention ---------------------------------
// 128 q-rows per CTA, j-tile = 64 -> 110KB smem -> 2 CTAs/SM.
// Paired-k layout for Q/K: elements (k, k+4) adjacent => float2 fragment loads.
// Pass 1: rowsums. Pass 2: recompute scores, write normalized attn, P@V.
#define QS_N (128*72)
#define KS_N (64*72)
#define VS_N (64*72)
#define PS_N (128*72)
#define ATTN_SMEM ((QS_N + KS_N + VS_N + PS_N + 256)*4 + 192*4)

__global__ __launch_bounds__(256, 2) void attn_kernel(const int* __restrict__ mask,
                                                      float* __restrict__ attn) {
    extern __shared__ float sm[];
    float* Qs     = sm;                    // [128][72] paired-k tf32
    float* Ks     = Qs + QS_N;             // [64][72]  paired-k tf32 (row = j-col)
    float* Vs     = Ks + KS_N;             // [64][72]  plain [k][dv] tf32
    float* Ps     = Vs + VS_N;             // [128][72] plain [q][j] tf32
    float* rowsum = Ps + PS_N;             // 128
    float* invs   = rowsum + 128;          // 128
    int*   mrow   = (int*)(invs + 128);    // 128
    int*   mcol   = mrow + 128;            // 64

    const int bh = blockIdx.y, b = bh >> 3;
    const int row0 = blockIdx.x * 128;
    const int tid = threadIdx.x, lane = tid & 31, warp = tid >> 5;
    const int g = lane >> 2, t = lane & 3;
    const int wm = warp & 3, wn = warp >> 2;

    const float* qbase = g_qh + (size_t)bh * SS * 64;
    const float* kbase = g_kh + (size_t)bh * SS * 64;
    const float* vbase = g_vh + (size_t)bh * SS * 64;

    const int fr = tid >> 3;            // fill: 8 threads per row
    const int fcb = (tid & 7) << 3;     // 8-element block

    // ---- load Q tile (paired) ----
    #pragma unroll
    for (int sw = 0; sw < 4; sw++) {
        int r = fr + sw * 32;
        const float* src = qbase + ((size_t)(row0 + r) << 6) + fcb;
        float4 v0 = *(const float4*)src;
        float4 v1 = *(const float4*)(src + 4);
        float xs[8] = {v0.x, v0.y, v0.z, v0.w, v1.x, v1.y, v1.z, v1.w};
        float* d = Qs + r * 72 + fcb;
        #pragma unroll
        for (int i = 0; i < 4; i++)
            *(float2*)(d + 2 * i) = make_float2(tf32r(xs[i]), tf32r(xs[i + 4]));
    }
    if (tid < 128) { mrow[tid] = mask[b * SS + row0 + tid]; rowsum[tid] = 0.f; }

    float rp0[2] = {0.f, 0.f};
    float rp1[2] = {0.f, 0.f};

    // ---------------- PASS 1: rowsums --------------------------------------
    #pragma unroll 1
    for (int j0 = 0; j0 < SS; j0 += 64) {
        __syncthreads();
        #pragma unroll
        for (int sw = 0; sw < 2; sw++) {
            int r = fr + sw * 32;
            const float* src = kbase + ((size_t)(j0 + r) << 6) + fcb;
            float4 v0 = *(const float4*)src;
            float4 v1 = *(const float4*)(src + 4);
            float xs[8] = {v0.x, v0.y, v0.z, v0.w, v1.x, v1.y, v1.z, v1.w};
            float* d = Ks + r * 72 + fcb;
            #pragma unroll
            for (int i = 0; i < 4; i++)
                *(float2*)(d + 2 * i) = make_float2(tf32r(xs[i]), tf32r(xs[i + 4]));
        }
        if (tid < 64) mcol[tid] = mask[b * SS + j0 + tid];
        __syncthreads();

        float acc[2][4][4] = {};
        #pragma unroll
        for (int s = 0; s < 8; s++) {
            int kb = s * 8;
            float2 pa[2][2];
            #pragma unroll
            for (int mt = 0; mt < 2; mt++) {
                int r = wm * 32 + mt * 16 + g;
                pa[mt][0] = *(const float2*)(Qs + r * 72 + kb + 2 * t);
                pa[mt][1] = *(const float2*)(Qs + (r + 8) * 72 + kb + 2 * t);
            }
            #pragma unroll
            for (int nt = 0; nt < 4; nt++) {
                int c = wn * 32 + nt * 8 + g;
                float2 pb = *(const float2*)(Ks + c * 72 + kb + 2 * t);
                #pragma unroll
                for (int mt = 0; mt < 2; mt++)
                    mma_tf32(acc[mt][nt], pa[mt][0].x, pa[mt][1].x,
                             pa[mt][0].y, pa[mt][1].y, pb.x, pb.y);
            }
        }
        #pragma unroll
        for (int mt = 0; mt < 2; mt++) {
            int lr0 = wm * 32 + mt * 16 + g, lr1 = lr0 + 8;
            int m0 = mrow[lr0], m1 = mrow[lr1];
            int gr0 = row0 + lr0, gr1 = row0 + lr1;
            #pragma unroll
            for (int nt = 0; nt < 4; nt++) {
                int lc = wn * 32 + nt * 8 + 2 * t;
                int gc = j0 + lc;
                int mc0 = mcol[lc], mc1 = mcol[lc + 1];
                float p00 = ((m0 && mc0) || (gr0 == gc))     ? __expf(acc[mt][nt][0] * 0.125f) : 1.0f;
                float p01 = ((m0 && mc1) || (gr0 == gc + 1)) ? __expf(acc[mt][nt][1] * 0.125f) : 1.0f;
                float p10 = ((m1 && mc0) || (gr1 == gc))     ? __expf(acc[mt][nt][2] * 0.125f) : 1.0f;
                float p11 = ((m1 && mc1) || (gr1 == gc + 1)) ? __expf(acc[mt][nt][3] * 0.125f) : 1.0f;
                rp0[mt] += p00 + p01;
                rp1[mt] += p10 + p11;
            }
        }
    }
    #pragma unroll
    for (int mt = 0; mt < 2; mt++) {
        float s0 = rp0[mt], s1 = rp1[mt];
        s0 += __shfl_xor_sync(0xffffffffu, s0, 1); s0 += __shfl_xor_sync(0xffffffffu, s0, 2);
        s1 += __shfl_xor_sync(0xffffffffu, s1, 1); s1 += __shfl_xor_sync(0xffffffffu, s1, 2);
        if (t == 0) {
            atomicAdd(&rowsum[wm * 32 + mt * 16 + g], s0);
            atomicAdd(&rowsum[wm * 32 + mt * 16 + g + 8], s1);
        }
    }
    __syncthreads();
    if (tid < 128) invs[tid] = 1.0f / rowsum[tid];

    float oacc[2][4][4] = {};
    float* arow = attn + ((size_t)bh * SS + row0) * SS;

    // ---------------- PASS 2: attn write + P@V -----------------------------
    #pragma unroll 1
    for (int j0 = 0; j0 < SS; j0 += 64) {
        __syncthreads();
        #pragma unroll
        for (int sw = 0; sw < 2; sw++) {
            int r = fr + sw * 32;
            const float* src = kbase + ((size_t)(j0 + r) << 6) + fcb;
            float4 v0 = *(const float4*)src;
            float4 v1 = *(const float4*)(src + 4);
            float xs[8] = {v0.x, v0.y, v0.z, v0.w, v1.x, v1.y, v1.z, v1.w};
            float* d = Ks + r * 72 + fcb;
            #pragma unroll
            for (int i = 0; i < 4; i++)
                *(float2*)(d + 2 * i) = make_float2(tf32r(xs[i]), tf32r(xs[i + 4]));
            // V tile: plain row-major, tf32
            const float* vsrc = vbase + ((size_t)(j0 + r) << 6) + fcb;
            float4 w0 = *(const float4*)vsrc;
            float4 w1 = *(const float4*)(vsrc + 4);
            float4 c0 = make_float4(tf32r(w0.x), tf32r(w0.y), tf32r(w0.z), tf32r(w0.w));
            float4 c1 = make_float4(tf32r(w1.x), tf32r(w1.y), tf32r(w1.z), tf32r(w1.w));
            *(float4*)(Vs + r * 72 + fcb)     = c0;
            *(float4*)(Vs + r * 72 + fcb + 4) = c1;
        }
        if (tid < 64) mcol[tid] = mask[b * SS + j0 + tid];
        __syncthreads();

        float acc[2][4][4] = {};
        #pragma unroll
        for (int s = 0; s < 8; s++) {
            int kb = s * 8;
            float2 pa[2][2];
            #pragma unroll
            for (int mt = 0; mt < 2; mt++) {
                int r = wm * 32 + mt * 16 + g;
                pa[mt][0] = *(const float2*)(Qs + r * 72 + kb + 2 * t);
                pa[mt][1] = *(const float2*)(Qs + (r + 8) * 72 + kb + 2 * t);
            }
            #pragma unroll
            for (int nt = 0; nt < 4; nt++) {
                int c = wn * 32 + nt * 8 + g;
                float2 pb = *(const float2*)(Ks + c * 72 + kb + 2 * t);
                #pragma unroll
                for (int mt = 0; mt < 2; mt++)
                    mma_tf32(acc[mt][nt], pa[mt][0].x, pa[mt][1].x,
                             pa[mt][0].y, pa[mt][1].y, pb.x, pb.y);
            }
        }
        #pragma unroll
        for (int mt = 0; mt < 2; mt++) {
            int lr0 = wm * 32 + mt * 16 + g, lr1 = lr0 + 8;
            int m0 = mrow[lr0], m1 = mrow[lr1];
            int gr0 = row0 + lr0, gr1 = row0 + lr1;
            float iv0 = invs[lr0], iv1 = invs[lr1];
            #pragma unroll
            for (int nt = 0; nt < 4; nt++) {
                int lc = wn * 32 + nt * 8 + 2 * t;
                int gc = j0 + lc;
                int mc0 = mcol[lc], mc1 = mcol[lc + 1];
                float p00 = ((m0 && mc0) || (gr0 == gc))     ? __expf(acc[mt][nt][0] * 0.125f) : 1.0f;
                float p01 = ((m0 && mc1) || (gr0 == gc + 1)) ? __expf(acc[mt][nt][1] * 0.125f) : 1.0f;
                float p10 = ((m1 && mc0) || (gr1 == gc))     ? __expf(acc[mt][nt][2] * 0.125f) : 1.0f;
                float p11 = ((m1 && mc1) || (gr1 == gc + 1)) ? __expf(acc[mt][nt][3] * 0.125f) : 1.0f;
                p00 *= iv0; p01 *= iv0; p10 *= iv1; p11 *= iv1;
                *(float2*)(arow + (size_t)lr0 * SS + gc) = make_float2(p00, p01);
                *(float2*)(arow + (size_t)lr1 * SS + gc) = make_float2(p10, p11);
                *(float2*)(Ps + lr0 * 72 + lc) = make_float2(tf32r(p00), tf32r(p01));
                *(float2*)(Ps + lr1 * 72 + lc) = make_float2(tf32r(p10), tf32r(p11));
            }
        }
        __syncthreads();
        #pragma unroll
        for (int s = 0; s < 8; s++) {
            int kb = s * 8;
            float a[2][4];
            #pragma unroll
            for (int mt = 0; mt < 2; mt++) {
                int r = wm * 32 + mt * 16 + g;
                a[mt][0] = Ps[r * 72 + kb + t];       a[mt][1] = Ps[(r + 8) * 72 + kb + t];
                a[mt][2] = Ps[r * 72 + kb + t + 4];   a[mt][3] = Ps[(r + 8) * 72 + kb + t + 4];
            }
            #pragma unroll
            for (int nt = 0; nt < 4; nt++) {
                int c = wn * 32 + nt * 8 + g;
                float b0 = Vs[(kb + t) * 72 + c], b1 = Vs[(kb + t + 4) * 72 + c];
                #pragma unroll
                for (int mt = 0; mt < 2; mt++)
                    mma_tf32(oacc[mt][nt], a[mt][0], a[mt][1], a[mt][2], a[mt][3], b0, b1);
            }
        }
    }
    float* obase = g_oh + ((size_t)bh * SS + row0) * 64;
    #pragma unroll
    for (int mt = 0; mt < 2; mt++) {
        int lr0 = wm * 32 + mt * 16 + g, lr1 = lr0 + 8;
        #pragma unroll
        for (int nt = 0; nt < 4; nt++) {
            int lc = wn * 32 + nt * 8 + 2 * t;
            *(float2*)(obase + (size_t)lr0 * 64 + lc) = make_float2(oacc[mt][nt][0], oacc[mt][nt][1]);
            *(float2*)(obase + (size_t)lr1 * 64 + lc) = make_float2(oacc[mt][nt][2], oacc[mt][nt][3]);
        }
    }
}

// ---------------- kernel 3: O @ Wo + residual (plain tf32) -------------------
__global__ __launch_bounds__(256) void out_proj_kernel(const float* __restrict__ q,
                                                       const float* __restrict__ Wo) {
    __shared__ float As_[128][40];
    __shared__ float Bs_[32][136];

    const int row0 = blockIdx.y * 128, col0 = blockIdx.x * 128;
    const int tid = threadIdx.x, lane = tid & 31, warp = tid >> 5;
    const int g = lane >> 2, t = lane & 3;
    const int wm = warp & 3, wn = warp >> 2;

    const int bidx = row0 >> 11, srow0 = row0 & 2047;

    float acc[2][8][4] = {};

    for (int k0 = 0; k0 < DD; k0 += 32) {
        __syncthreads();
        {
            int h = k0 >> 6, dv0 = k0 & 63;
            const float* abase = g_oh + (((size_t)(bidx * HH + h) * SS + srow0) << 6) + dv0;
            #pragma unroll
            for (int i = 0; i < 4; i++) {
                int e = tid + i * 256;
                int r = e >> 3, c = (e & 7) << 2;
                float4 x = *(const float4*)(abase + ((size_t)r << 6) + c);
                As_[r][c] = tf32r(x.x); As_[r][c+1] = tf32r(x.y);
                As_[r][c+2] = tf32r(x.z); As_[r][c+3] = tf32r(x.w);
            }
        }
        #pragma unroll
        for (int i = 0; i < 4; i++) {
            int e = tid + i * 256;
            int kr = e >> 5, c = (e & 31) << 2;
            float4 x = *(const float4*)(Wo + (size_t)(k0 + kr) * DD + col0 + c);
            Bs_[kr][c] = tf32r(x.x); Bs_[kr][c+1] = tf32r(x.y);
            Bs_[kr][c+2] = tf32r(x.z); Bs_[kr][c+3] = tf32r(x.w);
        }
        __syncthreads();
        #pragma unroll
        for (int s = 0; s < 4; s++) {
            int kb = s * 8;
            float a[2][4];
            #pragma unroll
            for (int mt = 0; mt < 2; mt++) {
                int r = wm * 32 + mt * 16 + g;
                a[mt][0] = As_[r][kb + t];       a[mt][1] = As_[r + 8][kb + t];
                a[mt][2] = As_[r][kb + t + 4];   a[mt][3] = As_[r + 8][kb + t + 4];
            }
            #pragma unroll
            for (int nt = 0; nt < 8; nt++) {
                int c = wn * 64 + nt * 8 + g;
                float b0 = Bs_[kb + t][c], b1 = Bs_[kb + t + 4][c];
                #pragma unroll
                for (int mt = 0; mt < 2; mt++)
                    mma_tf32(acc[mt][nt], a[mt][0], a[mt][1], a[mt][2], a[mt][3], b0, b1);
            }
        }
    }
    #pragma unroll
    for (int mt = 0; mt < 2; mt++) {
        int r0 = row0 + wm * 32 + mt * 16 + g;
        #pragma unroll
        for (int nt = 0; nt < 8; nt++) {
            int col = col0 + wn * 64 + nt * 8 + 2 * t;
            size_t off0 = (size_t)r0 * DD + col;
            size_t off1 = (size_t)(r0 + 8) * DD + col;
            float2 q0 = *(const float2*)(q + off0);
            float2 q1 = *(const float2*)(q + off1);
            *(float2*)(g_y + off0) = make_float2(acc[mt][nt][0] + q0.x, acc[mt][nt][1] + q0.y);
            *(float2*)(g_y + off1) = make_float2(acc[mt][nt][2] + q1.x, acc[mt][nt][3] + q1.y);
        }
    }
}

// ---------------- kernel 4: LayerNorm ---------------------------------------
__global__ void ln_kernel(const float* __restrict__ gamma, const float* __restrict__ beta,
                          float* __restrict__ out) {
    const int row = blockIdx.x;
    const float* x = g_y + (size_t)row * DD;
    const int t = threadIdx.x;

    float v0 = x[t], v1 = x[t + 256];
    float s  = v0 + v1;
    float sq = v0 * v0 + v1 * v1;

    __shared__ float ssum[8], ssq[8];
    #pragma unroll
    for (int off = 16; off > 0; off >>= 1) {
        s  += __shfl_down_sync(0xffffffffu, s,  off);
        sq += __shfl_down_sync(0xffffffffu, sq, off);
    }
    if ((t & 31) == 0) { ssum[t >> 5] = s; ssq[t >> 5] = sq; }
    __syncthreads();
    if (t < 32) {
        float a = (t < 8) ? ssum[t] : 0.f;
        float b = (t < 8) ? ssq[t]  : 0.f;
        #pragma unroll
        for (int off = 4; off > 0; off >>= 1) {
            a += __shfl_down_sync(0xffffffffu, a, off);
            b += __shfl_down_sync(0xffffffffu, b, off);
        }
        if (t == 0) { ssum[0] = a; ssq[0] = b; }
    }
    __syncthreads();
    float mean = ssum[0] * (1.0f / DD);
    float var  = ssq[0]  * (1.0f / DD) - mean * mean;
    float rs   = rsqrtf(var + 1e-6f);

    out[(size_t)row * DD + t]       = (v0 - mean) * rs * gamma[t]       + beta[t];
    out[(size_t)row * DD + t + 256] = (v1 - mean) * rs * gamma[t + 256] + beta[t + 256];
}

// ---------------- launch -----------------------------------------------------
extern "C" void kernel_launch(void* const* d_in, const int* in_sizes, int n_in,
                              void* d_out, int out_size) {
    const float* q     = (const float*)d_in[0];
    const float* k     = (const float*)d_in[1];
    const float* v     = (const float*)d_in[2];
    const int*   mask  = (const int*)  d_in[3];
    const float* Wq    = (const float*)d_in[4];
    const float* Wk    = (const float*)d_in[5];
    const float* Wv    = (const float*)d_in[6];
    const float* Wo    = (const float*)d_in[7];
    const float* gamma = (const float*)d_in[8];
    const float* beta  = (const float*)d_in[9];

    float* out  = (float*)d_out;                  // [B,S,D]
    float* attn = out + (size_t)BB * SS * DD;     // [B,H,S,S]

    cudaFuncSetAttribute(attn_kernel, cudaFuncAttributeMaxDynamicSharedMemorySize, ATTN_SMEM);

    proj_kernel<<<dim3(DD/128, BSN/128, 3), 256>>>(q, k, v, Wq, Wk, Wv);
    attn_kernel<<<dim3(SS/128, BH), 256, ATTN_SMEM>>>(mask, attn);
    out_proj_kernel<<<dim3(DD/128, BSN/128), 256>>>(q, Wo);
    ln_kernel<<<BSN, 256>>>(gamma, beta, out);
}

// round 5
// speedup vs baseline: 1.5793x; 1.0720x over previous
#include <cuda_runtime.h>
#include <math.h>

#define BB 4
#define SS 2048
#define DD 512
#define HH 8
#define BH (BB*HH)
#define BSN (BB*SS)

// ---------------- scratch (device globals; no allocation allowed) ----------
__device__ float g_qh[(size_t)BH*SS*64];   // [bh, s, 64]
__device__ float g_kh[(size_t)BH*SS*64];
__device__ float g_vh[(size_t)BH*SS*64];
__device__ float g_oh[(size_t)BH*SS*64];
__device__ float g_y[(size_t)BSN*DD];

// ---------------- helpers -----------------------------------------------------
__device__ __forceinline__ float tf32r(float x) {
    unsigned u;
    asm("cvt.rna.tf32.f32 %0, %1;" : "=r"(u) : "f"(x));
    return __uint_as_float(u);
}

__device__ __forceinline__ void mma_tf32(float c[4],
        float a0, float a1, float a2, float a3, float b0, float b1) {
    asm("mma.sync.aligned.m16n8k8.row.col.f32.tf32.tf32.f32 "
        "{%0,%1,%2,%3},{%4,%5,%6,%7},{%8,%9},{%0,%1,%2,%3};"
        : "+f"(c[0]), "+f"(c[1]), "+f"(c[2]), "+f"(c[3])
        : "r"(__float_as_uint(a0)), "r"(__float_as_uint(a1)),
          "r"(__float_as_uint(a2)), "r"(__float_as_uint(a3)),
          "r"(__float_as_uint(b0)), "r"(__float_as_uint(b1)));
}

__device__ __forceinline__ float fexp2(float x) {
    float y;
    asm("ex2.approx.f32 %0, %1;" : "=f"(y) : "f"(x));
    return y;
}
#define EXP_C 0.18033688011112042f   // log2(e)/8

// ---------------- kernel 1: fused QKV projections ---------------------------
// X[8192,512] @ W[512,512] -> head layout [bh, s, 64]. 128x128 block tile.
// Q/K (z=0,1): B-operand split hi/lo (2 MMAs). V (z=2): plain tf32 (1 MMA).
__global__ __launch_bounds__(256) void proj_kernel(
        const float* __restrict__ q, const float* __restrict__ k,
        const float* __restrict__ v, const float* __restrict__ Wq,
        const float* __restrict__ Wk, const float* __restrict__ Wv) {
    __shared__ float Ash[128][20];
    __shared__ float Bsh[16][136];
    __shared__ float Bsl[16][136];

    const float* X; const float* W; float* Y;
    if (blockIdx.z == 0)      { X = q; W = Wq; Y = g_qh; }
    else if (blockIdx.z == 1) { X = k; W = Wk; Y = g_kh; }
    else                      { X = v; W = Wv; Y = g_vh; }
    const bool split = (blockIdx.z != 2);

    const int row0 = blockIdx.y * 128, col0 = blockIdx.x * 128;
    const int tid = threadIdx.x, lane = tid & 31, warp = tid >> 5;
    const int g = lane >> 2, t = lane & 3;
    const int wm = warp & 3, wn = warp >> 2;

    float acc[2][8][4] = {};

    const int ar = tid >> 1, acb = (tid & 1) << 3;
    const int bkr = tid >> 4, bcb = (tid & 15) << 3;

    for (int k0 = 0; k0 < DD; k0 += 16) {
        __syncthreads();
        {
            const float* src = X + (size_t)(row0 + ar) * DD + k0 + acb;
            float4 v0 = *(const float4*)src;
            float4 v1 = *(const float4*)(src + 4);
            float xs[8] = {v0.x, v0.y, v0.z, v0.w, v1.x, v1.y, v1.z, v1.w};
            #pragma unroll
            for (int i = 0; i < 8; i++) Ash[ar][acb + i] = tf32r(xs[i]);
        }
        {
            const float* src = W + (size_t)(k0 + bkr) * DD + col0 + bcb;
            float4 v0 = *(const float4*)src;
            float4 v1 = *(const float4*)(src + 4);
            float xs[8] = {v0.x, v0.y, v0.z, v0.w, v1.x, v1.y, v1.z, v1.w};
            #pragma unroll
            for (int i = 0; i < 8; i++) {
                float hi = tf32r(xs[i]);
                Bsh[bkr][bcb + i] = hi;
                if (split) Bsl[bkr][bcb + i] = tf32r(xs[i] - hi);
            }
        }
        __syncthreads();
        #pragma unroll
        for (int s = 0; s < 2; s++) {
            const int kb = s * 8;
            float a[2][4];
            #pragma unroll
            for (int mt = 0; mt < 2; mt++) {
                int r = wm * 32 + mt * 16 + g;
                a[mt][0] = Ash[r][kb + t];       a[mt][1] = Ash[r + 8][kb + t];
                a[mt][2] = Ash[r][kb + t + 4];   a[mt][3] = Ash[r + 8][kb + t + 4];
            }
            #pragma unroll
            for (int nt = 0; nt < 8; nt++) {
                int c = wn * 64 + nt * 8 + g;
                float bh0 = Bsh[kb + t][c], bh1 = Bsh[kb + t + 4][c];
                #pragma unroll
                for (int mt = 0; mt < 2; mt++)
                    mma_tf32(acc[mt][nt], a[mt][0], a[mt][1], a[mt][2], a[mt][3], bh0, bh1);
                if (split) {
                    float bl0 = Bsl[kb + t][c], bl1 = Bsl[kb + t + 4][c];
                    #pragma unroll
                    for (int mt = 0; mt < 2; mt++)
                        mma_tf32(acc[mt][nt], a[mt][0], a[mt][1], a[mt][2], a[mt][3], bl0, bl1);
                }
            }
        }
    }
    const int bidx = row0 >> 11;
    #pragma unroll
    for (int mt = 0; mt < 2; mt++) {
        int r0 = row0 + wm * 32 + mt * 16 + g;
        int s0 = r0 & 2047;
        #pragma unroll
        for (int nt = 0; nt < 8; nt++) {
            int col = col0 + wn * 64 + nt * 8 + 2 * t;
            int h = col >> 6, dk = col & 63;
            float* dst0 = Y + (((size_t)(bidx * HH + h) * SS + s0) << 6) + dk;
            float* dst1 = Y + (((size_t)(bidx * HH + h) * SS + s0 + 8) << 6) + dk;
            *(float2*)dst0 = make_float2(acc[mt][nt][0], acc[mt][nt][1]);
            *(float2*)dst1 = make_float2(acc[mt][nt][2], acc[mt][nt][3]);
        }
    }
}

// ---------------- kernel 2: fused attention (round-3 proven version) --------
// 128 q-rows per CTA, j-tile = 64 -> 2 CTAs/SM. Paired-k tf32 layout.
// Pass 1: rowsums. Pass 2: recompute scores, write normalized attn, P@V.
#define QS_N (128*72)
#define KS_N (64*72)
#define VS_N (64*72)
#define PS_N (128*72)
#define ATTN_SMEM ((QS_N + KS_N + VS_N + PS_N + 256)*4 + 192*4)

__global__ __launch_bounds__(256, 2) void attn_kernel(const int* __restrict__ mask,
                                                      float* __restrict__ attn) {
    extern __shared__ float sm[];
    float* Qs     = sm;                    // [128][72] paired-k tf32
    float* Ks     = Qs + QS_N;             // [64][72]  paired-k tf32 (row = j-col)
    float* Vs     = Ks + KS_N;             // [64][72]  plain [k][dv] tf32
    float* Ps     = Vs + VS_N;             // [128][72] plain [q][j] tf32
    float* rowsum = Ps + PS_N;             // 128
    float* invs   = rowsum + 128;          // 128
    int*   mrow   = (int*)(invs + 128);    // 128
    int*   mcol   = mrow + 128;            // 64

    const int bh = blockIdx.y, b = bh >> 3;
    const int row0 = blockIdx.x * 128;
    const int tid = threadIdx.x, lane = tid & 31, warp = tid >> 5;
    const int g = lane >> 2, t = lane & 3;
    const int wm = warp & 3, wn = warp >> 2;

    const float* qbase = g_qh + (size_t)bh * SS * 64;
    const float* kbase = g_kh + (size_t)bh * SS * 64;
    const float* vbase = g_vh + (size_t)bh * SS * 64;

    const int fr = tid >> 3;            // fill: 8 threads per row
    const int fcb = (tid & 7) << 3;     // 8-element block

    // ---- load Q tile (paired) ----
    #pragma unroll
    for (int sw = 0; sw < 4; sw++) {
        int r = fr + sw * 32;
        const float* src = qbase + ((size_t)(row0 + r) << 6) + fcb;
        float4 v0 = *(const float4*)src;
        float4 v1 = *(const float4*)(src + 4);
        float xs[8] = {v0.x, v0.y, v0.z, v0.w, v1.x, v1.y, v1.z, v1.w};
        float* d = Qs + r * 72 + fcb;
        #pragma unroll
        for (int i = 0; i < 4; i++)
            *(float2*)(d + 2 * i) = make_float2(tf32r(xs[i]), tf32r(xs[i + 4]));
    }
    if (tid < 128) { mrow[tid] = mask[b * SS + row0 + tid]; rowsum[tid] = 0.f; }

    float rp0[2] = {0.f, 0.f};
    float rp1[2] = {0.f, 0.f};

    // ---------------- PASS 1: rowsums --------------------------------------
    #pragma unroll 1
    for (int j0 = 0; j0 < SS; j0 += 64) {
        __syncthreads();
        #pragma unroll
        for (int sw = 0; sw < 2; sw++) {
            int r = fr + sw * 32;
            const float* src = kbase + ((size_t)(j0 + r) << 6) + fcb;
            float4 v0 = *(const float4*)src;
            float4 v1 = *(const float4*)(src + 4);
            float xs[8] = {v0.x, v0.y, v0.z, v0.w, v1.x, v1.y, v1.z, v1.w};
            float* d = Ks + r * 72 + fcb;
            #pragma unroll
            for (int i = 0; i < 4; i++)
                *(float2*)(d + 2 * i) = make_float2(tf32r(xs[i]), tf32r(xs[i + 4]));
        }
        if (tid < 64) mcol[tid] = mask[b * SS + j0 + tid];
        __syncthreads();

        float acc[2][4][4] = {};
        #pragma unroll
        for (int s = 0; s < 8; s++) {
            int kb = s * 8;
            float2 pa[2][2];
            #pragma unroll
            for (int mt = 0; mt < 2; mt++) {
                int r = wm * 32 + mt * 16 + g;
                pa[mt][0] = *(const float2*)(Qs + r * 72 + kb + 2 * t);
                pa[mt][1] = *(const float2*)(Qs + (r + 8) * 72 + kb + 2 * t);
            }
            #pragma unroll
            for (int nt = 0; nt < 4; nt++) {
                int c = wn * 32 + nt * 8 + g;
                float2 pb = *(const float2*)(Ks + c * 72 + kb + 2 * t);
                #pragma unroll
                for (int mt = 0; mt < 2; mt++)
                    mma_tf32(acc[mt][nt], pa[mt][0].x, pa[mt][1].x,
                             pa[mt][0].y, pa[mt][1].y, pb.x, pb.y);
            }
        }
        #pragma unroll
        for (int mt = 0; mt < 2; mt++) {
            int lr0 = wm * 32 + mt * 16 + g, lr1 = lr0 + 8;
            int m0 = mrow[lr0], m1 = mrow[lr1];
            int gr0 = row0 + lr0, gr1 = row0 + lr1;
            #pragma unroll
            for (int nt = 0; nt < 4; nt++) {
                int lc = wn * 32 + nt * 8 + 2 * t;
                int gc = j0 + lc;
                int mc0 = mcol[lc], mc1 = mcol[lc + 1];
                float p00 = ((m0 && mc0) || (gr0 == gc))     ? fexp2(acc[mt][nt][0] * EXP_C) : 1.0f;
                float p01 = ((m0 && mc1) || (gr0 == gc + 1)) ? fexp2(acc[mt][nt][1] * EXP_C) : 1.0f;
                float p10 = ((m1 && mc0) || (gr1 == gc))     ? fexp2(acc[mt][nt][2] * EXP_C) : 1.0f;
                float p11 = ((m1 && mc1) || (gr1 == gc + 1)) ? fexp2(acc[mt][nt][3] * EXP_C) : 1.0f;
                rp0[mt] += p00 + p01;
                rp1[mt] += p10 + p11;
            }
        }
    }
    #pragma unroll
    for (int mt = 0; mt < 2; mt++) {
        float s0 = rp0[mt], s1 = rp1[mt];
        s0 += __shfl_xor_sync(0xffffffffu, s0, 1); s0 += __shfl_xor_sync(0xffffffffu, s0, 2);
        s1 += __shfl_xor_sync(0xffffffffu, s1, 1); s1 += __shfl_xor_sync(0xffffffffu, s1, 2);
        if (t == 0) {
            atomicAdd(&rowsum[wm * 32 + mt * 16 + g], s0);
            atomicAdd(&rowsum[wm * 32 + mt * 16 + g + 8], s1);
        }
    }
    __syncthreads();
    if (tid < 128) invs[tid] = 1.0f / rowsum[tid];

    float oacc[2][4][4] = {};
    float* arow = attn + ((size_t)bh * SS + row0) * SS;

    // ---------------- PASS 2: attn write + P@V -----------------------------
    #pragma unroll 1
    for (int j0 = 0; j0 < SS; j0 += 64) {
        __syncthreads();
        #pragma unroll
        for (int sw = 0; sw < 2; sw++) {
            int r = fr + sw * 32;
            const float* src = kbase + ((size_t)(j0 + r) << 6) + fcb;
            float4 v0 = *(const float4*)src;
            float4 v1 = *(const float4*)(src + 4);
            float xs[8] = {v0.x, v0.y, v0.z, v0.w, v1.x, v1.y, v1.z, v1.w};
            float* d = Ks + r * 72 + fcb;
            #pragma unroll
            for (int i = 0; i < 4; i++)
                *(float2*)(d + 2 * i) = make_float2(tf32r(xs[i]), tf32r(xs[i + 4]));
            const float* vsrc = vbase + ((size_t)(j0 + r) << 6) + fcb;
            float4 w0 = *(const float4*)vsrc;
            float4 w1 = *(const float4*)(vsrc + 4);
            float4 c0 = make_float4(tf32r(w0.x), tf32r(w0.y), tf32r(w0.z), tf32r(w0.w));
            float4 c1 = make_float4(tf32r(w1.x), tf32r(w1.y), tf32r(w1.z), tf32r(w1.w));
            *(float4*)(Vs + r * 72 + fcb)     = c0;
            *(float4*)(Vs + r * 72 + fcb + 4) = c1;
        }
        if (tid < 64) mcol[tid] = mask[b * SS + j0 + tid];
        __syncthreads();

        float acc[2][4][4] = {};
        #pragma unroll
        for (int s = 0; s < 8; s++) {
            int kb = s * 8;
            float2 pa[2][2];
            #pragma unroll
            for (int mt = 0; mt < 2; mt++) {
                int r = wm * 32 + mt * 16 + g;
                pa[mt][0] = *(const float2*)(Qs + r * 72 + kb + 2 * t);
                pa[mt][1] = *(const float2*)(Qs + (r + 8) * 72 + kb + 2 * t);
            }
            #pragma unroll
            for (int nt = 0; nt < 4; nt++) {
                int c = wn * 32 + nt * 8 + g;
                float2 pb = *(const float2*)(Ks + c * 72 + kb + 2 * t);
                #pragma unroll
                for (int mt = 0; mt < 2; mt++)
                    mma_tf32(acc[mt][nt], pa[mt][0].x, pa[mt][1].x,
                             pa[mt][0].y, pa[mt][1].y, pb.x, pb.y);
            }
        }
        #pragma unroll
        for (int mt = 0; mt < 2; mt++) {
            int lr0 = wm * 32 + mt * 16 + g, lr1 = lr0 + 8;
            int m0 = mrow[lr0], m1 = mrow[lr1];
            int gr0 = row0 + lr0, gr1 = row0 + lr1;
            float iv0 = invs[lr0], iv1 = invs[lr1];
            #pragma unroll
            for (int nt = 0; nt < 4; nt++) {
                int lc = wn * 32 + nt * 8 + 2 * t;
                int gc = j0 + lc;
                int mc0 = mcol[lc], mc1 = mcol[lc + 1];
                float p00 = ((m0 && mc0) || (gr0 == gc))     ? fexp2(acc[mt][nt][0] * EXP_C) : 1.0f;
                float p01 = ((m0 && mc1) || (gr0 == gc + 1)) ? fexp2(acc[mt][nt][1] * EXP_C) : 1.0f;
                float p10 = ((m1 && mc0) || (gr1 == gc))     ? fexp2(acc[mt][nt][2] * EXP_C) : 1.0f;
                float p11 = ((m1 && mc1) || (gr1 == gc + 1)) ? fexp2(acc[mt][nt][3] * EXP_C) : 1.0f;
                p00 *= iv0; p01 *= iv0; p10 *= iv1; p11 *= iv1;
                *(float2*)(arow + (size_t)lr0 * SS + gc) = make_float2(p00, p01);
                *(float2*)(arow + (size_t)lr1 * SS + gc) = make_float2(p10, p11);
                *(float2*)(Ps + lr0 * 72 + lc) = make_float2(tf32r(p00), tf32r(p01));
                *(float2*)(Ps + lr1 * 72 + lc) = make_float2(tf32r(p10), tf32r(p11));
            }
        }
        __syncthreads();
        #pragma unroll
        for (int s = 0; s < 8; s++) {
            int kb = s * 8;
            float a[2][4];
            #pragma unroll
            for (int mt = 0; mt < 2; mt++) {
                int r = wm * 32 + mt * 16 + g;
                a[mt][0] = Ps[r * 72 + kb + t];       a[mt][1] = Ps[(r + 8) * 72 + kb + t];
                a[mt][2] = Ps[r * 72 + kb + t + 4];   a[mt][3] = Ps[(r + 8) * 72 + kb + t + 4];
            }
            #pragma unroll
            for (int nt = 0; nt < 4; nt++) {
                int c = wn * 32 + nt * 8 + g;
                float b0 = Vs[(kb + t) * 72 + c], b1 = Vs[(kb + t + 4) * 72 + c];
                #pragma unroll
                for (int mt = 0; mt < 2; mt++)
                    mma_tf32(oacc[mt][nt], a[mt][0], a[mt][1], a[mt][2], a[mt][3], b0, b1);
            }
        }
    }
    float* obase = g_oh + ((size_t)bh * SS + row0) * 64;
    #pragma unroll
    for (int mt = 0; mt < 2; mt++) {
        int lr0 = wm * 32 + mt * 16 + g, lr1 = lr0 + 8;
        #pragma unroll
        for (int nt = 0; nt < 4; nt++) {
            int lc = wn * 32 + nt * 8 + 2 * t;
            *(float2*)(obase + (size_t)lr0 * 64 + lc) = make_float2(oacc[mt][nt][0], oacc[mt][nt][1]);
            *(float2*)(obase + (size_t)lr1 * 64 + lc) = make_float2(oacc[mt][nt][2], oacc[mt][nt][3]);
        }
    }
}

// ---------------- kernel 3: O @ Wo + residual (plain tf32) -------------------
__global__ __launch_bounds__(256) void out_proj_kernel(const float* __restrict__ q,
                                                       const float* __restrict__ Wo) {
    __shared__ float As_[128][40];
    __shared__ float Bs_[32][136];

    const int row0 = blockIdx.y * 128, col0 = blockIdx.x * 128;
    const int tid = threadIdx.x, lane = tid & 31, warp = tid >> 5;
    const int g = lane >> 2, t = lane & 3;
    const int wm = warp & 3, wn = warp >> 2;

    const int bidx = row0 >> 11, srow0 = row0 & 2047;

    float acc[2][8][4] = {};

    for (int k0 = 0; k0 < DD; k0 += 32) {
        __syncthreads();
        {
            int h = k0 >> 6, dv0 = k0 & 63;
            const float* abase = g_oh + (((size_t)(bidx * HH + h) * SS + srow0) << 6) + dv0;
            #pragma unroll
            for (int i = 0; i < 4; i++) {
                int e = tid + i * 256;
                int r = e >> 3, c = (e & 7) << 2;
                float4 x = *(const float4*)(abase + ((size_t)r << 6) + c);
                As_[r][c] = tf32r(x.x); As_[r][c+1] = tf32r(x.y);
                As_[r][c+2] = tf32r(x.z); As_[r][c+3] = tf32r(x.w);
            }
        }
        #pragma unroll
        for (int i = 0; i < 4; i++) {
            int e = tid + i * 256;
            int kr = e >> 5, c = (e & 31) << 2;
            float4 x = *(const float4*)(Wo + (size_t)(k0 + kr) * DD + col0 + c);
            Bs_[kr][c] = tf32r(x.x); Bs_[kr][c+1] = tf32r(x.y);
            Bs_[kr][c+2] = tf32r(x.z); Bs_[kr][c+3] = tf32r(x.w);
        }
        __syncthreads();
        #pragma unroll
        for (int s = 0; s < 4; s++) {
            int kb = s * 8;
            float a[2][4];
            #pragma unroll
            for (int mt = 0; mt < 2; mt++) {
                int r = wm * 32 + mt * 16 + g;
                a[mt][0] = As_[r][kb + t];       a[mt][1] = As_[r + 8][kb + t];
                a[mt][2] = As_[r][kb + t + 4];   a[mt][3] = As_[r + 8][kb + t + 4];
            }
            #pragma unroll
            for (int nt = 0; nt < 8; nt++) {
                int c = wn * 64 + nt * 8 + g;
                float b0 = Bs_[kb + t][c], b1 = Bs_[kb + t + 4][c];
                #pragma unroll
                for (int mt = 0; mt < 2; mt++)
                    mma_tf32(acc[mt][nt], a[mt][0], a[mt][1], a[mt][2], a[mt][3], b0, b1);
            }
        }
    }
    #pragma unroll
    for (int mt = 0; mt < 2; mt++) {
        int r0 = row0 + wm * 32 + mt * 16 + g;
        #pragma unroll
        for (int nt = 0; nt < 8; nt++) {
            int col = col0 + wn * 64 + nt * 8 + 2 * t;
            size_t off0 = (size_t)r0 * DD + col;
            size_t off1 = (size_t)(r0 + 8) * DD + col;
            float2 q0 = *(const float2*)(q + off0);
            float2 q1 = *(const float2*)(q + off1);
            *(float2*)(g_y + off0) = make_float2(acc[mt][nt][0] + q0.x, acc[mt][nt][1] + q0.y);
            *(float2*)(g_y + off1) = make_float2(acc[mt][nt][2] + q1.x, acc[mt][nt][3] + q1.y);
        }
    }
}

// ---------------- kernel 4: LayerNorm ---------------------------------------
__global__ void ln_kernel(const float* __restrict__ gamma, const float* __restrict__ beta,
                          float* __restrict__ out) {
    const int row = blockIdx.x;
    const float* x = g_y + (size_t)row * DD;
    const int t = threadIdx.x;

    float v0 = x[t], v1 = x[t + 256];
    float s  = v0 + v1;
    float sq = v0 * v0 + v1 * v1;

    __shared__ float ssum[8], ssq[8];
    #pragma unroll
    for (int off = 16; off > 0; off >>= 1) {
        s  += __shfl_down_sync(0xffffffffu, s,  off);
        sq += __shfl_down_sync(0xffffffffu, sq, off);
    }
    if ((t & 31) == 0) { ssum[t >> 5] = s; ssq[t >> 5] = sq; }
    __syncthreads();
    if (t < 32) {
        float a = (t < 8) ? ssum[t] : 0.f;
        float b = (t < 8) ? ssq[t]  : 0.f;
        #pragma unroll
        for (int off = 4; off > 0; off >>= 1) {
            a += __shfl_down_sync(0xffffffffu, a, off);
            b += __shfl_down_sync(0xffffffffu, b, off);
        }
        if (t == 0) { ssum[0] = a; ssq[0] = b; }
    }
    __syncthreads();
    float mean = ssum[0] * (1.0f / DD);
    float var  = ssq[0]  * (1.0f / DD) - mean * mean;
    float rs   = rsqrtf(var + 1e-6f);

    out[(size_t)row * DD + t]       = (v0 - mean) * rs * gamma[t]       + beta[t];
    out[(size_t)row * DD + t + 256] = (v1 - mean) * rs * gamma[t + 256] + beta[t + 256];
}

// ---------------- launch -----------------------------------------------------
extern "C" void kernel_launch(void* const* d_in, const int* in_sizes, int n_in,
                              void* d_out, int out_size) {
    const float* q     = (const float*)d_in[0];
    const float* k     = (const float*)d_in[1];
    const float* v     = (const float*)d_in[2];
    const int*   mask  = (const int*)  d_in[3];
    const float* Wq    = (const float*)d_in[4];
    const float* Wk    = (const float*)d_in[5];
    const float* Wv    = (const float*)d_in[6];
    const float* Wo    = (const float*)d_in[7];
    const float* gamma = (const float*)d_in[8];
    const float* beta  = (const float*)d_in[9];

    float* out  = (float*)d_out;                  // [B,S,D]
    float* attn = out + (size_t)BB * SS * DD;     // [B,H,S,S]

    cudaFuncSetAttribute(attn_kernel, cudaFuncAttributeMaxDynamicSharedMemorySize, ATTN_SMEM);

    proj_kernel<<<dim3(DD/128, BSN/128, 3), 256>>>(q, k, v, Wq, Wk, Wv);
    attn_kernel<<<dim3(SS/128, BH), 256, ATTN_SMEM>>>(mask, attn);
    out_proj_kernel<<<dim3(DD/128, BSN/128), 256>>>(q, Wo);
    ln_kernel<<<BSN, 256>>>(gamma, beta, out);
}

// round 6
// speedup vs baseline: 1.8461x; 1.1690x over previous
#include <cuda_runtime.h>
#include <math.h>

#define BB 4
#define SS 2048
#define DD 512
#define HH 8
#define BH (BB*HH)
#define BSN (BB*SS)

// ---------------- scratch (device globals; no allocation allowed) ----------
__device__ float g_qh[(size_t)BH*SS*64];   // [bh, s, 64]
__device__ float g_kh[(size_t)BH*SS*64];
__device__ float g_vh[(size_t)BH*SS*64];
__device__ float g_oh[(size_t)BH*SS*64];
__device__ float g_y[(size_t)BSN*DD];

// ---------------- helpers -----------------------------------------------------
__device__ __forceinline__ float tf32r(float x) {
    unsigned u;
    asm("cvt.rna.tf32.f32 %0, %1;" : "=r"(u) : "f"(x));
    return __uint_as_float(u);
}

__device__ __forceinline__ void mma_tf32(float c[4],
        float a0, float a1, float a2, float a3, float b0, float b1) {
    asm("mma.sync.aligned.m16n8k8.row.col.f32.tf32.tf32.f32 "
        "{%0,%1,%2,%3},{%4,%5,%6,%7},{%8,%9},{%0,%1,%2,%3};"
        : "+f"(c[0]), "+f"(c[1]), "+f"(c[2]), "+f"(c[3])
        : "r"(__float_as_uint(a0)), "r"(__float_as_uint(a1)),
          "r"(__float_as_uint(a2)), "r"(__float_as_uint(a3)),
          "r"(__float_as_uint(b0)), "r"(__float_as_uint(b1)));
}

__device__ __forceinline__ unsigned bfpack(float lo, float hi) {
    unsigned r;
    asm("cvt.rn.bf16x2.f32 %0, %1, %2;" : "=r"(r) : "f"(hi), "f"(lo));
    return r;
}

__device__ __forceinline__ void mma_bf16(float c[4], unsigned a0, unsigned a1,
        unsigned a2, unsigned a3, unsigned b0, unsigned b1) {
    asm("mma.sync.aligned.m16n8k16.row.col.f32.bf16.bf16.f32 "
        "{%0,%1,%2,%3},{%4,%5,%6,%7},{%8,%9},{%0,%1,%2,%3};"
        : "+f"(c[0]), "+f"(c[1]), "+f"(c[2]), "+f"(c[3])
        : "r"(a0), "r"(a1), "r"(a2), "r"(a3), "r"(b0), "r"(b1));
}

__device__ __forceinline__ float fexp2(float x) {
    float y;
    asm("ex2.approx.f32 %0, %1;" : "=f"(y) : "f"(x));
    return y;
}
#define EXP_C 0.18033688011112042f   // log2(e)/8

// ---------------- kernel 1: fused QKV projections ---------------------------
// Q/K (z=0,1): B-operand split hi/lo (2 MMAs). V (z=2): plain tf32 (1 MMA).
__global__ __launch_bounds__(256) void proj_kernel(
        const float* __restrict__ q, const float* __restrict__ k,
        const float* __restrict__ v, const float* __restrict__ Wq,
        const float* __restrict__ Wk, const float* __restrict__ Wv) {
    __shared__ float Ash[128][20];
    __shared__ float Bsh[16][136];
    __shared__ float Bsl[16][136];

    const float* X; const float* W; float* Y;
    if (blockIdx.z == 0)      { X = q; W = Wq; Y = g_qh; }
    else if (blockIdx.z == 1) { X = k; W = Wk; Y = g_kh; }
    else                      { X = v; W = Wv; Y = g_vh; }
    const bool split = (blockIdx.z != 2);

    const int row0 = blockIdx.y * 128, col0 = blockIdx.x * 128;
    const int tid = threadIdx.x, lane = tid & 31, warp = tid >> 5;
    const int g = lane >> 2, t = lane & 3;
    const int wm = warp & 3, wn = warp >> 2;

    float acc[2][8][4] = {};

    const int ar = tid >> 1, acb = (tid & 1) << 3;
    const int bkr = tid >> 4, bcb = (tid & 15) << 3;

    for (int k0 = 0; k0 < DD; k0 += 16) {
        __syncthreads();
        {
            const float* src = X + (size_t)(row0 + ar) * DD + k0 + acb;
            float4 v0 = *(const float4*)src;
            float4 v1 = *(const float4*)(src + 4);
            float xs[8] = {v0.x, v0.y, v0.z, v0.w, v1.x, v1.y, v1.z, v1.w};
            #pragma unroll
            for (int i = 0; i < 8; i++) Ash[ar][acb + i] = tf32r(xs[i]);
        }
        {
            const float* src = W + (size_t)(k0 + bkr) * DD + col0 + bcb;
            float4 v0 = *(const float4*)src;
            float4 v1 = *(const float4*)(src + 4);
            float xs[8] = {v0.x, v0.y, v0.z, v0.w, v1.x, v1.y, v1.z, v1.w};
            #pragma unroll
            for (int i = 0; i < 8; i++) {
                float hi = tf32r(xs[i]);
                Bsh[bkr][bcb + i] = hi;
                if (split) Bsl[bkr][bcb + i] = tf32r(xs[i] - hi);
            }
        }
        __syncthreads();
        #pragma unroll
        for (int s = 0; s < 2; s++) {
            const int kb = s * 8;
            float a[2][4];
            #pragma unroll
            for (int mt = 0; mt < 2; mt++) {
                int r = wm * 32 + mt * 16 + g;
                a[mt][0] = Ash[r][kb + t];       a[mt][1] = Ash[r + 8][kb + t];
                a[mt][2] = Ash[r][kb + t + 4];   a[mt][3] = Ash[r + 8][kb + t + 4];
            }
            #pragma unroll
            for (int nt = 0; nt < 8; nt++) {
                int c = wn * 64 + nt * 8 + g;
                float bh0 = Bsh[kb + t][c], bh1 = Bsh[kb + t + 4][c];
                #pragma unroll
                for (int mt = 0; mt < 2; mt++)
                    mma_tf32(acc[mt][nt], a[mt][0], a[mt][1], a[mt][2], a[mt][3], bh0, bh1);
                if (split) {
                    float bl0 = Bsl[kb + t][c], bl1 = Bsl[kb + t + 4][c];
                    #pragma unroll
                    for (int mt = 0; mt < 2; mt++)
                        mma_tf32(acc[mt][nt], a[mt][0], a[mt][1], a[mt][2], a[mt][3], bl0, bl1);
                }
            }
        }
    }
    const int bidx = row0 >> 11;
    #pragma unroll
    for (int mt = 0; mt < 2; mt++) {
        int r0 = row0 + wm * 32 + mt * 16 + g;
        int s0 = r0 & 2047;
        #pragma unroll
        for (int nt = 0; nt < 8; nt++) {
            int col = col0 + wn * 64 + nt * 8 + 2 * t;
            int h = col >> 6, dk = col & 63;
            float* dst0 = Y + (((size_t)(bidx * HH + h) * SS + s0) << 6) + dk;
            float* dst1 = Y + (((size_t)(bidx * HH + h) * SS + s0 + 8) << 6) + dk;
            *(float2*)dst0 = make_float2(acc[mt][nt][0], acc[mt][nt][1]);
            *(float2*)dst1 = make_float2(acc[mt][nt][2], acc[mt][nt][3]);
        }
    }
}

// ---------------- kernel 2: fused attention ---------------------------------
// Pass 1: bf16 m16n8k16 QK -> rowsums. Pass 2: tf32 QK recompute -> normalized
// attn write (fp32) + bf16 P@V.
#define QS_N (128*72)
#define KS_N (64*72)
#define VS_N (64*72)
#define PS_N (128*72)
#define ATTN_SMEM ((QS_N + KS_N + VS_N + PS_N + 256)*4 + 192*4)

__global__ __launch_bounds__(256, 2) void attn_kernel(const int* __restrict__ mask,
                                                      float* __restrict__ attn) {
    extern __shared__ float sm[];
    float* Qs     = sm;                    // pass2: [128][72] paired-k tf32
    float* Ks     = Qs + QS_N;             // pass2: [64][72]  paired-k tf32
    float* Vs     = Ks + KS_N;             // pass2: bf16x2 [64 d][36 jw]
    float* Ps     = Vs + VS_N;             // pass2: bf16x2 [128 q][36 jw]
    float* rowsum = Ps + PS_N;             // 128
    float* invs   = rowsum + 128;          // 128
    int*   mrow   = (int*)(invs + 128);    // 128
    int*   mcol   = mrow + 128;            // 64

    unsigned* Qb = (unsigned*)Qs;          // pass1: [128][36] bf16x2
    unsigned* Kb = (unsigned*)Ks;          // pass1: [64][36]  bf16x2
    unsigned* Vb = (unsigned*)Vs;          // [64 d][36 jw] bf16x2 (V transposed)
    unsigned* Pb = (unsigned*)Ps;          // [128 q][36 jw] bf16x2

    const int bh = blockIdx.y, b = bh >> 3;
    const int row0 = blockIdx.x * 128;
    const int tid = threadIdx.x, lane = tid & 31, warp = tid >> 5;
    const int g = lane >> 2, t = lane & 3;
    const int wm = warp & 3, wn = warp >> 2;

    const float* qbase = g_qh + (size_t)bh * SS * 64;
    const float* kbase = g_kh + (size_t)bh * SS * 64;
    const float* vbase = g_vh + (size_t)bh * SS * 64;

    const int fr = tid >> 3;            // fill: 8 threads per row
    const int fcb = (tid & 7) << 3;     // 8-element block

    // ---- load Q tile as bf16x2 for pass 1 ----
    #pragma unroll
    for (int sw = 0; sw < 4; sw++) {
        int r = fr + sw * 32;
        const float* src = qbase + ((size_t)(row0 + r) << 6) + fcb;
        float4 v0 = *(const float4*)src;
        float4 v1 = *(const float4*)(src + 4);
        unsigned* d = Qb + r * 36 + (fcb >> 1);
        d[0] = bfpack(v0.x, v0.y); d[1] = bfpack(v0.z, v0.w);
        d[2] = bfpack(v1.x, v1.y); d[3] = bfpack(v1.z, v1.w);
    }
    if (tid < 128) { mrow[tid] = mask[b * SS + row0 + tid]; rowsum[tid] = 0.f; }

    float rp0[2] = {0.f, 0.f};
    float rp1[2] = {0.f, 0.f};

    // ---------------- PASS 1 (bf16): rowsums --------------------------------
    #pragma unroll 1
    for (int j0 = 0; j0 < SS; j0 += 64) {
        __syncthreads();
        #pragma unroll
        for (int sw = 0; sw < 2; sw++) {
            int r = fr + sw * 32;
            const float* src = kbase + ((size_t)(j0 + r) << 6) + fcb;
            float4 v0 = *(const float4*)src;
            float4 v1 = *(const float4*)(src + 4);
            unsigned* d = Kb + r * 36 + (fcb >> 1);
            d[0] = bfpack(v0.x, v0.y); d[1] = bfpack(v0.z, v0.w);
            d[2] = bfpack(v1.x, v1.y); d[3] = bfpack(v1.z, v1.w);
        }
        if (tid < 64) mcol[tid] = mask[b * SS + j0 + tid];
        __syncthreads();

        float acc[2][4][4] = {};
        #pragma unroll
        for (int s = 0; s < 4; s++) {
            int kw = s * 8;
            unsigned a[2][4];
            #pragma unroll
            for (int mt = 0; mt < 2; mt++) {
                int r = wm * 32 + mt * 16 + g;
                a[mt][0] = Qb[r * 36 + kw + t];        a[mt][1] = Qb[(r + 8) * 36 + kw + t];
                a[mt][2] = Qb[r * 36 + kw + t + 4];    a[mt][3] = Qb[(r + 8) * 36 + kw + t + 4];
            }
            #pragma unroll
            for (int nt = 0; nt < 4; nt++) {
                int c = wn * 32 + nt * 8 + g;
                unsigned b0 = Kb[c * 36 + kw + t], b1 = Kb[c * 36 + kw + t + 4];
                #pragma unroll
                for (int mt = 0; mt < 2; mt++)
                    mma_bf16(acc[mt][nt], a[mt][0], a[mt][1], a[mt][2], a[mt][3], b0, b1);
            }
        }
        #pragma unroll
        for (int mt = 0; mt < 2; mt++) {
            int lr0 = wm * 32 + mt * 16 + g, lr1 = lr0 + 8;
            int m0 = mrow[lr0], m1 = mrow[lr1];
            int gr0 = row0 + lr0, gr1 = row0 + lr1;
            #pragma unroll
            for (int nt = 0; nt < 4; nt++) {
                int lc = wn * 32 + nt * 8 + 2 * t;
                int gc = j0 + lc;
                int mc0 = mcol[lc], mc1 = mcol[lc + 1];
                float p00 = ((m0 && mc0) || (gr0 == gc))     ? fexp2(acc[mt][nt][0] * EXP_C) : 1.0f;
                float p01 = ((m0 && mc1) || (gr0 == gc + 1)) ? fexp2(acc[mt][nt][1] * EXP_C) : 1.0f;
                float p10 = ((m1 && mc0) || (gr1 == gc))     ? fexp2(acc[mt][nt][2] * EXP_C) : 1.0f;
                float p11 = ((m1 && mc1) || (gr1 == gc + 1)) ? fexp2(acc[mt][nt][3] * EXP_C) : 1.0f;
                rp0[mt] += p00 + p01;
                rp1[mt] += p10 + p11;
            }
        }
    }
    #pragma unroll
    for (int mt = 0; mt < 2; mt++) {
        float s0 = rp0[mt], s1 = rp1[mt];
        s0 += __shfl_xor_sync(0xffffffffu, s0, 1); s0 += __shfl_xor_sync(0xffffffffu, s0, 2);
        s1 += __shfl_xor_sync(0xffffffffu, s1, 1); s1 += __shfl_xor_sync(0xffffffffu, s1, 2);
        if (t == 0) {
            atomicAdd(&rowsum[wm * 32 + mt * 16 + g], s0);
            atomicAdd(&rowsum[wm * 32 + mt * 16 + g + 8], s1);
        }
    }
    __syncthreads();
    if (tid < 128) invs[tid] = 1.0f / rowsum[tid];

    // ---- reload Q tile as tf32-paired for pass 2 (overwrites Qb) ----
    #pragma unroll
    for (int sw = 0; sw < 4; sw++) {
        int r = fr + sw * 32;
        const float* src = qbase + ((size_t)(row0 + r) << 6) + fcb;
        float4 v0 = *(const float4*)src;
        float4 v1 = *(const float4*)(src + 4);
        float xs[8] = {v0.x, v0.y, v0.z, v0.w, v1.x, v1.y, v1.z, v1.w};
        float* d = Qs + r * 72 + fcb;
        #pragma unroll
        for (int i = 0; i < 4; i++)
            *(float2*)(d + 2 * i) = make_float2(tf32r(xs[i]), tf32r(xs[i + 4]));
    }

    float oacc[2][4][4] = {};
    float* arow = attn + ((size_t)bh * SS + row0) * SS;

    // V-transpose fill indices: thread -> (j-pair, 8 d's)
    const int vjp = tid & 31;           // j' = j/2, 0..31
    const int vd0 = (tid >> 5) << 3;    // d block of 8

    // ---------------- PASS 2: tf32 QK -> attn write + bf16 P@V --------------
    #pragma unroll 1
    for (int j0 = 0; j0 < SS; j0 += 64) {
        __syncthreads();
        #pragma unroll
        for (int sw = 0; sw < 2; sw++) {
            int r = fr + sw * 32;
            const float* src = kbase + ((size_t)(j0 + r) << 6) + fcb;
            float4 v0 = *(const float4*)src;
            float4 v1 = *(const float4*)(src + 4);
            float xs[8] = {v0.x, v0.y, v0.z, v0.w, v1.x, v1.y, v1.z, v1.w};
            float* d = Ks + r * 72 + fcb;
            #pragma unroll
            for (int i = 0; i < 4; i++)
                *(float2*)(d + 2 * i) = make_float2(tf32r(xs[i]), tf32r(xs[i + 4]));
        }
        {   // V tile transposed bf16x2: Vb[d][j'] = (v[2j'][d], v[2j'+1][d])
            const float* v0p = vbase + ((size_t)(j0 + 2 * vjp) << 6) + vd0;
            const float* v1p = v0p + 64;
            float4 a0 = *(const float4*)v0p;
            float4 a1 = *(const float4*)(v0p + 4);
            float4 b0 = *(const float4*)v1p;
            float4 b1 = *(const float4*)(v1p + 4);
            float e0[8] = {a0.x, a0.y, a0.z, a0.w, a1.x, a1.y, a1.z, a1.w};
            float e1[8] = {b0.x, b0.y, b0.z, b0.w, b1.x, b1.y, b1.z, b1.w};
            #pragma unroll
            for (int i = 0; i < 8; i++)
                Vb[(vd0 + i) * 36 + vjp] = bfpack(e0[i], e1[i]);
        }
        if (tid < 64) mcol[tid] = mask[b * SS + j0 + tid];
        __syncthreads();

        float acc[2][4][4] = {};
        #pragma unroll
        for (int s = 0; s < 8; s++) {
            int kb = s * 8;
            float2 pa[2][2];
            #pragma unroll
            for (int mt = 0; mt < 2; mt++) {
                int r = wm * 32 + mt * 16 + g;
                pa[mt][0] = *(const float2*)(Qs + r * 72 + kb + 2 * t);
                pa[mt][1] = *(const float2*)(Qs + (r + 8) * 72 + kb + 2 * t);
            }
            #pragma unroll
            for (int nt = 0; nt < 4; nt++) {
                int c = wn * 32 + nt * 8 + g;
                float2 pb = *(const float2*)(Ks + c * 72 + kb + 2 * t);
                #pragma unroll
                for (int mt = 0; mt < 2; mt++)
                    mma_tf32(acc[mt][nt], pa[mt][0].x, pa[mt][1].x,
                             pa[mt][0].y, pa[mt][1].y, pb.x, pb.y);
            }
        }
        #pragma unroll
        for (int mt = 0; mt < 2; mt++) {
            int lr0 = wm * 32 + mt * 16 + g, lr1 = lr0 + 8;
            int m0 = mrow[lr0], m1 = mrow[lr1];
            int gr0 = row0 + lr0, gr1 = row0 + lr1;
            float iv0 = invs[lr0], iv1 = invs[lr1];
            #pragma unroll
            for (int nt = 0; nt < 4; nt++) {
                int lc = wn * 32 + nt * 8 + 2 * t;
                int gc = j0 + lc;
                int mc0 = mcol[lc], mc1 = mcol[lc + 1];
                float p00 = ((m0 && mc0) || (gr0 == gc))     ? fexp2(acc[mt][nt][0] * EXP_C) : 1.0f;
                float p01 = ((m0 && mc1) || (gr0 == gc + 1)) ? fexp2(acc[mt][nt][1] * EXP_C) : 1.0f;
                float p10 = ((m1 && mc0) || (gr1 == gc))     ? fexp2(acc[mt][nt][2] * EXP_C) : 1.0f;
                float p11 = ((m1 && mc1) || (gr1 == gc + 1)) ? fexp2(acc[mt][nt][3] * EXP_C) : 1.0f;
                p00 *= iv0; p01 *= iv0; p10 *= iv1; p11 *= iv1;
                *(float2*)(arow + (size_t)lr0 * SS + gc) = make_float2(p00, p01);
                *(float2*)(arow + (size_t)lr1 * SS + gc) = make_float2(p10, p11);
                Pb[lr0 * 36 + (lc >> 1)] = bfpack(p00, p01);
                Pb[lr1 * 36 + (lc >> 1)] = bfpack(p10, p11);
            }
        }
        __syncthreads();
        #pragma unroll
        for (int s = 0; s < 4; s++) {
            int kw = s * 8;
            unsigned a[2][4];
            #pragma unroll
            for (int mt = 0; mt < 2; mt++) {
                int r = wm * 32 + mt * 16 + g;
                a[mt][0] = Pb[r * 36 + kw + t];        a[mt][1] = Pb[(r + 8) * 36 + kw + t];
                a[mt][2] = Pb[r * 36 + kw + t + 4];    a[mt][3] = Pb[(r + 8) * 36 + kw + t + 4];
            }
            #pragma unroll
            for (int nt = 0; nt < 4; nt++) {
                int c = wn * 32 + nt * 8 + g;
                unsigned b0 = Vb[c * 36 + kw + t], b1 = Vb[c * 36 + kw + t + 4];
                #pragma unroll
                for (int mt = 0; mt < 2; mt++)
                    mma_bf16(oacc[mt][nt], a[mt][0], a[mt][1], a[mt][2], a[mt][3], b0, b1);
            }
        }
    }
    float* obase = g_oh + ((size_t)bh * SS + row0) * 64;
    #pragma unroll
    for (int mt = 0; mt < 2; mt++) {
        int lr0 = wm * 32 + mt * 16 + g, lr1 = lr0 + 8;
        #pragma unroll
        for (int nt = 0; nt < 4; nt++) {
            int lc = wn * 32 + nt * 8 + 2 * t;
            *(float2*)(obase + (size_t)lr0 * 64 + lc) = make_float2(oacc[mt][nt][0], oacc[mt][nt][1]);
            *(float2*)(obase + (size_t)lr1 * 64 + lc) = make_float2(oacc[mt][nt][2], oacc[mt][nt][3]);
        }
    }
}

// ---------------- kernel 3: O @ Wo + residual (plain tf32) -------------------
__global__ __launch_bounds__(256) void out_proj_kernel(const float* __restrict__ q,
                                                       const float* __restrict__ Wo) {
    __shared__ float As_[128][40];
    __shared__ float Bs_[32][136];

    const int row0 = blockIdx.y * 128, col0 = blockIdx.x * 128;
    const int tid = threadIdx.x, lane = tid & 31, warp = tid >> 5;
    const int g = lane >> 2, t = lane & 3;
    const int wm = warp & 3, wn = warp >> 2;

    const int bidx = row0 >> 11, srow0 = row0 & 2047;

    float acc[2][8][4] = {};

    for (int k0 = 0; k0 < DD; k0 += 32) {
        __syncthreads();
        {
            int h = k0 >> 6, dv0 = k0 & 63;
            const float* abase = g_oh + (((size_t)(bidx * HH + h) * SS + srow0) << 6) + dv0;
            #pragma unroll
            for (int i = 0; i < 4; i++) {
                int e = tid + i * 256;
                int r = e >> 3, c = (e & 7) << 2;
                float4 x = *(const float4*)(abase + ((size_t)r << 6) + c);
                As_[r][c] = tf32r(x.x); As_[r][c+1] = tf32r(x.y);
                As_[r][c+2] = tf32r(x.z); As_[r][c+3] = tf32r(x.w);
            }
        }
        #pragma unroll
        for (int i = 0; i < 4; i++) {
            int e = tid + i * 256;
            int kr = e >> 5, c = (e & 31) << 2;
            float4 x = *(const float4*)(Wo + (size_t)(k0 + kr) * DD + col0 + c);
            Bs_[kr][c] = tf32r(x.x); Bs_[kr][c+1] = tf32r(x.y);
            Bs_[kr][c+2] = tf32r(x.z); Bs_[kr][c+3] = tf32r(x.w);
        }
        __syncthreads();
        #pragma unroll
        for (int s = 0; s < 4; s++) {
            int kb = s * 8;
            float a[2][4];
            #pragma unroll
            for (int mt = 0; mt < 2; mt++) {
                int r = wm * 32 + mt * 16 + g;
                a[mt][0] = As_[r][kb + t];       a[mt][1] = As_[r + 8][kb + t];
                a[mt][2] = As_[r][kb + t + 4];   a[mt][3] = As_[r + 8][kb + t + 4];
            }
            #pragma unroll
            for (int nt = 0; nt < 8; nt++) {
                int c = wn * 64 + nt * 8 + g;
                float b0 = Bs_[kb + t][c], b1 = Bs_[kb + t + 4][c];
                #pragma unroll
                for (int mt = 0; mt < 2; mt++)
                    mma_tf32(acc[mt][nt], a[mt][0], a[mt][1], a[mt][2], a[mt][3], b0, b1);
            }
        }
    }
    #pragma unroll
    for (int mt = 0; mt < 2; mt++) {
        int r0 = row0 + wm * 32 + mt * 16 + g;
        #pragma unroll
        for (int nt = 0; nt < 8; nt++) {
            int col = col0 + wn * 64 + nt * 8 + 2 * t;
            size_t off0 = (size_t)r0 * DD + col;
            size_t off1 = (size_t)(r0 + 8) * DD + col;
            float2 q0 = *(const float2*)(q + off0);
            float2 q1 = *(const float2*)(q + off1);
            *(float2*)(g_y + off0) = make_float2(acc[mt][nt][0] + q0.x, acc[mt][nt][1] + q0.y);
            *(float2*)(g_y + off1) = make_float2(acc[mt][nt][2] + q1.x, acc[mt][nt][3] + q1.y);
        }
    }
}

// ---------------- kernel 4: LayerNorm ---------------------------------------
__global__ void ln_kernel(const float* __restrict__ gamma, const float* __restrict__ beta,
                          float* __restrict__ out) {
    const int row = blockIdx.x;
    const float* x = g_y + (size_t)row * DD;
    const int t = threadIdx.x;

    float v0 = x[t], v1 = x[t + 256];
    float s  = v0 + v1;
    float sq = v0 * v0 + v1 * v1;

    __shared__ float ssum[8], ssq[8];
    #pragma unroll
    for (int off = 16; off > 0; off >>= 1) {
        s  += __shfl_down_sync(0xffffffffu, s,  off);
        sq += __shfl_down_sync(0xffffffffu, sq, off);
    }
    if ((t & 31) == 0) { ssum[t >> 5] = s; ssq[t >> 5] = sq; }
    __syncthreads();
    if (t < 32) {
        float a = (t < 8) ? ssum[t] : 0.f;
        float b = (t < 8) ? ssq[t]  : 0.f;
        #pragma unroll
        for (int off = 4; off > 0; off >>= 1) {
            a += __shfl_down_sync(0xffffffffu, a, off);
            b += __shfl_down_sync(0xffffffffu, b, off);
        }
        if (t == 0) { ssum[0] = a; ssq[0] = b; }
    }
    __syncthreads();
    float mean = ssum[0] * (1.0f / DD);
    float var  = ssq[0]  * (1.0f / DD) - mean * mean;
    float rs   = rsqrtf(var + 1e-6f);

    out[(size_t)row * DD + t]       = (v0 - mean) * rs * gamma[t]       + beta[t];
    out[(size_t)row * DD + t + 256] = (v1 - mean) * rs * gamma[t + 256] + beta[t + 256];
}

// ---------------- launch -----------------------------------------------------
extern "C" void kernel_launch(void* const* d_in, const int* in_sizes, int n_in,
                              void* d_out, int out_size) {
    const float* q     = (const float*)d_in[0];
    const float* k     = (const float*)d_in[1];
    const float* v     = (const float*)d_in[2];
    const int*   mask  = (const int*)  d_in[3];
    const float* Wq    = (const float*)d_in[4];
    const float* Wk    = (const float*)d_in[5];
    const float* Wv    = (const float*)d_in[6];
    const float* Wo    = (const float*)d_in[7];
    const float* gamma = (const float*)d_in[8];
    const float* beta  = (const float*)d_in[9];

    float* out  = (float*)d_out;                  // [B,S,D]
    float* attn = out + (size_t)BB * SS * DD;     // [B,H,S,S]

    cudaFuncSetAttribute(attn_kernel, cudaFuncAttributeMaxDynamicSharedMemorySize, ATTN_SMEM);

    proj_kernel<<<dim3(DD/128, BSN/128, 3), 256>>>(q, k, v, Wq, Wk, Wv);
    attn_kernel<<<dim3(SS/128, BH), 256, ATTN_SMEM>>>(mask, attn);
    out_proj_kernel<<<dim3(DD/128, BSN/128), 256>>>(q, Wo);
    ln_kernel<<<BSN, 256>>>(gamma, beta, out);
}

// round 8
// speedup vs baseline: 2.1636x; 1.1719x over previous
#include <cuda_runtime.h>
#include <math.h>
#include <cstdint>

#define BB 4
#define SS 2048
#define DD 512
#define HH 8
#define BH (BB*HH)
#define BSN (BB*SS)

// ---------------- scratch (device globals; no allocation allowed) ----------
__device__ float g_qh[(size_t)BH*SS*64];   // [bh, s, 64]
__device__ float g_kh[(size_t)BH*SS*64];
__device__ float g_vh[(size_t)BH*SS*64];
__device__ float g_oh[(size_t)BH*SS*64];
__device__ float g_y[(size_t)BSN*DD];
__device__ float g_wt[3*(size_t)DD*DD];    // W^T for q/k/v projections

// ---------------- helpers -----------------------------------------------------
__device__ __forceinline__ float tf32r(float x) {
    unsigned u;
    asm("cvt.rna.tf32.f32 %0, %1;" : "=r"(u) : "f"(x));
    return __uint_as_float(u);
}

__device__ __forceinline__ void mma_tf32(float c[4],
        float a0, float a1, float a2, float a3, float b0, float b1) {
    asm("mma.sync.aligned.m16n8k8.row.col.f32.tf32.tf32.f32 "
        "{%0,%1,%2,%3},{%4,%5,%6,%7},{%8,%9},{%0,%1,%2,%3};"
        : "+f"(c[0]), "+f"(c[1]), "+f"(c[2]), "+f"(c[3])
        : "r"(__float_as_uint(a0)), "r"(__float_as_uint(a1)),
          "r"(__float_as_uint(a2)), "r"(__float_as_uint(a3)),
          "r"(__float_as_uint(b0)), "r"(__float_as_uint(b1)));
}

__device__ __forceinline__ unsigned bfpack(float lo, float hi) {
    unsigned r;
    asm("cvt.rn.bf16x2.f32 %0, %1, %2;" : "=r"(r) : "f"(hi), "f"(lo));
    return r;
}

__device__ __forceinline__ void mma_bf16(float c[4], unsigned a0, unsigned a1,
        unsigned a2, unsigned a3, unsigned b0, unsigned b1) {
    asm("mma.sync.aligned.m16n8k16.row.col.f32.bf16.bf16.f32 "
        "{%0,%1,%2,%3},{%4,%5,%6,%7},{%8,%9},{%0,%1,%2,%3};"
        : "+f"(c[0]), "+f"(c[1]), "+f"(c[2]), "+f"(c[3])
        : "r"(a0), "r"(a1), "r"(a2), "r"(a3), "r"(b0), "r"(b1));
}

__device__ __forceinline__ float fexp2(float x) {
    float y;
    asm("ex2.approx.f32 %0, %1;" : "=f"(y) : "f"(x));
    return y;
}
#define EXP_C 0.18033688011112042f   // log2(e)/8

// split an fp32 pair into bf16x2 hi and lo words
__device__ __forceinline__ void bfsplit(float x, float y, unsigned& h, unsigned& l) {
    h = bfpack(x, y);
    float f0 = __uint_as_float(h << 16);
    float f1 = __uint_as_float(h & 0xFFFF0000u);
    l = bfpack(x - f0, y - f1);
}

// ---------------- kernel 0: transpose W (Wt[n][k] = W[k][n]) -----------------
__global__ __launch_bounds__(256) void wtrans_kernel(const float* __restrict__ Wq,
        const float* __restrict__ Wk, const float* __restrict__ Wv) {
    __shared__ float tile[32][33];
    const float* W = (blockIdx.z == 0) ? Wq : (blockIdx.z == 1) ? Wk : Wv;
    float* T = g_wt + (size_t)blockIdx.z * DD * DD;
    const int x0 = blockIdx.x * 32, y0 = blockIdx.y * 32;
    const int tx = threadIdx.x & 31, ty = threadIdx.x >> 5;   // 32 x 8
    #pragma unroll
    for (int i = 0; i < 32; i += 8)
        tile[ty + i][tx] = W[(size_t)(y0 + ty + i) * DD + x0 + tx];
    __syncthreads();
    #pragma unroll
    for (int i = 0; i < 32; i += 8)
        T[(size_t)(x0 + ty + i) * DD + y0 + tx] = tile[tx][ty + i];
}

// ---------------- kernel 1: QKV projection (split-bf16 mma.sync) -------------
// X[8192,512] @ W -> head layout. Q/K: 3-MMA hi/lo split. V: plain bf16.
// A: Xtile[128 m][64 k], B: Wt tile[128 n][64 k], both bf16x2 words, stride 36.
#define PJ_SMEM (4*128*36*4)

__global__ __launch_bounds__(256, 2) void proj_kernel(const float* __restrict__ q,
        const float* __restrict__ k, const float* __restrict__ v) {
    extern __shared__ unsigned ps[];
    unsigned* Ahi = ps;
    unsigned* Alo = Ahi + 128*36;
    unsigned* Bhi = Alo + 128*36;
    unsigned* Blo = Bhi + 128*36;

    const float* X; float* Y;
    if (blockIdx.z == 0)      { X = q; Y = g_qh; }
    else if (blockIdx.z == 1) { X = k; Y = g_kh; }
    else                      { X = v; Y = g_vh; }
    const float* Wt = g_wt + (size_t)blockIdx.z * DD * DD;
    const bool split = (blockIdx.z != 2);

    const int row0 = blockIdx.y * 128, col0 = blockIdx.x * 128;
    const int tid = threadIdx.x, lane = tid & 31, warp = tid >> 5;
    const int g = lane >> 2, t = lane & 3;
    const int wm = warp & 3, wn = warp >> 2;

    const int fr = tid >> 3;            // 32 rows per sweep
    const int fcb = (tid & 7) << 3;     // 8-elem block
    const int fw = fcb >> 1;            // word offset

    float acc[2][8][4] = {};

    for (int c = 0; c < 8; c++) {
        const int k0 = c * 64;
        __syncthreads();
        #pragma unroll
        for (int sw = 0; sw < 4; sw++) {
            int r = fr + sw * 32;
            {   // A = X rows
                const float* src = X + (size_t)(row0 + r) * DD + k0 + fcb;
                float4 v0 = *(const float4*)src;
                float4 v1 = *(const float4*)(src + 4);
                unsigned h0, h1, h2, h3, l0, l1, l2, l3;
                bfsplit(v0.x, v0.y, h0, l0); bfsplit(v0.z, v0.w, h1, l1);
                bfsplit(v1.x, v1.y, h2, l2); bfsplit(v1.z, v1.w, h3, l3);
                *(uint4*)(Ahi + r*36 + fw) = make_uint4(h0, h1, h2, h3);
                if (split) *(uint4*)(Alo + r*36 + fw) = make_uint4(l0, l1, l2, l3);
            }
            {   // B = Wt rows (= output cols)
                const float* src = Wt + (size_t)(col0 + r) * DD + k0 + fcb;
                float4 v0 = *(const float4*)src;
                float4 v1 = *(const float4*)(src + 4);
                unsigned h0, h1, h2, h3, l0, l1, l2, l3;
                bfsplit(v0.x, v0.y, h0, l0); bfsplit(v0.z, v0.w, h1, l1);
                bfsplit(v1.x, v1.y, h2, l2); bfsplit(v1.z, v1.w, h3, l3);
                *(uint4*)(Bhi + r*36 + fw) = make_uint4(h0, h1, h2, h3);
                if (split) *(uint4*)(Blo + r*36 + fw) = make_uint4(l0, l1, l2, l3);
            }
        }
        __syncthreads();
        #pragma unroll
        for (int s = 0; s < 4; s++) {
            const int kw = s * 8;
            unsigned ah[2][4], al[2][4];
            #pragma unroll
            for (int mt = 0; mt < 2; mt++) {
                int r = wm * 32 + mt * 16 + g;
                ah[mt][0] = Ahi[r*36 + kw + t];       ah[mt][1] = Ahi[(r+8)*36 + kw + t];
                ah[mt][2] = Ahi[r*36 + kw + t + 4];   ah[mt][3] = Ahi[(r+8)*36 + kw + t + 4];
                if (split) {
                    al[mt][0] = Alo[r*36 + kw + t];       al[mt][1] = Alo[(r+8)*36 + kw + t];
                    al[mt][2] = Alo[r*36 + kw + t + 4];   al[mt][3] = Alo[(r+8)*36 + kw + t + 4];
                }
            }
            #pragma unroll
            for (int nt = 0; nt < 8; nt++) {
                int cc = wn * 64 + nt * 8 + g;
                unsigned bh0 = Bhi[cc*36 + kw + t], bh1 = Bhi[cc*36 + kw + t + 4];
                #pragma unroll
                for (int mt = 0; mt < 2; mt++)
                    mma_bf16(acc[mt][nt], ah[mt][0], ah[mt][1], ah[mt][2], ah[mt][3], bh0, bh1);
                if (split) {
                    unsigned bl0 = Blo[cc*36 + kw + t], bl1 = Blo[cc*36 + kw + t + 4];
                    #pragma unroll
                    for (int mt = 0; mt < 2; mt++) {
                        mma_bf16(acc[mt][nt], ah[mt][0], ah[mt][1], ah[mt][2], ah[mt][3], bl0, bl1);
                        mma_bf16(acc[mt][nt], al[mt][0], al[mt][1], al[mt][2], al[mt][3], bh0, bh1);
                    }
                }
            }
        }
    }
    const int bidx = row0 >> 11;
    #pragma unroll
    for (int mt = 0; mt < 2; mt++) {
        int r0 = row0 + wm * 32 + mt * 16 + g;
        int s0 = r0 & 2047;
        #pragma unroll
        for (int nt = 0; nt < 8; nt++) {
            int col = col0 + wn * 64 + nt * 8 + 2 * t;
            int h = col >> 6, dk = col & 63;
            float* dst0 = Y + (((size_t)(bidx * HH + h) * SS + s0) << 6) + dk;
            float* dst1 = Y + (((size_t)(bidx * HH + h) * SS + s0 + 8) << 6) + dk;
            *(float2*)dst0 = make_float2(acc[mt][nt][0], acc[mt][nt][1]);
            *(float2*)dst1 = make_float2(acc[mt][nt][2], acc[mt][nt][3]);
        }
    }
}

// ---------------- kernel 2: fused attention ---------------------------------
// Pass 1: plain-bf16 QK -> rowsums. Pass 2: split-bf16 QK (3 MMA) -> normalized
// attn write + plain-bf16 P@V. Q hi/lo persist across both passes.
#define ATTN_WORDS (4608*3 + 2304*3 + 448)
#define ATTN_SMEM (ATTN_WORDS*4)

__global__ __launch_bounds__(256, 2) void attn_kernel(const int* __restrict__ mask,
                                                      float* __restrict__ attn) {
    extern __shared__ unsigned usm[];
    unsigned* Qhi = usm;                  // [128][36]
    unsigned* Qlo = Qhi + 4608;           // [128][36]
    unsigned* Khi = Qlo + 4608;           // [64][36]
    unsigned* Klo = Khi + 2304;           // [64][36]
    unsigned* Vb  = Klo + 2304;           // [64 d][36 j'] transposed
    unsigned* Pb  = Vb  + 2304;           // [128][36]
    float* rowsum = (float*)(Pb + 4608);  // 128
    float* invs   = rowsum + 128;         // 128
    int*   mrow   = (int*)(invs + 128);   // 128
    int*   mcol   = mrow + 128;           // 64

    const int bh = blockIdx.y, b = bh >> 3;
    const int row0 = blockIdx.x * 128;
    const int tid = threadIdx.x, lane = tid & 31, warp = tid >> 5;
    const int g = lane >> 2, t = lane & 3;
    const int wm = warp & 3, wn = warp >> 2;

    const float* qbase = g_qh + (size_t)bh * SS * 64;
    const float* kbase = g_kh + (size_t)bh * SS * 64;
    const float* vbase = g_vh + (size_t)bh * SS * 64;

    const int fr = tid >> 3;
    const int fcb = (tid & 7) << 3;
    const int fw = fcb >> 1;

    // ---- load Q tile hi+lo (persists across both passes) ----
    #pragma unroll
    for (int sw = 0; sw < 4; sw++) {
        int r = fr + sw * 32;
        const float* src = qbase + ((size_t)(row0 + r) << 6) + fcb;
        float4 v0 = *(const float4*)src;
        float4 v1 = *(const float4*)(src + 4);
        unsigned h0, h1, h2, h3, l0, l1, l2, l3;
        bfsplit(v0.x, v0.y, h0, l0); bfsplit(v0.z, v0.w, h1, l1);
        bfsplit(v1.x, v1.y, h2, l2); bfsplit(v1.z, v1.w, h3, l3);
        *(uint4*)(Qhi + r*36 + fw) = make_uint4(h0, h1, h2, h3);
        *(uint4*)(Qlo + r*36 + fw) = make_uint4(l0, l1, l2, l3);
    }
    if (tid < 128) { mrow[tid] = mask[b * SS + row0 + tid]; rowsum[tid] = 0.f; }

    float rp0[2] = {0.f, 0.f};
    float rp1[2] = {0.f, 0.f};

    // ---------------- PASS 1 (plain bf16): rowsums --------------------------
    #pragma unroll 1
    for (int j0 = 0; j0 < SS; j0 += 64) {
        __syncthreads();
        #pragma unroll
        for (int sw = 0; sw < 2; sw++) {
            int r = fr + sw * 32;
            const float* src = kbase + ((size_t)(j0 + r) << 6) + fcb;
            float4 v0 = *(const float4*)src;
            float4 v1 = *(const float4*)(src + 4);
            *(uint4*)(Khi + r*36 + fw) = make_uint4(
                bfpack(v0.x, v0.y), bfpack(v0.z, v0.w),
                bfpack(v1.x, v1.y), bfpack(v1.z, v1.w));
        }
        if (tid < 64) mcol[tid] = mask[b * SS + j0 + tid];
        __syncthreads();

        float acc[2][4][4] = {};
        #pragma unroll
        for (int s = 0; s < 4; s++) {
            int kw = s * 8;
            unsigned a[2][4];
            #pragma unroll
            for (int mt = 0; mt < 2; mt++) {
                int r = wm * 32 + mt * 16 + g;
                a[mt][0] = Qhi[r*36 + kw + t];        a[mt][1] = Qhi[(r+8)*36 + kw + t];
                a[mt][2] = Qhi[r*36 + kw + t + 4];    a[mt][3] = Qhi[(r+8)*36 + kw + t + 4];
            }
            #pragma unroll
            for (int nt = 0; nt < 4; nt++) {
                int c = wn * 32 + nt * 8 + g;
                unsigned b0 = Khi[c*36 + kw + t], b1 = Khi[c*36 + kw + t + 4];
                #pragma unroll
                for (int mt = 0; mt < 2; mt++)
                    mma_bf16(acc[mt][nt], a[mt][0], a[mt][1], a[mt][2], a[mt][3], b0, b1);
            }
        }
        #pragma unroll
        for (int mt = 0; mt < 2; mt++) {
            int lr0 = wm * 32 + mt * 16 + g, lr1 = lr0 + 8;
            int m0 = mrow[lr0], m1 = mrow[lr1];
            int gr0 = row0 + lr0, gr1 = row0 + lr1;
            #pragma unroll
            for (int nt = 0; nt < 4; nt++) {
                int lc = wn * 32 + nt * 8 + 2 * t;
                int gc = j0 + lc;
                int mc0 = mcol[lc], mc1 = mcol[lc + 1];
                float p00 = ((m0 && mc0) || (gr0 == gc))     ? fexp2(acc[mt][nt][0] * EXP_C) : 1.0f;
                float p01 = ((m0 && mc1) || (gr0 == gc + 1)) ? fexp2(acc[mt][nt][1] * EXP_C) : 1.0f;
                float p10 = ((m1 && mc0) || (gr1 == gc))     ? fexp2(acc[mt][nt][2] * EXP_C) : 1.0f;
                float p11 = ((m1 && mc1) || (gr1 == gc + 1)) ? fexp2(acc[mt][nt][3] * EXP_C) : 1.0f;
                rp0[mt] += p00 + p01;
                rp1[mt] += p10 + p11;
            }
        }
    }
    #pragma unroll
    for (int mt = 0; mt < 2; mt++) {
        float s0 = rp0[mt], s1 = rp1[mt];
        s0 += __shfl_xor_sync(0xffffffffu, s0, 1); s0 += __shfl_xor_sync(0xffffffffu, s0, 2);
        s1 += __shfl_xor_sync(0xffffffffu, s1, 1); s1 += __shfl_xor_sync(0xffffffffu, s1, 2);
        if (t == 0) {
            atomicAdd(&rowsum[wm * 32 + mt * 16 + g], s0);
            atomicAdd(&rowsum[wm * 32 + mt * 16 + g + 8], s1);
        }
    }
    __syncthreads();
    if (tid < 128) invs[tid] = 1.0f / rowsum[tid];

    float oacc[2][4][4] = {};
    float* arow = attn + ((size_t)bh * SS + row0) * SS;

    const int vjp = tid & 31;           // j' = j/2
    const int vd0 = (tid >> 5) << 3;    // d block of 8

    // ---------------- PASS 2: split-bf16 QK -> attn write + bf16 P@V --------
    #pragma unroll 1
    for (int j0 = 0; j0 < SS; j0 += 64) {
        __syncthreads();
        #pragma unroll
        for (int sw = 0; sw < 2; sw++) {
            int r = fr + sw * 32;
            const float* src = kbase + ((size_t)(j0 + r) << 6) + fcb;
            float4 v0 = *(const float4*)src;
            float4 v1 = *(const float4*)(src + 4);
            unsigned h0, h1, h2, h3, l0, l1, l2, l3;
            bfsplit(v0.x, v0.y, h0, l0); bfsplit(v0.z, v0.w, h1, l1);
            bfsplit(v1.x, v1.y, h2, l2); bfsplit(v1.z, v1.w, h3, l3);
            *(uint4*)(Khi + r*36 + fw) = make_uint4(h0, h1, h2, h3);
            *(uint4*)(Klo + r*36 + fw) = make_uint4(l0, l1, l2, l3);
        }
        {   // V tile transposed bf16x2: Vb[d][j'] = (v[2j'][d], v[2j'+1][d])
            const float* v0p = vbase + ((size_t)(j0 + 2 * vjp) << 6) + vd0;
            const float* v1p = v0p + 64;
            float4 a0 = *(const float4*)v0p;
            float4 a1 = *(const float4*)(v0p + 4);
            float4 b0 = *(const float4*)v1p;
            float4 b1 = *(const float4*)(v1p + 4);
            float e0[8] = {a0.x, a0.y, a0.z, a0.w, a1.x, a1.y, a1.z, a1.w};
            float e1[8] = {b0.x, b0.y, b0.z, b0.w, b1.x, b1.y, b1.z, b1.w};
            #pragma unroll
            for (int i = 0; i < 8; i++)
                Vb[(vd0 + i) * 36 + vjp] = bfpack(e0[i], e1[i]);
        }
        if (tid < 64) mcol[tid] = mask[b * SS + j0 + tid];
        __syncthreads();

        float acc[2][4][4] = {};
        #pragma unroll
        for (int s = 0; s < 4; s++) {
            int kw = s * 8;
            unsigned ah[2][4], al[2][4];
            #pragma unroll
            for (int mt = 0; mt < 2; mt++) {
                int r = wm * 32 + mt * 16 + g;
                ah[mt][0] = Qhi[r*36 + kw + t];        ah[mt][1] = Qhi[(r+8)*36 + kw + t];
                ah[mt][2] = Qhi[r*36 + kw + t + 4];    ah[mt][3] = Qhi[(r+8)*36 + kw + t + 4];
                al[mt][0] = Qlo[r*36 + kw + t];        al[mt][1] = Qlo[(r+8)*36 + kw + t];
                al[mt][2] = Qlo[r*36 + kw + t + 4];    al[mt][3] = Qlo[(r+8)*36 + kw + t + 4];
            }
            #pragma unroll
            for (int nt = 0; nt < 4; nt++) {
                int c = wn * 32 + nt * 8 + g;
                unsigned bh0 = Khi[c*36 + kw + t], bh1 = Khi[c*36 + kw + t + 4];
                unsigned bl0 = Klo[c*36 + kw + t], bl1 = Klo[c*36 + kw + t + 4];
                #pragma unroll
                for (int mt = 0; mt < 2; mt++) {
                    mma_bf16(acc[mt][nt], ah[mt][0], ah[mt][1], ah[mt][2], ah[mt][3], bh0, bh1);
                    mma_bf16(acc[mt][nt], ah[mt][0], ah[mt][1], ah[mt][2], ah[mt][3], bl0, bl1);
                    mma_bf16(acc[mt][nt], al[mt][0], al[mt][1], al[mt][2], al[mt][3], bh0, bh1);
                }
            }
        }
        #pragma unroll
        for (int mt = 0; mt < 2; mt++) {
            int lr0 = wm * 32 + mt * 16 + g, lr1 = lr0 + 8;
            int m0 = mrow[lr0], m1 = mrow[lr1];
            int gr0 = row0 + lr0, gr1 = row0 + lr1;
            float iv0 = invs[lr0], iv1 = invs[lr1];
            #pragma unroll
            for (int nt = 0; nt < 4; nt++) {
                int lc = wn * 32 + nt * 8 + 2 * t;
                int gc = j0 + lc;
                int mc0 = mcol[lc], mc1 = mcol[lc + 1];
                float p00 = ((m0 && mc0) || (gr0 == gc))     ? fexp2(acc[mt][nt][0] * EXP_C) : 1.0f;
                float p01 = ((m0 && mc1) || (gr0 == gc + 1)) ? fexp2(acc[mt][nt][1] * EXP_C) : 1.0f;
                float p10 = ((m1 && mc0) || (gr1 == gc))     ? fexp2(acc[mt][nt][2] * EXP_C) : 1.0f;
                float p11 = ((m1 && mc1) || (gr1 == gc + 1)) ? fexp2(acc[mt][nt][3] * EXP_C) : 1.0f;
                p00 *= iv0; p01 *= iv0; p10 *= iv1; p11 *= iv1;
                *(float2*)(arow + (size_t)lr0 * SS + gc) = make_float2(p00, p01);
                *(float2*)(arow + (size_t)lr1 * SS + gc) = make_float2(p10, p11);
                Pb[lr0 * 36 + (lc >> 1)] = bfpack(p00, p01);
                Pb[lr1 * 36 + (lc >> 1)] = bfpack(p10, p11);
            }
        }
        __syncthreads();
        #pragma unroll
        for (int s = 0; s < 4; s++) {
            int kw = s * 8;
            unsigned a[2][4];
            #pragma unroll
            for (int mt = 0; mt < 2; mt++) {
                int r = wm * 32 + mt * 16 + g;
                a[mt][0] = Pb[r * 36 + kw + t];        a[mt][1] = Pb[(r + 8) * 36 + kw + t];
                a[mt][2] = Pb[r * 36 + kw + t + 4];    a[mt][3] = Pb[(r + 8) * 36 + kw + t + 4];
            }
            #pragma unroll
            for (int nt = 0; nt < 4; nt++) {
                int c = wn * 32 + nt * 8 + g;
                unsigned b0 = Vb[c * 36 + kw + t], b1 = Vb[c * 36 + kw + t + 4];
                #pragma unroll
                for (int mt = 0; mt < 2; mt++)
                    mma_bf16(oacc[mt][nt], a[mt][0], a[mt][1], a[mt][2], a[mt][3], b0, b1);
            }
        }
    }
    float* obase = g_oh + ((size_t)bh * SS + row0) * 64;
    #pragma unroll
    for (int mt = 0; mt < 2; mt++) {
        int lr0 = wm * 32 + mt * 16 + g, lr1 = lr0 + 8;
        #pragma unroll
        for (int nt = 0; nt < 4; nt++) {
            int lc = wn * 32 + nt * 8 + 2 * t;
            *(float2*)(obase + (size_t)lr0 * 64 + lc) = make_float2(oacc[mt][nt][0], oacc[mt][nt][1]);
            *(float2*)(obase + (size_t)lr1 * 64 + lc) = make_float2(oacc[mt][nt][2], oacc[mt][nt][3]);
        }
    }
}

// ---------------- kernel 3: O @ Wo + residual (plain tf32) -------------------
__global__ __launch_bounds__(256) void out_proj_kernel(const float* __restrict__ q,
                                                       const float* __restrict__ Wo) {
    __shared__ float As_[128][40];
    __shared__ float Bs_[32][136];

    const int row0 = blockIdx.y * 128, col0 = blockIdx.x * 128;
    const int tid = threadIdx.x, lane = tid & 31, warp = tid >> 5;
    const int g = lane >> 2, t = lane & 3;
    const int wm = warp & 3, wn = warp >> 2;

    const int bidx = row0 >> 11, srow0 = row0 & 2047;

    float acc[2][8][4] = {};

    for (int k0 = 0; k0 < DD; k0 += 32) {
        __syncthreads();
        {
            int h = k0 >> 6, dv0 = k0 & 63;
            const float* abase = g_oh + (((size_t)(bidx * HH + h) * SS + srow0) << 6) + dv0;
            #pragma unroll
            for (int i = 0; i < 4; i++) {
                int e = tid + i * 256;
                int r = e >> 3, c = (e & 7) << 2;
                float4 x = *(const float4*)(abase + ((size_t)r << 6) + c);
                As_[r][c] = tf32r(x.x); As_[r][c+1] = tf32r(x.y);
                As_[r][c+2] = tf32r(x.z); As_[r][c+3] = tf32r(x.w);
            }
        }
        #pragma unroll
        for (int i = 0; i < 4; i++) {
            int e = tid + i * 256;
            int kr = e >> 5, c = (e & 31) << 2;
            float4 x = *(const float4*)(Wo + (size_t)(k0 + kr) * DD + col0 + c);
            Bs_[kr][c] = tf32r(x.x); Bs_[kr][c+1] = tf32r(x.y);
            Bs_[kr][c+2] = tf32r(x.z); Bs_[kr][c+3] = tf32r(x.w);
        }
        __syncthreads();
        #pragma unroll
        for (int s = 0; s < 4; s++) {
            int kb = s * 8;
            float a[2][4];
            #pragma unroll
            for (int mt = 0; mt < 2; mt++) {
                int r = wm * 32 + mt * 16 + g;
                a[mt][0] = As_[r][kb + t];       a[mt][1] = As_[r + 8][kb + t];
                a[mt][2] = As_[r][kb + t + 4];   a[mt][3] = As_[r + 8][kb + t + 4];
            }
            #pragma unroll
            for (int nt = 0; nt < 8; nt++) {
                int c = wn * 64 + nt * 8 + g;
                float b0 = Bs_[kb + t][c], b1 = Bs_[kb + t + 4][c];
                #pragma unroll
                for (int mt = 0; mt < 2; mt++)
                    mma_tf32(acc[mt][nt], a[mt][0], a[mt][1], a[mt][2], a[mt][3], b0, b1);
            }
        }
    }
    #pragma unroll
    for (int mt = 0; mt < 2; mt++) {
        int r0 = row0 + wm * 32 + mt * 16 + g;
        #pragma unroll
        for (int nt = 0; nt < 8; nt++) {
            int col = col0 + wn * 64 + nt * 8 + 2 * t;
            size_t off0 = (size_t)r0 * DD + col;
            size_t off1 = (size_t)(r0 + 8) * DD + col;
            float2 q0 = *(const float2*)(q + off0);
            float2 q1 = *(const float2*)(q + off1);
            *(float2*)(g_y + off0) = make_float2(acc[mt][nt][0] + q0.x, acc[mt][nt][1] + q0.y);
            *(float2*)(g_y + off1) = make_float2(acc[mt][nt][2] + q1.x, acc[mt][nt][3] + q1.y);
        }
    }
}

// ---------------- kernel 4: LayerNorm ---------------------------------------
__global__ void ln_kernel(const float* __restrict__ gamma, const float* __restrict__ beta,
                          float* __restrict__ out) {
    const int row = blockIdx.x;
    const float* x = g_y + (size_t)row * DD;
    const int t = threadIdx.x;

    float v0 = x[t], v1 = x[t + 256];
    float s  = v0 + v1;
    float sq = v0 * v0 + v1 * v1;

    __shared__ float ssum[8], ssq[8];
    #pragma unroll
    for (int off = 16; off > 0; off >>= 1) {
        s  += __shfl_down_sync(0xffffffffu, s,  off);
        sq += __shfl_down_sync(0xffffffffu, sq, off);
    }
    if ((t & 31) == 0) { ssum[t >> 5] = s; ssq[t >> 5] = sq; }
    __syncthreads();
    if (t < 32) {
        float a = (t < 8) ? ssum[t] : 0.f;
        float b = (t < 8) ? ssq[t]  : 0.f;
        #pragma unroll
        for (int off = 4; off > 0; off >>= 1) {
            a += __shfl_down_sync(0xffffffffu, a, off);
            b += __shfl_down_sync(0xffffffffu, b, off);
        }
        if (t == 0) { ssum[0] = a; ssq[0] = b; }
    }
    __syncthreads();
    float mean = ssum[0] * (1.0f / DD);
    float var  = ssq[0]  * (1.0f / DD) - mean * mean;
    float rs   = rsqrtf(var + 1e-6f);

    out[(size_t)row * DD + t]       = (v0 - mean) * rs * gamma[t]       + beta[t];
    out[(size_t)row * DD + t + 256] = (v1 - mean) * rs * gamma[t + 256] + beta[t + 256];
}

// ---------------- launch -----------------------------------------------------
extern "C" void kernel_launch(void* const* d_in, const int* in_sizes, int n_in,
                              void* d_out, int out_size) {
    const float* q     = (const float*)d_in[0];
    const float* k     = (const float*)d_in[1];
    const float* v     = (const float*)d_in[2];
    const int*   mask  = (const int*)  d_in[3];
    const float* Wq    = (const float*)d_in[4];
    const float* Wk    = (const float*)d_in[5];
    const float* Wv    = (const float*)d_in[6];
    const float* Wo    = (const float*)d_in[7];
    const float* gamma = (const float*)d_in[8];
    const float* beta  = (const float*)d_in[9];

    float* out  = (float*)d_out;                  // [B,S,D]
    float* attn = out + (size_t)BB * SS * DD;     // [B,H,S,S]

    cudaFuncSetAttribute(attn_kernel, cudaFuncAttributeMaxDynamicSharedMemorySize, ATTN_SMEM);
    cudaFuncSetAttribute(proj_kernel, cudaFuncAttributeMaxDynamicSharedMemorySize, PJ_SMEM);

    wtrans_kernel<<<dim3(16, 16, 3), 256>>>(Wq, Wk, Wv);
    proj_kernel<<<dim3(DD/128, BSN/128, 3), 256, PJ_SMEM>>>(q, k, v);
    attn_kernel<<<dim3(SS/128, BH), 256, ATTN_SMEM>>>(mask, attn);
    out_proj_kernel<<<dim3(DD/128, BSN/128), 256>>>(q, Wo);
    ln_kernel<<<BSN, 256>>>(gamma, beta, out);
}

// round 9
// speedup vs baseline: 2.4980x; 1.1546x over previous
#include <cuda_runtime.h>
#include <cuda_fp16.h>
#include <math.h>
#include <cstdint>

#define BB 4
#define SS 2048
#define DD 512
#define HH 8
#define BH (BB*HH)
#define BSN (BB*SS)

// ---------------- scratch (device globals; no allocation allowed) ----------
__device__ float g_qh[(size_t)BH*SS*64];   // [bh, s, 64]
__device__ float g_kh[(size_t)BH*SS*64];
__device__ float g_vh[(size_t)BH*SS*64];
__device__ float g_oh[(size_t)BH*SS*64];
__device__ float g_y[(size_t)BSN*DD];
__device__ float g_wt[4*(size_t)DD*DD];    // W^T for q/k/v/o projections

// ---------------- helpers -----------------------------------------------------
__device__ __forceinline__ unsigned fppack(float lo, float hi) {
    __half2 h = __floats2half2_rn(lo, hi);
    return *reinterpret_cast<unsigned*>(&h);
}

__device__ __forceinline__ void fpsplit(float x, float y, unsigned& h, unsigned& l) {
    __half2 hh = __floats2half2_rn(x, y);
    h = *reinterpret_cast<unsigned*>(&hh);
    float fx = __half2float(__low2half(hh));
    float fy = __half2float(__high2half(hh));
    __half2 ll = __floats2half2_rn(x - fx, y - fy);
    l = *reinterpret_cast<unsigned*>(&ll);
}

__device__ __forceinline__ void mma_fp16(float c[4], unsigned a0, unsigned a1,
        unsigned a2, unsigned a3, unsigned b0, unsigned b1) {
    asm("mma.sync.aligned.m16n8k16.row.col.f32.f16.f16.f32 "
        "{%0,%1,%2,%3},{%4,%5,%6,%7},{%8,%9},{%0,%1,%2,%3};"
        : "+f"(c[0]), "+f"(c[1]), "+f"(c[2]), "+f"(c[3])
        : "r"(a0), "r"(a1), "r"(a2), "r"(a3), "r"(b0), "r"(b1));
}

__device__ __forceinline__ float fexp2(float x) {
    float y;
    asm("ex2.approx.f32 %0, %1;" : "=f"(y) : "f"(x));
    return y;
}
#define EXP_C 0.18033688011112042f   // log2(e)/8

// ---------------- kernel 0: transpose W (Wt[n][k] = W[k][n]) -----------------
__global__ __launch_bounds__(256) void wtrans_kernel(const float* __restrict__ Wq,
        const float* __restrict__ Wk, const float* __restrict__ Wv,
        const float* __restrict__ Wo) {
    __shared__ float tile[32][33];
    const float* W = (blockIdx.z == 0) ? Wq : (blockIdx.z == 1) ? Wk
                   : (blockIdx.z == 2) ? Wv : Wo;
    float* T = g_wt + (size_t)blockIdx.z * DD * DD;
    const int x0 = blockIdx.x * 32, y0 = blockIdx.y * 32;
    const int tx = threadIdx.x & 31, ty = threadIdx.x >> 5;   // 32 x 8
    #pragma unroll
    for (int i = 0; i < 32; i += 8)
        tile[ty + i][tx] = W[(size_t)(y0 + ty + i) * DD + x0 + tx];
    __syncthreads();
    #pragma unroll
    for (int i = 0; i < 32; i += 8)
        T[(size_t)(x0 + ty + i) * DD + y0 + tx] = tile[tx][ty + i];
}

// ---------------- kernel 1: QKV projection (fp16 mma, B hi/lo split) ---------
// X[8192,512] @ W -> head layout. Q/K: 2-MMA (A plain fp16, B split). V: 1-MMA.
#define PJ_SMEM (3*128*36*4)

__global__ __launch_bounds__(256, 2) void proj_kernel(const float* __restrict__ q,
        const float* __restrict__ k, const float* __restrict__ v) {
    extern __shared__ unsigned ps[];
    unsigned* Ah  = ps;              // [128][36] fp16x2 (X rows)
    unsigned* Bhi = Ah  + 128*36;    // [128][36] (Wt rows hi)
    unsigned* Blo = Bhi + 128*36;    // [128][36] (Wt rows lo)

    const float* X; float* Y;
    if (blockIdx.z == 0)      { X = q; Y = g_qh; }
    else if (blockIdx.z == 1) { X = k; Y = g_kh; }
    else                      { X = v; Y = g_vh; }
    const float* Wt = g_wt + (size_t)blockIdx.z * DD * DD;
    const bool split = (blockIdx.z != 2);

    const int row0 = blockIdx.y * 128, col0 = blockIdx.x * 128;
    const int tid = threadIdx.x, lane = tid & 31, warp = tid >> 5;
    const int g = lane >> 2, t = lane & 3;
    const int wm = warp & 3, wn = warp >> 2;

    const int fr = tid >> 3;            // 32 rows per sweep
    const int fcb = (tid & 7) << 3;     // 8-elem block
    const int fw = fcb >> 1;            // word offset

    float acc[2][8][4] = {};

    for (int c = 0; c < 8; c++) {
        const int k0 = c * 64;
        __syncthreads();
        #pragma unroll
        for (int sw = 0; sw < 4; sw++) {
            int r = fr + sw * 32;
            {   // A = X rows, plain fp16
                const float* src = X + (size_t)(row0 + r) * DD + k0 + fcb;
                float4 v0 = *(const float4*)src;
                float4 v1 = *(const float4*)(src + 4);
                *(uint4*)(Ah + r*36 + fw) = make_uint4(
                    fppack(v0.x, v0.y), fppack(v0.z, v0.w),
                    fppack(v1.x, v1.y), fppack(v1.z, v1.w));
            }
            {   // B = Wt rows (= output cols), split hi/lo
                const float* src = Wt + (size_t)(col0 + r) * DD + k0 + fcb;
                float4 v0 = *(const float4*)src;
                float4 v1 = *(const float4*)(src + 4);
                unsigned h0, h1, h2, h3, l0, l1, l2, l3;
                fpsplit(v0.x, v0.y, h0, l0); fpsplit(v0.z, v0.w, h1, l1);
                fpsplit(v1.x, v1.y, h2, l2); fpsplit(v1.z, v1.w, h3, l3);
                *(uint4*)(Bhi + r*36 + fw) = make_uint4(h0, h1, h2, h3);
                if (split) *(uint4*)(Blo + r*36 + fw) = make_uint4(l0, l1, l2, l3);
            }
        }
        __syncthreads();
        #pragma unroll
        for (int s = 0; s < 4; s++) {
            const int kw = s * 8;
            unsigned a[2][4];
            #pragma unroll
            for (int mt = 0; mt < 2; mt++) {
                int r = wm * 32 + mt * 16 + g;
                a[mt][0] = Ah[r*36 + kw + t];       a[mt][1] = Ah[(r+8)*36 + kw + t];
                a[mt][2] = Ah[r*36 + kw + t + 4];   a[mt][3] = Ah[(r+8)*36 + kw + t + 4];
            }
            #pragma unroll
            for (int nt = 0; nt < 8; nt++) {
                int cc = wn * 64 + nt * 8 + g;
                unsigned bh0 = Bhi[cc*36 + kw + t], bh1 = Bhi[cc*36 + kw + t + 4];
                #pragma unroll
                for (int mt = 0; mt < 2; mt++)
                    mma_fp16(acc[mt][nt], a[mt][0], a[mt][1], a[mt][2], a[mt][3], bh0, bh1);
                if (split) {
                    unsigned bl0 = Blo[cc*36 + kw + t], bl1 = Blo[cc*36 + kw + t + 4];
                    #pragma unroll
                    for (int mt = 0; mt < 2; mt++)
                        mma_fp16(acc[mt][nt], a[mt][0], a[mt][1], a[mt][2], a[mt][3], bl0, bl1);
                }
            }
        }
    }
    const int bidx = row0 >> 11;
    #pragma unroll
    for (int mt = 0; mt < 2; mt++) {
        int r0 = row0 + wm * 32 + mt * 16 + g;
        int s0 = r0 & 2047;
        #pragma unroll
        for (int nt = 0; nt < 8; nt++) {
            int col = col0 + wn * 64 + nt * 8 + 2 * t;
            int h = col >> 6, dk = col & 63;
            float* dst0 = Y + (((size_t)(bidx * HH + h) * SS + s0) << 6) + dk;
            float* dst1 = Y + (((size_t)(bidx * HH + h) * SS + s0 + 8) << 6) + dk;
            *(float2*)dst0 = make_float2(acc[mt][nt][0], acc[mt][nt][1]);
            *(float2*)dst1 = make_float2(acc[mt][nt][2], acc[mt][nt][3]);
        }
    }
}

// ---------------- kernel 2: fused attention (all fp16 mma) -------------------
// Pass 1: fp16 QK -> rowsums. Pass 2: identical fp16 QK -> normalized attn
// write + fp16 P@V. Q tile loaded once (fp16, 11-bit = tf32-class accuracy).
#define ATTN_WORDS (4608 + 2304 + 2304 + 4608 + 448)
#define ATTN_SMEM (ATTN_WORDS*4)

__global__ __launch_bounds__(256, 2) void attn_kernel(const int* __restrict__ mask,
                                                      float* __restrict__ attn) {
    extern __shared__ unsigned usm[];
    unsigned* Qh  = usm;                  // [128][36] fp16x2
    unsigned* Kh  = Qh + 4608;            // [64][36]
    unsigned* Vb  = Kh + 2304;            // [64 d][36 j'] transposed
    unsigned* Pb  = Vb + 2304;            // [128][36]
    float* rowsum = (float*)(Pb + 4608);  // 128
    float* invs   = rowsum + 128;         // 128
    int*   mrow   = (int*)(invs + 128);   // 128
    int*   mcol   = mrow + 128;           // 64

    const int bh = blockIdx.y, b = bh >> 3;
    const int row0 = blockIdx.x * 128;
    const int tid = threadIdx.x, lane = tid & 31, warp = tid >> 5;
    const int g = lane >> 2, t = lane & 3;
    const int wm = warp & 3, wn = warp >> 2;

    const float* qbase = g_qh + (size_t)bh * SS * 64;
    const float* kbase = g_kh + (size_t)bh * SS * 64;
    const float* vbase = g_vh + (size_t)bh * SS * 64;

    const int fr = tid >> 3;
    const int fcb = (tid & 7) << 3;
    const int fw = fcb >> 1;

    // ---- load Q tile fp16 (persists across both passes) ----
    #pragma unroll
    for (int sw = 0; sw < 4; sw++) {
        int r = fr + sw * 32;
        const float* src = qbase + ((size_t)(row0 + r) << 6) + fcb;
        float4 v0 = *(const float4*)src;
        float4 v1 = *(const float4*)(src + 4);
        *(uint4*)(Qh + r*36 + fw) = make_uint4(
            fppack(v0.x, v0.y), fppack(v0.z, v0.w),
            fppack(v1.x, v1.y), fppack(v1.z, v1.w));
    }
    if (tid < 128) { mrow[tid] = mask[b * SS + row0 + tid]; rowsum[tid] = 0.f; }

    float rp0[2] = {0.f, 0.f};
    float rp1[2] = {0.f, 0.f};

    // ---------------- PASS 1: rowsums --------------------------------------
    #pragma unroll 1
    for (int j0 = 0; j0 < SS; j0 += 64) {
        __syncthreads();
        #pragma unroll
        for (int sw = 0; sw < 2; sw++) {
            int r = fr + sw * 32;
            const float* src = kbase + ((size_t)(j0 + r) << 6) + fcb;
            float4 v0 = *(const float4*)src;
            float4 v1 = *(const float4*)(src + 4);
            *(uint4*)(Kh + r*36 + fw) = make_uint4(
                fppack(v0.x, v0.y), fppack(v0.z, v0.w),
                fppack(v1.x, v1.y), fppack(v1.z, v1.w));
        }
        if (tid < 64) mcol[tid] = mask[b * SS + j0 + tid];
        __syncthreads();

        float acc[2][4][4] = {};
        #pragma unroll
        for (int s = 0; s < 4; s++) {
            int kw = s * 8;
            unsigned a[2][4];
            #pragma unroll
            for (int mt = 0; mt < 2; mt++) {
                int r = wm * 32 + mt * 16 + g;
                a[mt][0] = Qh[r*36 + kw + t];        a[mt][1] = Qh[(r+8)*36 + kw + t];
                a[mt][2] = Qh[r*36 + kw + t + 4];    a[mt][3] = Qh[(r+8)*36 + kw + t + 4];
            }
            #pragma unroll
            for (int nt = 0; nt < 4; nt++) {
                int c = wn * 32 + nt * 8 + g;
                unsigned b0 = Kh[c*36 + kw + t], b1 = Kh[c*36 + kw + t + 4];
                #pragma unroll
                for (int mt = 0; mt < 2; mt++)
                    mma_fp16(acc[mt][nt], a[mt][0], a[mt][1], a[mt][2], a[mt][3], b0, b1);
            }
        }
        #pragma unroll
        for (int mt = 0; mt < 2; mt++) {
            int lr0 = wm * 32 + mt * 16 + g, lr1 = lr0 + 8;
            int m0 = mrow[lr0], m1 = mrow[lr1];
            int gr0 = row0 + lr0, gr1 = row0 + lr1;
            #pragma unroll
            for (int nt = 0; nt < 4; nt++) {
                int lc = wn * 32 + nt * 8 + 2 * t;
                int gc = j0 + lc;
                int mc0 = mcol[lc], mc1 = mcol[lc + 1];
                float p00 = ((m0 && mc0) || (gr0 == gc))     ? fexp2(acc[mt][nt][0] * EXP_C) : 1.0f;
                float p01 = ((m0 && mc1) || (gr0 == gc + 1)) ? fexp2(acc[mt][nt][1] * EXP_C) : 1.0f;
                float p10 = ((m1 && mc0) || (gr1 == gc))     ? fexp2(acc[mt][nt][2] * EXP_C) : 1.0f;
                float p11 = ((m1 && mc1) || (gr1 == gc + 1)) ? fexp2(acc[mt][nt][3] * EXP_C) : 1.0f;
                rp0[mt] += p00 + p01;
                rp1[mt] += p10 + p11;
            }
        }
    }
    #pragma unroll
    for (int mt = 0; mt < 2; mt++) {
        float s0 = rp0[mt], s1 = rp1[mt];
        s0 += __shfl_xor_sync(0xffffffffu, s0, 1); s0 += __shfl_xor_sync(0xffffffffu, s0, 2);
        s1 += __shfl_xor_sync(0xffffffffu, s1, 1); s1 += __shfl_xor_sync(0xffffffffu, s1, 2);
        if (t == 0) {
            atomicAdd(&rowsum[wm * 32 + mt * 16 + g], s0);
            atomicAdd(&rowsum[wm * 32 + mt * 16 + g + 8], s1);
        }
    }
    __syncthreads();
    if (tid < 128) invs[tid] = 1.0f / rowsum[tid];

    float oacc[2][4][4] = {};
    float* arow = attn + ((size_t)bh * SS + row0) * SS;

    const int vjp = tid & 31;           // j' = j/2
    const int vd0 = (tid >> 5) << 3;    // d block of 8

    // ---------------- PASS 2: fp16 QK -> attn write + fp16 P@V --------------
    #pragma unroll 1
    for (int j0 = 0; j0 < SS; j0 += 64) {
        __syncthreads();
        #pragma unroll
        for (int sw = 0; sw < 2; sw++) {
            int r = fr + sw * 32;
            const float* src = kbase + ((size_t)(j0 + r) << 6) + fcb;
            float4 v0 = *(const float4*)src;
            float4 v1 = *(const float4*)(src + 4);
            *(uint4*)(Kh + r*36 + fw) = make_uint4(
                fppack(v0.x, v0.y), fppack(v0.z, v0.w),
                fppack(v1.x, v1.y), fppack(v1.z, v1.w));
        }
        {   // V tile transposed fp16x2: Vb[d][j'] = (v[2j'][d], v[2j'+1][d])
            const float* v0p = vbase + ((size_t)(j0 + 2 * vjp) << 6) + vd0;
            const float* v1p = v0p + 64;
            float4 a0 = *(const float4*)v0p;
            float4 a1 = *(const float4*)(v0p + 4);
            float4 b0 = *(const float4*)v1p;
            float4 b1 = *(const float4*)(v1p + 4);
            float e0[8] = {a0.x, a0.y, a0.z, a0.w, a1.x, a1.y, a1.z, a1.w};
            float e1[8] = {b0.x, b0.y, b0.z, b0.w, b1.x, b1.y, b1.z, b1.w};
            #pragma unroll
            for (int i = 0; i < 8; i++)
                Vb[(vd0 + i) * 36 + vjp] = fppack(e0[i], e1[i]);
        }
        if (tid < 64) mcol[tid] = mask[b * SS + j0 + tid];
        __syncthreads();

        float acc[2][4][4] = {};
        #pragma unroll
        for (int s = 0; s < 4; s++) {
            int kw = s * 8;
            unsigned a[2][4];
            #pragma unroll
            for (int mt = 0; mt < 2; mt++) {
                int r = wm * 32 + mt * 16 + g;
                a[mt][0] = Qh[r*36 + kw + t];        a[mt][1] = Qh[(r+8)*36 + kw + t];
                a[mt][2] = Qh[r*36 + kw + t + 4];    a[mt][3] = Qh[(r+8)*36 + kw + t + 4];
            }
            #pragma unroll
            for (int nt = 0; nt < 4; nt++) {
                int c = wn * 32 + nt * 8 + g;
                unsigned b0 = Kh[c*36 + kw + t], b1 = Kh[c*36 + kw + t + 4];
                #pragma unroll
                for (int mt = 0; mt < 2; mt++)
                    mma_fp16(acc[mt][nt], a[mt][0], a[mt][1], a[mt][2], a[mt][3], b0, b1);
            }
        }
        #pragma unroll
        for (int mt = 0; mt < 2; mt++) {
            int lr0 = wm * 32 + mt * 16 + g, lr1 = lr0 + 8;
            int m0 = mrow[lr0], m1 = mrow[lr1];
            int gr0 = row0 + lr0, gr1 = row0 + lr1;
            float iv0 = invs[lr0], iv1 = invs[lr1];
            #pragma unroll
            for (int nt = 0; nt < 4; nt++) {
                int lc = wn * 32 + nt * 8 + 2 * t;
                int gc = j0 + lc;
                int mc0 = mcol[lc], mc1 = mcol[lc + 1];
                float p00 = ((m0 && mc0) || (gr0 == gc))     ? fexp2(acc[mt][nt][0] * EXP_C) : 1.0f;
                float p01 = ((m0 && mc1) || (gr0 == gc + 1)) ? fexp2(acc[mt][nt][1] * EXP_C) : 1.0f;
                float p10 = ((m1 && mc0) || (gr1 == gc))     ? fexp2(acc[mt][nt][2] * EXP_C) : 1.0f;
                float p11 = ((m1 && mc1) || (gr1 == gc + 1)) ? fexp2(acc[mt][nt][3] * EXP_C) : 1.0f;
                p00 *= iv0; p01 *= iv0; p10 *= iv1; p11 *= iv1;
                *(float2*)(arow + (size_t)lr0 * SS + gc) = make_float2(p00, p01);
                *(float2*)(arow + (size_t)lr1 * SS + gc) = make_float2(p10, p11);
                Pb[lr0 * 36 + (lc >> 1)] = fppack(p00, p01);
                Pb[lr1 * 36 + (lc >> 1)] = fppack(p10, p11);
            }
        }
        __syncthreads();
        #pragma unroll
        for (int s = 0; s < 4; s++) {
            int kw = s * 8;
            unsigned a[2][4];
            #pragma unroll
            for (int mt = 0; mt < 2; mt++) {
                int r = wm * 32 + mt * 16 + g;
                a[mt][0] = Pb[r * 36 + kw + t];        a[mt][1] = Pb[(r + 8) * 36 + kw + t];
                a[mt][2] = Pb[r * 36 + kw + t + 4];    a[mt][3] = Pb[(r + 8) * 36 + kw + t + 4];
            }
            #pragma unroll
            for (int nt = 0; nt < 4; nt++) {
                int c = wn * 32 + nt * 8 + g;
                unsigned b0 = Vb[c * 36 + kw + t], b1 = Vb[c * 36 + kw + t + 4];
                #pragma unroll
                for (int mt = 0; mt < 2; mt++)
                    mma_fp16(oacc[mt][nt], a[mt][0], a[mt][1], a[mt][2], a[mt][3], b0, b1);
            }
        }
    }
    float* obase = g_oh + ((size_t)bh * SS + row0) * 64;
    #pragma unroll
    for (int mt = 0; mt < 2; mt++) {
        int lr0 = wm * 32 + mt * 16 + g, lr1 = lr0 + 8;
        #pragma unroll
        for (int nt = 0; nt < 4; nt++) {
            int lc = wn * 32 + nt * 8 + 2 * t;
            *(float2*)(obase + (size_t)lr0 * 64 + lc) = make_float2(oacc[mt][nt][0], oacc[mt][nt][1]);
            *(float2*)(obase + (size_t)lr1 * 64 + lc) = make_float2(oacc[mt][nt][2], oacc[mt][nt][3]);
        }
    }
}

// ---------------- kernel 3: O @ Wo + residual (fp16, split Wo) ---------------
__global__ __launch_bounds__(256, 2) void out_proj_kernel(const float* __restrict__ q) {
    extern __shared__ unsigned ps[];
    unsigned* Ah  = ps;              // [128][36] fp16x2 (O rows, head-gathered)
    unsigned* Bhi = Ah  + 128*36;    // [128][36] (WoT rows hi)
    unsigned* Blo = Bhi + 128*36;    // [128][36] (WoT rows lo)

    const float* WoT = g_wt + 3 * (size_t)DD * DD;

    const int row0 = blockIdx.y * 128, col0 = blockIdx.x * 128;
    const int tid = threadIdx.x, lane = tid & 31, warp = tid >> 5;
    const int g = lane >> 2, t = lane & 3;
    const int wm = warp & 3, wn = warp >> 2;

    const int bidx = row0 >> 11, srow0 = row0 & 2047;

    const int fr = tid >> 3;
    const int fcb = (tid & 7) << 3;
    const int fw = fcb >> 1;

    float acc[2][8][4] = {};

    for (int c = 0; c < 8; c++) {
        const int k0 = c * 64;      // head index = c, dv = fcb (64-aligned chunks)
        __syncthreads();
        #pragma unroll
        for (int sw = 0; sw < 4; sw++) {
            int r = fr + sw * 32;
            {   // A = O rows from head layout
                const float* src = g_oh +
                    (((size_t)(bidx * HH + c) * SS + srow0 + r) << 6) + fcb;
                float4 v0 = *(const float4*)src;
                float4 v1 = *(const float4*)(src + 4);
                *(uint4*)(Ah + r*36 + fw) = make_uint4(
                    fppack(v0.x, v0.y), fppack(v0.z, v0.w),
                    fppack(v1.x, v1.y), fppack(v1.z, v1.w));
            }
            {   // B = WoT rows (= output cols), split hi/lo
                const float* src = WoT + (size_t)(col0 + r) * DD + k0 + fcb;
                float4 v0 = *(const float4*)src;
                float4 v1 = *(const float4*)(src + 4);
                unsigned h0, h1, h2, h3, l0, l1, l2, l3;
                fpsplit(v0.x, v0.y, h0, l0); fpsplit(v0.z, v0.w, h1, l1);
                fpsplit(v1.x, v1.y, h2, l2); fpsplit(v1.z, v1.w, h3, l3);
                *(uint4*)(Bhi + r*36 + fw) = make_uint4(h0, h1, h2, h3);
                *(uint4*)(Blo + r*36 + fw) = make_uint4(l0, l1, l2, l3);
            }
        }
        __syncthreads();
        #pragma unroll
        for (int s = 0; s < 4; s++) {
            const int kw = s * 8;
            unsigned a[2][4];
            #pragma unroll
            for (int mt = 0; mt < 2; mt++) {
                int r = wm * 32 + mt * 16 + g;
                a[mt][0] = Ah[r*36 + kw + t];       a[mt][1] = Ah[(r+8)*36 + kw + t];
                a[mt][2] = Ah[r*36 + kw + t + 4];   a[mt][3] = Ah[(r+8)*36 + kw + t + 4];
            }
            #pragma unroll
            for (int nt = 0; nt < 8; nt++) {
                int cc = wn * 64 + nt * 8 + g;
                unsigned bh0 = Bhi[cc*36 + kw + t], bh1 = Bhi[cc*36 + kw + t + 4];
                unsigned bl0 = Blo[cc*36 + kw + t], bl1 = Blo[cc*36 + kw + t + 4];
                #pragma unroll
                for (int mt = 0; mt < 2; mt++) {
                    mma_fp16(acc[mt][nt], a[mt][0], a[mt][1], a[mt][2], a[mt][3], bh0, bh1);
                    mma_fp16(acc[mt][nt], a[mt][0], a[mt][1], a[mt][2], a[mt][3], bl0, bl1);
                }
            }
        }
    }
    #pragma unroll
    for (int mt = 0; mt < 2; mt++) {
        int r0 = row0 + wm * 32 + mt * 16 + g;
        #pragma unroll
        for (int nt = 0; nt < 8; nt++) {
            int col = col0 + wn * 64 + nt * 8 + 2 * t;
            size_t off0 = (size_t)r0 * DD + col;
            size_t off1 = (size_t)(r0 + 8) * DD + col;
            float2 q0 = *(const float2*)(q + off0);
            float2 q1 = *(const float2*)(q + off1);
            *(float2*)(g_y + off0) = make_float2(acc[mt][nt][0] + q0.x, acc[mt][nt][1] + q0.y);
            *(float2*)(g_y + off1) = make_float2(acc[mt][nt][2] + q1.x, acc[mt][nt][3] + q1.y);
        }
    }
}

// ---------------- kernel 4: LayerNorm ---------------------------------------
__global__ void ln_kernel(const float* __restrict__ gamma, const float* __restrict__ beta,
                          float* __restrict__ out) {
    const int row = blockIdx.x;
    const float* x = g_y + (size_t)row * DD;
    const int t = threadIdx.x;

    float v0 = x[t], v1 = x[t + 256];
    float s  = v0 + v1;
    float sq = v0 * v0 + v1 * v1;

    __shared__ float ssum[8], ssq[8];
    #pragma unroll
    for (int off = 16; off > 0; off >>= 1) {
        s  += __shfl_down_sync(0xffffffffu, s,  off);
        sq += __shfl_down_sync(0xffffffffu, sq, off);
    }
    if ((t & 31) == 0) { ssum[t >> 5] = s; ssq[t >> 5] = sq; }
    __syncthreads();
    if (t < 32) {
        float a = (t < 8) ? ssum[t] : 0.f;
        float b = (t < 8) ? ssq[t]  : 0.f;
        #pragma unroll
        for (int off = 4; off > 0; off >>= 1) {
            a += __shfl_down_sync(0xffffffffu, a, off);
            b += __shfl_down_sync(0xffffffffu, b, off);
        }
        if (t == 0) { ssum[0] = a; ssq[0] = b; }
    }
    __syncthreads();
    float mean = ssum[0] * (1.0f / DD);
    float var  = ssq[0]  * (1.0f / DD) - mean * mean;
    float rs   = rsqrtf(var + 1e-6f);

    out[(size_t)row * DD + t]       = (v0 - mean) * rs * gamma[t]       + beta[t];
    out[(size_t)row * DD + t + 256] = (v1 - mean) * rs * gamma[t + 256] + beta[t + 256];
}

// ---------------- launch -----------------------------------------------------
extern "C" void kernel_launch(void* const* d_in, const int* in_sizes, int n_in,
                              void* d_out, int out_size) {
    const float* q     = (const float*)d_in[0];
    const float* k     = (const float*)d_in[1];
    const float* v     = (const float*)d_in[2];
    const int*   mask  = (const int*)  d_in[3];
    const float* Wq    = (const float*)d_in[4];
    const float* Wk    = (const float*)d_in[5];
    const float* Wv    = (const float*)d_in[6];
    const float* Wo    = (const float*)d_in[7];
    const float* gamma = (const float*)d_in[8];
    const float* beta  = (const float*)d_in[9];

    float* out  = (float*)d_out;                  // [B,S,D]
    float* attn = out + (size_t)BB * SS * DD;     // [B,H,S,S]

    cudaFuncSetAttribute(attn_kernel, cudaFuncAttributeMaxDynamicSharedMemorySize, ATTN_SMEM);
    cudaFuncSetAttribute(proj_kernel, cudaFuncAttributeMaxDynamicSharedMemorySize, PJ_SMEM);
    cudaFuncSetAttribute(out_proj_kernel, cudaFuncAttributeMaxDynamicSharedMemorySize, PJ_SMEM);

    wtrans_kernel<<<dim3(16, 16, 4), 256>>>(Wq, Wk, Wv, Wo);
    proj_kernel<<<dim3(DD/128, BSN/128, 3), 256, PJ_SMEM>>>(q, k, v);
    attn_kernel<<<dim3(SS/128, BH), 256, ATTN_SMEM>>>(mask, attn);
    out_proj_kernel<<<dim3(DD/128, BSN/128), 256, PJ_SMEM>>>(q);
    ln_kernel<<<BSN, 256>>>(gamma, beta, out);
}

// round 10
// speedup vs baseline: 2.9885x; 1.1964x over previous
#include <cuda_runtime.h>
#include <cuda_fp16.h>
#include <math.h>
#include <cstdint>

#define BB 4
#define SS 2048
#define DD 512
#define HH 8
#define BH (BB*HH)
#define BSN (BB*SS)

// ---------------- scratch (device globals; fp16x2 words) --------------------
__device__ unsigned g_qhw[(size_t)BH*SS*32];   // [bh, s, 32w]
__device__ unsigned g_khw[(size_t)BH*SS*32];
__device__ unsigned g_vhw[(size_t)BH*SS*32];
__device__ unsigned g_ohw[(size_t)BH*SS*32];
__device__ unsigned g_wtw[4*(size_t)DD*(DD/2)]; // W^T fp16x2, [n][k/2]
__device__ float    g_y[(size_t)BSN*DD];

// ---------------- helpers -----------------------------------------------------
__device__ __forceinline__ unsigned fppack(float lo, float hi) {
    __half2 h = __floats2half2_rn(lo, hi);
    return *reinterpret_cast<unsigned*>(&h);
}

__device__ __forceinline__ void mma_fp16(float c[4], unsigned a0, unsigned a1,
        unsigned a2, unsigned a3, unsigned b0, unsigned b1) {
    asm("mma.sync.aligned.m16n8k16.row.col.f32.f16.f16.f32 "
        "{%0,%1,%2,%3},{%4,%5,%6,%7},{%8,%9},{%0,%1,%2,%3};"
        : "+f"(c[0]), "+f"(c[1]), "+f"(c[2]), "+f"(c[3])
        : "r"(a0), "r"(a1), "r"(a2), "r"(a3), "r"(b0), "r"(b1));
}

__device__ __forceinline__ float fexp2(float x) {
    float y;
    asm("ex2.approx.f32 %0, %1;" : "=f"(y) : "f"(x));
    return y;
}
#define EXP_C 0.18033688011112042f   // log2(e)/8

// ---------------- kernel 0: transpose W -> fp16 (Wt[n][k] = W[k][n]) --------
__global__ __launch_bounds__(256) void wtrans_kernel(const float* __restrict__ Wq,
        const float* __restrict__ Wk, const float* __restrict__ Wv,
        const float* __restrict__ Wo) {
    __shared__ float tile[32][33];
    const float* W = (blockIdx.z == 0) ? Wq : (blockIdx.z == 1) ? Wk
                   : (blockIdx.z == 2) ? Wv : Wo;
    unsigned* T = g_wtw + (size_t)blockIdx.z * DD * (DD/2);
    const int x0 = blockIdx.x * 32, y0 = blockIdx.y * 32;
    const int tx = threadIdx.x & 31, ty = threadIdx.x >> 5;   // 32 x 8
    #pragma unroll
    for (int i = 0; i < 32; i += 8)
        tile[ty + i][tx] = W[(size_t)(y0 + ty + i) * DD + x0 + tx];
    __syncthreads();
    const int wc0 = threadIdx.x & 7, xx = threadIdx.x >> 3;   // 8 wc x 32 xx
    #pragma unroll
    for (int i = 0; i < 16; i += 8) {
        int wc = wc0 + i;
        T[(size_t)(x0 + xx) * (DD/2) + (y0 >> 1) + wc] =
            fppack(tile[2*wc][xx], tile[2*wc + 1][xx]);
    }
}

// ---------------- kernel 1: QKV projection (plain fp16 mma) ------------------
// X[8192,512](fp32) @ Wt(fp16) -> head layout fp16. 1 MMA per k16.
#define PJ_SMEM (2*128*36*4)

__global__ __launch_bounds__(256, 2) void proj_kernel(const float* __restrict__ q,
        const float* __restrict__ k, const float* __restrict__ v) {
    extern __shared__ unsigned ps[];
    unsigned* Ah = ps;              // [128][36] fp16x2 (X rows)
    unsigned* Bh = Ah + 128*36;     // [128][36] (Wt rows = output cols)

    const float* X; unsigned* Y;
    if (blockIdx.z == 0)      { X = q; Y = g_qhw; }
    else if (blockIdx.z == 1) { X = k; Y = g_khw; }
    else                      { X = v; Y = g_vhw; }
    const unsigned* Wt = g_wtw + (size_t)blockIdx.z * DD * (DD/2);

    const int row0 = blockIdx.y * 128, col0 = blockIdx.x * 128;
    const int tid = threadIdx.x, lane = tid & 31, warp = tid >> 5;
    const int g = lane >> 2, t = lane & 3;
    const int wm = warp & 3, wn = warp >> 2;

    const int fr = tid >> 3;            // 32 rows per sweep
    const int fcb = (tid & 7) << 3;     // 8-elem block
    const int fw = fcb >> 1;            // word offset (0,4,..,28)

    float acc[2][8][4] = {};

    for (int c = 0; c < 8; c++) {
        const int k0 = c * 64, kw0 = c * 32;
        __syncthreads();
        #pragma unroll
        for (int sw = 0; sw < 4; sw++) {
            int r = fr + sw * 32;
            {   // A = X rows (fp32 -> fp16)
                const float* src = X + (size_t)(row0 + r) * DD + k0 + fcb;
                float4 v0 = *(const float4*)src;
                float4 v1 = *(const float4*)(src + 4);
                *(uint4*)(Ah + r*36 + fw) = make_uint4(
                    fppack(v0.x, v0.y), fppack(v0.z, v0.w),
                    fppack(v1.x, v1.y), fppack(v1.z, v1.w));
            }
            // B = Wt rows, already fp16 — pure copy
            *(uint4*)(Bh + r*36 + fw) =
                *(const uint4*)(Wt + (size_t)(col0 + r) * (DD/2) + kw0 + fw);
        }
        __syncthreads();
        #pragma unroll
        for (int s = 0; s < 4; s++) {
            const int kw = s * 8;
            unsigned a[2][4];
            #pragma unroll
            for (int mt = 0; mt < 2; mt++) {
                int r = wm * 32 + mt * 16 + g;
                a[mt][0] = Ah[r*36 + kw + t];       a[mt][1] = Ah[(r+8)*36 + kw + t];
                a[mt][2] = Ah[r*36 + kw + t + 4];   a[mt][3] = Ah[(r+8)*36 + kw + t + 4];
            }
            #pragma unroll
            for (int nt = 0; nt < 8; nt++) {
                int cc = wn * 64 + nt * 8 + g;
                unsigned b0 = Bh[cc*36 + kw + t], b1 = Bh[cc*36 + kw + t + 4];
                #pragma unroll
                for (int mt = 0; mt < 2; mt++)
                    mma_fp16(acc[mt][nt], a[mt][0], a[mt][1], a[mt][2], a[mt][3], b0, b1);
            }
        }
    }
    const int bidx = row0 >> 11;
    #pragma unroll
    for (int mt = 0; mt < 2; mt++) {
        int r0 = row0 + wm * 32 + mt * 16 + g;
        int s0 = r0 & 2047;
        #pragma unroll
        for (int nt = 0; nt < 8; nt++) {
            int col = col0 + wn * 64 + nt * 8 + 2 * t;
            int h = col >> 6, dkw = (col & 63) >> 1;
            Y[(((size_t)(bidx * HH + h) * SS + s0) << 5) + dkw]     = fppack(acc[mt][nt][0], acc[mt][nt][1]);
            Y[(((size_t)(bidx * HH + h) * SS + s0 + 8) << 5) + dkw] = fppack(acc[mt][nt][2], acc[mt][nt][3]);
        }
    }
}

// ---------------- kernel 2: fused attention (fp16 mma, fp16 scratch) ---------
#define ATTN_WORDS (4608 + 2304 + 2304 + 4608 + 448)
#define ATTN_SMEM (ATTN_WORDS*4)

__global__ __launch_bounds__(256, 2) void attn_kernel(const int* __restrict__ mask,
                                                      float* __restrict__ attn) {
    extern __shared__ unsigned usm[];
    unsigned* Qh  = usm;                  // [128][36] fp16x2
    unsigned* Kh  = Qh + 4608;            // [64][36]
    unsigned* Vb  = Kh + 2304;            // [64 d][36 j'] transposed
    unsigned* Pb  = Vb + 2304;            // [128][36]
    float* rowsum = (float*)(Pb + 4608);  // 128
    float* invs   = rowsum + 128;         // 128
    int*   mrow   = (int*)(invs + 128);   // 128
    int*   mcol   = mrow + 128;           // 64

    const int bh = blockIdx.y, b = bh >> 3;
    const int row0 = blockIdx.x * 128;
    const int tid = threadIdx.x, lane = tid & 31, warp = tid >> 5;
    const int g = lane >> 2, t = lane & 3;
    const int wm = warp & 3, wn = warp >> 2;

    const unsigned* qbase = g_qhw + ((size_t)bh * SS << 5);
    const unsigned* kbase = g_khw + ((size_t)bh * SS << 5);
    const unsigned* vbase = g_vhw + ((size_t)bh * SS << 5);

    const int fr = tid >> 3;
    const int fw = (tid & 7) << 2;      // word offset 0..28

    // ---- load Q tile (copy fp16 words; persists across both passes) ----
    #pragma unroll
    for (int sw = 0; sw < 4; sw++) {
        int r = fr + sw * 32;
        *(uint4*)(Qh + r*36 + fw) = *(const uint4*)(qbase + ((size_t)(row0 + r) << 5) + fw);
    }
    if (tid < 128) { mrow[tid] = mask[b * SS + row0 + tid]; rowsum[tid] = 0.f; }

    float rp0[2] = {0.f, 0.f};
    float rp1[2] = {0.f, 0.f};

    // ---------------- PASS 1: rowsums --------------------------------------
    #pragma unroll 1
    for (int j0 = 0; j0 < SS; j0 += 64) {
        __syncthreads();
        #pragma unroll
        for (int sw = 0; sw < 2; sw++) {
            int r = fr + sw * 32;
            *(uint4*)(Kh + r*36 + fw) = *(const uint4*)(kbase + ((size_t)(j0 + r) << 5) + fw);
        }
        if (tid < 64) mcol[tid] = mask[b * SS + j0 + tid];
        __syncthreads();

        float acc[2][4][4] = {};
        #pragma unroll
        for (int s = 0; s < 4; s++) {
            int kw = s * 8;
            unsigned a[2][4];
            #pragma unroll
            for (int mt = 0; mt < 2; mt++) {
                int r = wm * 32 + mt * 16 + g;
                a[mt][0] = Qh[r*36 + kw + t];        a[mt][1] = Qh[(r+8)*36 + kw + t];
                a[mt][2] = Qh[r*36 + kw + t + 4];    a[mt][3] = Qh[(r+8)*36 + kw + t + 4];
            }
            #pragma unroll
            for (int nt = 0; nt < 4; nt++) {
                int c = wn * 32 + nt * 8 + g;
                unsigned b0 = Kh[c*36 + kw + t], b1 = Kh[c*36 + kw + t + 4];
                #pragma unroll
                for (int mt = 0; mt < 2; mt++)
                    mma_fp16(acc[mt][nt], a[mt][0], a[mt][1], a[mt][2], a[mt][3], b0, b1);
            }
        }
        #pragma unroll
        for (int mt = 0; mt < 2; mt++) {
            int lr0 = wm * 32 + mt * 16 + g, lr1 = lr0 + 8;
            int m0 = mrow[lr0], m1 = mrow[lr1];
            int gr0 = row0 + lr0, gr1 = row0 + lr1;
            #pragma unroll
            for (int nt = 0; nt < 4; nt++) {
                int lc = wn * 32 + nt * 8 + 2 * t;
                int gc = j0 + lc;
                int mc0 = mcol[lc], mc1 = mcol[lc + 1];
                float p00 = ((m0 && mc0) || (gr0 == gc))     ? fexp2(acc[mt][nt][0] * EXP_C) : 1.0f;
                float p01 = ((m0 && mc1) || (gr0 == gc + 1)) ? fexp2(acc[mt][nt][1] * EXP_C) : 1.0f;
                float p10 = ((m1 && mc0) || (gr1 == gc))     ? fexp2(acc[mt][nt][2] * EXP_C) : 1.0f;
                float p11 = ((m1 && mc1) || (gr1 == gc + 1)) ? fexp2(acc[mt][nt][3] * EXP_C) : 1.0f;
                rp0[mt] += p00 + p01;
                rp1[mt] += p10 + p11;
            }
        }
    }
    #pragma unroll
    for (int mt = 0; mt < 2; mt++) {
        float s0 = rp0[mt], s1 = rp1[mt];
        s0 += __shfl_xor_sync(0xffffffffu, s0, 1); s0 += __shfl_xor_sync(0xffffffffu, s0, 2);
        s1 += __shfl_xor_sync(0xffffffffu, s1, 1); s1 += __shfl_xor_sync(0xffffffffu, s1, 2);
        if (t == 0) {
            atomicAdd(&rowsum[wm * 32 + mt * 16 + g], s0);
            atomicAdd(&rowsum[wm * 32 + mt * 16 + g + 8], s1);
        }
    }
    __syncthreads();
    if (tid < 128) invs[tid] = 1.0f / rowsum[tid];

    float oacc[2][4][4] = {};
    float* arow = attn + ((size_t)bh * SS + row0) * SS;

    const int vjp = tid & 31;           // j' = j/2
    const int vd0 = (tid >> 5) << 3;    // d block of 8 (4 words)

    // ---------------- PASS 2: fp16 QK -> attn write + fp16 P@V --------------
    #pragma unroll 1
    for (int j0 = 0; j0 < SS; j0 += 64) {
        __syncthreads();
        #pragma unroll
        for (int sw = 0; sw < 2; sw++) {
            int r = fr + sw * 32;
            *(uint4*)(Kh + r*36 + fw) = *(const uint4*)(kbase + ((size_t)(j0 + r) << 5) + fw);
        }
        {   // V tile transposed via PRMT: Vb[d][j'] = (v[2j'][d], v[2j'+1][d])
            uint4 ea = *(const uint4*)(vbase + ((size_t)(j0 + 2*vjp)     << 5) + (vd0 >> 1));
            uint4 eb = *(const uint4*)(vbase + ((size_t)(j0 + 2*vjp + 1) << 5) + (vd0 >> 1));
            unsigned wa[4] = {ea.x, ea.y, ea.z, ea.w};
            unsigned wb[4] = {eb.x, eb.y, eb.z, eb.w};
            #pragma unroll
            for (int i = 0; i < 4; i++) {
                Vb[(vd0 + 2*i)     * 36 + vjp] = __byte_perm(wa[i], wb[i], 0x5410);
                Vb[(vd0 + 2*i + 1) * 36 + vjp] = __byte_perm(wa[i], wb[i], 0x7632);
            }
        }
        if (tid < 64) mcol[tid] = mask[b * SS + j0 + tid];
        __syncthreads();

        float acc[2][4][4] = {};
        #pragma unroll
        for (int s = 0; s < 4; s++) {
            int kw = s * 8;
            unsigned a[2][4];
            #pragma unroll
            for (int mt = 0; mt < 2; mt++) {
                int r = wm * 32 + mt * 16 + g;
                a[mt][0] = Qh[r*36 + kw + t];        a[mt][1] = Qh[(r+8)*36 + kw + t];
                a[mt][2] = Qh[r*36 + kw + t + 4];    a[mt][3] = Qh[(r+8)*36 + kw + t + 4];
            }
            #pragma unroll
            for (int nt = 0; nt < 4; nt++) {
                int c = wn * 32 + nt * 8 + g;
                unsigned b0 = Kh[c*36 + kw + t], b1 = Kh[c*36 + kw + t + 4];
                #pragma unroll
                for (int mt = 0; mt < 2; mt++)
                    mma_fp16(acc[mt][nt], a[mt][0], a[mt][1], a[mt][2], a[mt][3], b0, b1);
            }
        }
        #pragma unroll
        for (int mt = 0; mt < 2; mt++) {
            int lr0 = wm * 32 + mt * 16 + g, lr1 = lr0 + 8;
            int m0 = mrow[lr0], m1 = mrow[lr1];
            int gr0 = row0 + lr0, gr1 = row0 + lr1;
            float iv0 = invs[lr0], iv1 = invs[lr1];
            #pragma unroll
            for (int nt = 0; nt < 4; nt++) {
                int lc = wn * 32 + nt * 8 + 2 * t;
                int gc = j0 + lc;
                int mc0 = mcol[lc], mc1 = mcol[lc + 1];
                float p00 = ((m0 && mc0) || (gr0 == gc))     ? fexp2(acc[mt][nt][0] * EXP_C) : 1.0f;
                float p01 = ((m0 && mc1) || (gr0 == gc + 1)) ? fexp2(acc[mt][nt][1] * EXP_C) : 1.0f;
                float p10 = ((m1 && mc0) || (gr1 == gc))     ? fexp2(acc[mt][nt][2] * EXP_C) : 1.0f;
                float p11 = ((m1 && mc1) || (gr1 == gc + 1)) ? fexp2(acc[mt][nt][3] * EXP_C) : 1.0f;
                p00 *= iv0; p01 *= iv0; p10 *= iv1; p11 *= iv1;
                *(float2*)(arow + (size_t)lr0 * SS + gc) = make_float2(p00, p01);
                *(float2*)(arow + (size_t)lr1 * SS + gc) = make_float2(p10, p11);
                Pb[lr0 * 36 + (lc >> 1)] = fppack(p00, p01);
                Pb[lr1 * 36 + (lc >> 1)] = fppack(p10, p11);
            }
        }
        __syncthreads();
        #pragma unroll
        for (int s = 0; s < 4; s++) {
            int kw = s * 8;
            unsigned a[2][4];
            #pragma unroll
            for (int mt = 0; mt < 2; mt++) {
                int r = wm * 32 + mt * 16 + g;
                a[mt][0] = Pb[r * 36 + kw + t];        a[mt][1] = Pb[(r + 8) * 36 + kw + t];
                a[mt][2] = Pb[r * 36 + kw + t + 4];    a[mt][3] = Pb[(r + 8) * 36 + kw + t + 4];
            }
            #pragma unroll
            for (int nt = 0; nt < 4; nt++) {
                int c = wn * 32 + nt * 8 + g;
                unsigned b0 = Vb[c * 36 + kw + t], b1 = Vb[c * 36 + kw + t + 4];
                #pragma unroll
                for (int mt = 0; mt < 2; mt++)
                    mma_fp16(oacc[mt][nt], a[mt][0], a[mt][1], a[mt][2], a[mt][3], b0, b1);
            }
        }
    }
    unsigned* obase = g_ohw + (((size_t)bh * SS + row0) << 5);
    #pragma unroll
    for (int mt = 0; mt < 2; mt++) {
        int lr0 = wm * 32 + mt * 16 + g, lr1 = lr0 + 8;
        #pragma unroll
        for (int nt = 0; nt < 4; nt++) {
            int lc = wn * 32 + nt * 8 + 2 * t;
            obase[((size_t)lr0 << 5) + (lc >> 1)] = fppack(oacc[mt][nt][0], oacc[mt][nt][1]);
            obase[((size_t)lr1 << 5) + (lc >> 1)] = fppack(oacc[mt][nt][2], oacc[mt][nt][3]);
        }
    }
}

// ---------------- kernel 3: O @ Wo + residual (plain fp16 mma) ---------------
__global__ __launch_bounds__(256, 2) void out_proj_kernel(const float* __restrict__ q) {
    extern __shared__ unsigned ps[];
    unsigned* Ah = ps;              // [128][36] (O rows, head-gathered)
    unsigned* Bh = Ah + 128*36;     // [128][36] (WoT rows)

    const unsigned* WoT = g_wtw + 3 * (size_t)DD * (DD/2);

    const int row0 = blockIdx.y * 128, col0 = blockIdx.x * 128;
    const int tid = threadIdx.x, lane = tid & 31, warp = tid >> 5;
    const int g = lane >> 2, t = lane & 3;
    const int wm = warp & 3, wn = warp >> 2;

    const int bidx = row0 >> 11, srow0 = row0 & 2047;

    const int fr = tid >> 3;
    const int fw = (tid & 7) << 2;

    float acc[2][8][4] = {};

    for (int c = 0; c < 8; c++) {
        const int kw0 = c * 32;
        __syncthreads();
        #pragma unroll
        for (int sw = 0; sw < 4; sw++) {
            int r = fr + sw * 32;
            // A = O rows from head layout (head index = c), fp16 copy
            *(uint4*)(Ah + r*36 + fw) = *(const uint4*)(g_ohw +
                (((size_t)(bidx * HH + c) * SS + srow0 + r) << 5) + fw);
            // B = WoT rows, fp16 copy
            *(uint4*)(Bh + r*36 + fw) =
                *(const uint4*)(WoT + (size_t)(col0 + r) * (DD/2) + kw0 + fw);
        }
        __syncthreads();
        #pragma unroll
        for (int s = 0; s < 4; s++) {
            const int kw = s * 8;
            unsigned a[2][4];
            #pragma unroll
            for (int mt = 0; mt < 2; mt++) {
                int r = wm * 32 + mt * 16 + g;
                a[mt][0] = Ah[r*36 + kw + t];       a[mt][1] = Ah[(r+8)*36 + kw + t];
                a[mt][2] = Ah[r*36 + kw + t + 4];   a[mt][3] = Ah[(r+8)*36 + kw + t + 4];
            }
            #pragma unroll
            for (int nt = 0; nt < 8; nt++) {
                int cc = wn * 64 + nt * 8 + g;
                unsigned b0 = Bh[cc*36 + kw + t], b1 = Bh[cc*36 + kw + t + 4];
                #pragma unroll
                for (int mt = 0; mt < 2; mt++)
                    mma_fp16(acc[mt][nt], a[mt][0], a[mt][1], a[mt][2], a[mt][3], b0, b1);
            }
        }
    }
    #pragma unroll
    for (int mt = 0; mt < 2; mt++) {
        int r0 = row0 + wm * 32 + mt * 16 + g;
        #pragma unroll
        for (int nt = 0; nt < 8; nt++) {
            int col = col0 + wn * 64 + nt * 8 + 2 * t;
            size_t off0 = (size_t)r0 * DD + col;
            size_t off1 = (size_t)(r0 + 8) * DD + col;
            float2 q0 = *(const float2*)(q + off0);
            float2 q1 = *(const float2*)(q + off1);
            *(float2*)(g_y + off0) = make_float2(acc[mt][nt][0] + q0.x, acc[mt][nt][1] + q0.y);
            *(float2*)(g_y + off1) = make_float2(acc[mt][nt][2] + q1.x, acc[mt][nt][3] + q1.y);
        }
    }
}

// ---------------- kernel 4: LayerNorm ---------------------------------------
__global__ void ln_kernel(const float* __restrict__ gamma, const float* __restrict__ beta,
                          float* __restrict__ out) {
    const int row = blockIdx.x;
    const float* x = g_y + (size_t)row * DD;
    const int t = threadIdx.x;

    float v0 = x[t], v1 = x[t + 256];
    float s  = v0 + v1;
    float sq = v0 * v0 + v1 * v1;

    __shared__ float ssum[8], ssq[8];
    #pragma unroll
    for (int off = 16; off > 0; off >>= 1) {
        s  += __shfl_down_sync(0xffffffffu, s,  off);
        sq += __shfl_down_sync(0xffffffffu, sq, off);
    }
    if ((t & 31) == 0) { ssum[t >> 5] = s; ssq[t >> 5] = sq; }
    __syncthreads();
    if (t < 32) {
        float a = (t < 8) ? ssum[t] : 0.f;
        float b = (t < 8) ? ssq[t]  : 0.f;
        #pragma unroll
        for (int off = 4; off > 0; off >>= 1) {
            a += __shfl_down_sync(0xffffffffu, a, off);
            b += __shfl_down_sync(0xffffffffu, b, off);
        }
        if (t == 0) { ssum[0] = a; ssq[0] = b; }
    }
    __syncthreads();
    float mean = ssum[0] * (1.0f / DD);
    float var  = ssq[0]  * (1.0f / DD) - mean * mean;
    float rs   = rsqrtf(var + 1e-6f);

    out[(size_t)row * DD + t]       = (v0 - mean) * rs * gamma[t]       + beta[t];
    out[(size_t)row * DD + t + 256] = (v1 - mean) * rs * gamma[t + 256] + beta[t + 256];
}

// ---------------- launch -----------------------------------------------------
extern "C" void kernel_launch(void* const* d_in, const int* in_sizes, int n_in,
                              void* d_out, int out_size) {
    const float* q     = (const float*)d_in[0];
    const float* k     = (const float*)d_in[1];
    const float* v     = (const float*)d_in[2];
    const int*   mask  = (const int*)  d_in[3];
    const float* Wq    = (const float*)d_in[4];
    const float* Wk    = (const float*)d_in[5];
    const float* Wv    = (const float*)d_in[6];
    const float* Wo    = (const float*)d_in[7];
    const float* gamma = (const float*)d_in[8];
    const float* beta  = (const float*)d_in[9];

    float* out  = (float*)d_out;                  // [B,S,D]
    float* attn = out + (size_t)BB * SS * DD;     // [B,H,S,S]

    cudaFuncSetAttribute(attn_kernel, cudaFuncAttributeMaxDynamicSharedMemorySize, ATTN_SMEM);
    cudaFuncSetAttribute(proj_kernel, cudaFuncAttributeMaxDynamicSharedMemorySize, PJ_SMEM);
    cudaFuncSetAttribute(out_proj_kernel, cudaFuncAttributeMaxDynamicSharedMemorySize, PJ_SMEM);

    wtrans_kernel<<<dim3(16, 16, 4), 256>>>(Wq, Wk, Wv, Wo);
    proj_kernel<<<dim3(DD/128, BSN/128, 3), 256, PJ_SMEM>>>(q, k, v);
    attn_kernel<<<dim3(SS/128, BH), 256, ATTN_SMEM>>>(mask, attn);
    out_proj_kernel<<<dim3(DD/128, BSN/128), 256, PJ_SMEM>>>(q);
    ln_kernel<<<BSN, 256>>>(gamma, beta, out);
}

// round 11
// speedup vs baseline: 3.4066x; 1.1399x over previous
#include <cuda_runtime.h>
#include <cuda_fp16.h>
#include <math.h>
#include <cstdint>

#define BB 4
#define SS 2048
#define DD 512
#define HH 8
#define BH (BB*HH)
#define BSN (BB*SS)

// ---------------- scratch (device globals; fp16x2 words) --------------------
__device__ unsigned g_qhw[(size_t)BH*SS*32];   // [bh, s, 32w]
__device__ unsigned g_khw[(size_t)BH*SS*32];
__device__ unsigned g_vhw[(size_t)BH*SS*32];
__device__ unsigned g_ohw[(size_t)BH*SS*32];
__device__ unsigned g_wtw[4*(size_t)DD*(DD/2)]; // W^T fp16x2, [n][k/2]
__device__ float    g_y[(size_t)BSN*DD];

// ---------------- helpers -----------------------------------------------------
__device__ __forceinline__ unsigned fppack(float lo, float hi) {
    __half2 h = __floats2half2_rn(lo, hi);
    return *reinterpret_cast<unsigned*>(&h);
}

__device__ __forceinline__ void mma_fp16(float c[4], unsigned a0, unsigned a1,
        unsigned a2, unsigned a3, unsigned b0, unsigned b1) {
    asm("mma.sync.aligned.m16n8k16.row.col.f32.f16.f16.f32 "
        "{%0,%1,%2,%3},{%4,%5,%6,%7},{%8,%9},{%0,%1,%2,%3};"
        : "+f"(c[0]), "+f"(c[1]), "+f"(c[2]), "+f"(c[3])
        : "r"(a0), "r"(a1), "r"(a2), "r"(a3), "r"(b0), "r"(b1));
}

__device__ __forceinline__ float fexp2(float x) {
    float y;
    asm("ex2.approx.f32 %0, %1;" : "=f"(y) : "f"(x));
    return y;
}
__device__ __forceinline__ float flog2(float x) {
    float y;
    asm("lg2.approx.f32 %0, %1;" : "=f"(y) : "f"(x));
    return y;
}
#define EXP_C 0.18033688011112042f   // log2(e)/8

// ---------------- kernel 0: transpose W -> fp16 (Wt[n][k] = W[k][n]) --------
__global__ __launch_bounds__(256) void wtrans_kernel(const float* __restrict__ Wq,
        const float* __restrict__ Wk, const float* __restrict__ Wv,
        const float* __restrict__ Wo) {
    __shared__ float tile[32][33];
    const float* W = (blockIdx.z == 0) ? Wq : (blockIdx.z == 1) ? Wk
                   : (blockIdx.z == 2) ? Wv : Wo;
    unsigned* T = g_wtw + (size_t)blockIdx.z * DD * (DD/2);
    const int x0 = blockIdx.x * 32, y0 = blockIdx.y * 32;
    const int tx = threadIdx.x & 31, ty = threadIdx.x >> 5;   // 32 x 8
    #pragma unroll
    for (int i = 0; i < 32; i += 8)
        tile[ty + i][tx] = W[(size_t)(y0 + ty + i) * DD + x0 + tx];
    __syncthreads();
    const int wc0 = threadIdx.x & 7, xx = threadIdx.x >> 3;   // 8 wc x 32 xx
    #pragma unroll
    for (int i = 0; i < 16; i += 8) {
        int wc = wc0 + i;
        T[(size_t)(x0 + xx) * (DD/2) + (y0 >> 1) + wc] =
            fppack(tile[2*wc][xx], tile[2*wc + 1][xx]);
    }
}

// ---------------- kernel 1: QKV projection (plain fp16 mma) ------------------
#define PJ_SMEM (2*128*36*4)

__global__ __launch_bounds__(256, 2) void proj_kernel(const float* __restrict__ q,
        const float* __restrict__ k, const float* __restrict__ v) {
    extern __shared__ unsigned ps[];
    unsigned* Ah = ps;              // [128][36] fp16x2 (X rows)
    unsigned* Bh = Ah + 128*36;     // [128][36] (Wt rows = output cols)

    const float* X; unsigned* Y;
    if (blockIdx.z == 0)      { X = q; Y = g_qhw; }
    else if (blockIdx.z == 1) { X = k; Y = g_khw; }
    else                      { X = v; Y = g_vhw; }
    const unsigned* Wt = g_wtw + (size_t)blockIdx.z * DD * (DD/2);

    const int row0 = blockIdx.y * 128, col0 = blockIdx.x * 128;
    const int tid = threadIdx.x, lane = tid & 31, warp = tid >> 5;
    const int g = lane >> 2, t = lane & 3;
    const int wm = warp & 3, wn = warp >> 2;

    const int fr = tid >> 3;            // 32 rows per sweep
    const int fcb = (tid & 7) << 3;     // 8-elem block
    const int fw = fcb >> 1;            // word offset (0,4,..,28)

    float acc[2][8][4] = {};

    for (int c = 0; c < 8; c++) {
        const int k0 = c * 64, kw0 = c * 32;
        __syncthreads();
        #pragma unroll
        for (int sw = 0; sw < 4; sw++) {
            int r = fr + sw * 32;
            {   // A = X rows (fp32 -> fp16)
                const float* src = X + (size_t)(row0 + r) * DD + k0 + fcb;
                float4 v0 = *(const float4*)src;
                float4 v1 = *(const float4*)(src + 4);
                *(uint4*)(Ah + r*36 + fw) = make_uint4(
                    fppack(v0.x, v0.y), fppack(v0.z, v0.w),
                    fppack(v1.x, v1.y), fppack(v1.z, v1.w));
            }
            *(uint4*)(Bh + r*36 + fw) =
                *(const uint4*)(Wt + (size_t)(col0 + r) * (DD/2) + kw0 + fw);
        }
        __syncthreads();
        #pragma unroll
        for (int s = 0; s < 4; s++) {
            const int kw = s * 8;
            unsigned a[2][4];
            #pragma unroll
            for (int mt = 0; mt < 2; mt++) {
                int r = wm * 32 + mt * 16 + g;
                a[mt][0] = Ah[r*36 + kw + t];       a[mt][1] = Ah[(r+8)*36 + kw + t];
                a[mt][2] = Ah[r*36 + kw + t + 4];   a[mt][3] = Ah[(r+8)*36 + kw + t + 4];
            }
            #pragma unroll
            for (int nt = 0; nt < 8; nt++) {
                int cc = wn * 64 + nt * 8 + g;
                unsigned b0 = Bh[cc*36 + kw + t], b1 = Bh[cc*36 + kw + t + 4];
                #pragma unroll
                for (int mt = 0; mt < 2; mt++)
                    mma_fp16(acc[mt][nt], a[mt][0], a[mt][1], a[mt][2], a[mt][3], b0, b1);
            }
        }
    }
    const int bidx = row0 >> 11;
    #pragma unroll
    for (int mt = 0; mt < 2; mt++) {
        int r0 = row0 + wm * 32 + mt * 16 + g;
        int s0 = r0 & 2047;
        #pragma unroll
        for (int nt = 0; nt < 8; nt++) {
            int col = col0 + wn * 64 + nt * 8 + 2 * t;
            int h = col >> 6, dkw = (col & 63) >> 1;
            Y[(((size_t)(bidx * HH + h) * SS + s0) << 5) + dkw]     = fppack(acc[mt][nt][0], acc[mt][nt][1]);
            Y[(((size_t)(bidx * HH + h) * SS + s0 + 8) << 5) + dkw] = fppack(acc[mt][nt][2], acc[mt][nt][3]);
        }
    }
}

// ---------------- kernel 2: fused attention (fp16 mma, folded epilogue) ------
// Pass 1 (j-tile 128): QK -> p = exp2(acc * prf*pm) -> rowsums.
// Pass 2 (j-tile 64): QK -> p = exp2(acc * prf*pm + linv) -> attn write + PV.
#define ATTN_WORDS (4608 + 4608 + 2304 + 4608 + 768)
#define ATTN_SMEM (ATTN_WORDS*4)

__global__ __launch_bounds__(256, 2) void attn_kernel(const int* __restrict__ mask,
                                                      float* __restrict__ attn) {
    extern __shared__ unsigned usm[];
    unsigned* Qh  = usm;                  // [128][36] fp16x2
    unsigned* Kh  = Qh + 4608;            // [128][36] (pass2 uses first 64 rows)
    unsigned* Vb  = Kh + 4608;            // [64 d][36 j'] transposed
    unsigned* Pb  = Vb + 2304;            // [128][36]
    float* rowsum = (float*)(Pb + 4608);  // 128
    float* linv   = rowsum + 128;         // 128  (-log2 rowsum)
    float* mrowf  = linv + 128;           // 128  (1.0 / 0.0)
    float* mcolf  = mrowf + 128;          // 128  (EXP_C / 0.0)

    const int bh = blockIdx.y, b = bh >> 3;
    const int row0 = blockIdx.x * 128;
    const int tid = threadIdx.x, lane = tid & 31, warp = tid >> 5;
    const int g = lane >> 2, t = lane & 3;
    const int wm = warp & 3, wn = warp >> 2;

    const unsigned* qbase = g_qhw + ((size_t)bh * SS << 5);
    const unsigned* kbase = g_khw + ((size_t)bh * SS << 5);
    const unsigned* vbase = g_vhw + ((size_t)bh * SS << 5);

    const int fr = tid >> 3;
    const int fw = (tid & 7) << 2;      // word offset 0..28

    // ---- load Q tile (fp16 copy; persists across both passes) ----
    #pragma unroll
    for (int sw = 0; sw < 4; sw++) {
        int r = fr + sw * 32;
        *(uint4*)(Qh + r*36 + fw) = *(const uint4*)(qbase + ((size_t)(row0 + r) << 5) + fw);
    }
    if (tid < 128) {
        mrowf[tid] = mask[b * SS + row0 + tid] ? 1.0f : 0.0f;
        rowsum[tid] = 0.f;
    }

    float rp0[2] = {0.f, 0.f};
    float rp1[2] = {0.f, 0.f};

    // ---------------- PASS 1 (j-tile 128): rowsums --------------------------
    #pragma unroll 1
    for (int j0 = 0; j0 < SS; j0 += 128) {
        __syncthreads();
        #pragma unroll
        for (int sw = 0; sw < 4; sw++) {
            int r = fr + sw * 32;
            *(uint4*)(Kh + r*36 + fw) = *(const uint4*)(kbase + ((size_t)(j0 + r) << 5) + fw);
        }
        if (tid < 128) mcolf[tid] = mask[b * SS + j0 + tid] ? EXP_C : 0.0f;
        __syncthreads();

        float acc[2][8][4] = {};
        #pragma unroll
        for (int s = 0; s < 4; s++) {
            int kw = s * 8;
            unsigned a[2][4];
            #pragma unroll
            for (int mt = 0; mt < 2; mt++) {
                int r = wm * 32 + mt * 16 + g;
                a[mt][0] = Qh[r*36 + kw + t];        a[mt][1] = Qh[(r+8)*36 + kw + t];
                a[mt][2] = Qh[r*36 + kw + t + 4];    a[mt][3] = Qh[(r+8)*36 + kw + t + 4];
            }
            #pragma unroll
            for (int nt = 0; nt < 8; nt++) {
                int c = wn * 64 + nt * 8 + g;
                unsigned b0 = Kh[c*36 + kw + t], b1 = Kh[c*36 + kw + t + 4];
                #pragma unroll
                for (int mt = 0; mt < 2; mt++)
                    mma_fp16(acc[mt][nt], a[mt][0], a[mt][1], a[mt][2], a[mt][3], b0, b1);
            }
        }
        const bool dtile = (j0 == row0);
        #pragma unroll
        for (int mt = 0; mt < 2; mt++) {
            int lr0 = wm * 32 + mt * 16 + g, lr1 = lr0 + 8;
            float pr0 = mrowf[lr0], pr1 = mrowf[lr1];
            int gr0 = row0 + lr0, gr1 = row0 + lr1;
            #pragma unroll
            for (int nt = 0; nt < 8; nt++) {
                int lc = wn * 64 + nt * 8 + 2 * t;
                float pm0 = mcolf[lc], pm1 = mcolf[lc + 1];
                float f00 = pr0 * pm0, f01 = pr0 * pm1;
                float f10 = pr1 * pm0, f11 = pr1 * pm1;
                if (dtile) {
                    int gc = j0 + lc;
                    if (gr0 == gc)     f00 = EXP_C;
                    if (gr0 == gc + 1) f01 = EXP_C;
                    if (gr1 == gc)     f10 = EXP_C;
                    if (gr1 == gc + 1) f11 = EXP_C;
                }
                float p00 = fexp2(acc[mt][nt][0] * f00);
                float p01 = fexp2(acc[mt][nt][1] * f01);
                float p10 = fexp2(acc[mt][nt][2] * f10);
                float p11 = fexp2(acc[mt][nt][3] * f11);
                rp0[mt] += p00 + p01;
                rp1[mt] += p10 + p11;
            }
        }
    }
    #pragma unroll
    for (int mt = 0; mt < 2; mt++) {
        float s0 = rp0[mt], s1 = rp1[mt];
        s0 += __shfl_xor_sync(0xffffffffu, s0, 1); s0 += __shfl_xor_sync(0xffffffffu, s0, 2);
        s1 += __shfl_xor_sync(0xffffffffu, s1, 1); s1 += __shfl_xor_sync(0xffffffffu, s1, 2);
        if (t == 0) {
            atomicAdd(&rowsum[wm * 32 + mt * 16 + g], s0);
            atomicAdd(&rowsum[wm * 32 + mt * 16 + g + 8], s1);
        }
    }
    __syncthreads();
    if (tid < 128) linv[tid] = -flog2(rowsum[tid]);

    float oacc[2][4][4] = {};
    float* arow = attn + ((size_t)bh * SS + row0) * SS;

    const int vjp = tid & 31;           // j' = j/2
    const int vd0 = (tid >> 5) << 3;    // d block of 8 (4 words)

    // ---------------- PASS 2 (j-tile 64): attn write + PV -------------------
    #pragma unroll 1
    for (int j0 = 0; j0 < SS; j0 += 64) {
        __syncthreads();
        #pragma unroll
        for (int sw = 0; sw < 2; sw++) {
            int r = fr + sw * 32;
            *(uint4*)(Kh + r*36 + fw) = *(const uint4*)(kbase + ((size_t)(j0 + r) << 5) + fw);
        }
        {   // V tile transposed via PRMT: Vb[d][j'] = (v[2j'][d], v[2j'+1][d])
            uint4 ea = *(const uint4*)(vbase + ((size_t)(j0 + 2*vjp)     << 5) + (vd0 >> 1));
            uint4 eb = *(const uint4*)(vbase + ((size_t)(j0 + 2*vjp + 1) << 5) + (vd0 >> 1));
            unsigned wa[4] = {ea.x, ea.y, ea.z, ea.w};
            unsigned wb[4] = {eb.x, eb.y, eb.z, eb.w};
            #pragma unroll
            for (int i = 0; i < 4; i++) {
                Vb[(vd0 + 2*i)     * 36 + vjp] = __byte_perm(wa[i], wb[i], 0x5410);
                Vb[(vd0 + 2*i + 1) * 36 + vjp] = __byte_perm(wa[i], wb[i], 0x7632);
            }
        }
        if (tid < 64) mcolf[tid] = mask[b * SS + j0 + tid] ? EXP_C : 0.0f;
        __syncthreads();

        float acc[2][4][4] = {};
        #pragma unroll
        for (int s = 0; s < 4; s++) {
            int kw = s * 8;
            unsigned a[2][4];
            #pragma unroll
            for (int mt = 0; mt < 2; mt++) {
                int r = wm * 32 + mt * 16 + g;
                a[mt][0] = Qh[r*36 + kw + t];        a[mt][1] = Qh[(r+8)*36 + kw + t];
                a[mt][2] = Qh[r*36 + kw + t + 4];    a[mt][3] = Qh[(r+8)*36 + kw + t + 4];
            }
            #pragma unroll
            for (int nt = 0; nt < 4; nt++) {
                int c = wn * 32 + nt * 8 + g;
                unsigned b0 = Kh[c*36 + kw + t], b1 = Kh[c*36 + kw + t + 4];
                #pragma unroll
                for (int mt = 0; mt < 2; mt++)
                    mma_fp16(acc[mt][nt], a[mt][0], a[mt][1], a[mt][2], a[mt][3], b0, b1);
            }
        }
        const bool dtile = ((unsigned)(j0 - row0) < 128u);
        #pragma unroll
        for (int mt = 0; mt < 2; mt++) {
            int lr0 = wm * 32 + mt * 16 + g, lr1 = lr0 + 8;
            float pr0 = mrowf[lr0], pr1 = mrowf[lr1];
            float li0 = linv[lr0], li1 = linv[lr1];
            int gr0 = row0 + lr0, gr1 = row0 + lr1;
            #pragma unroll
            for (int nt = 0; nt < 4; nt++) {
                int lc = wn * 32 + nt * 8 + 2 * t;
                float pm0 = mcolf[lc], pm1 = mcolf[lc + 1];
                float f00 = pr0 * pm0, f01 = pr0 * pm1;
                float f10 = pr1 * pm0, f11 = pr1 * pm1;
                if (dtile) {
                    int gc = j0 + lc;
                    if (gr0 == gc)     f00 = EXP_C;
                    if (gr0 == gc + 1) f01 = EXP_C;
                    if (gr1 == gc)     f10 = EXP_C;
                    if (gr1 == gc + 1) f11 = EXP_C;
                }
                float p00 = fexp2(fmaf(acc[mt][nt][0], f00, li0));
                float p01 = fexp2(fmaf(acc[mt][nt][1], f01, li0));
                float p10 = fexp2(fmaf(acc[mt][nt][2], f10, li1));
                float p11 = fexp2(fmaf(acc[mt][nt][3], f11, li1));
                int gc = j0 + lc;
                *(float2*)(arow + (size_t)lr0 * SS + gc) = make_float2(p00, p01);
                *(float2*)(arow + (size_t)lr1 * SS + gc) = make_float2(p10, p11);
                Pb[lr0 * 36 + (lc >> 1)] = fppack(p00, p01);
                Pb[lr1 * 36 + (lc >> 1)] = fppack(p10, p11);
            }
        }
        __syncthreads();
        #pragma unroll
        for (int s = 0; s < 4; s++) {
            int kw = s * 8;
            unsigned a[2][4];
            #pragma unroll
            for (int mt = 0; mt < 2; mt++) {
                int r = wm * 32 + mt * 16 + g;
                a[mt][0] = Pb[r * 36 + kw + t];        a[mt][1] = Pb[(r + 8) * 36 + kw + t];
                a[mt][2] = Pb[r * 36 + kw + t + 4];    a[mt][3] = Pb[(r + 8) * 36 + kw + t + 4];
            }
            #pragma unroll
            for (int nt = 0; nt < 4; nt++) {
                int c = wn * 32 + nt * 8 + g;
                unsigned b0 = Vb[c * 36 + kw + t], b1 = Vb[c * 36 + kw + t + 4];
                #pragma unroll
                for (int mt = 0; mt < 2; mt++)
                    mma_fp16(oacc[mt][nt], a[mt][0], a[mt][1], a[mt][2], a[mt][3], b0, b1);
            }
        }
    }
    unsigned* obase = g_ohw + (((size_t)bh * SS + row0) << 5);
    #pragma unroll
    for (int mt = 0; mt < 2; mt++) {
        int lr0 = wm * 32 + mt * 16 + g, lr1 = lr0 + 8;
        #pragma unroll
        for (int nt = 0; nt < 4; nt++) {
            int lc = wn * 32 + nt * 8 + 2 * t;
            obase[((size_t)lr0 << 5) + (lc >> 1)] = fppack(oacc[mt][nt][0], oacc[mt][nt][1]);
            obase[((size_t)lr1 << 5) + (lc >> 1)] = fppack(oacc[mt][nt][2], oacc[mt][nt][3]);
        }
    }
}

// ---------------- kernel 3: O @ Wo + residual (plain fp16 mma) ---------------
__global__ __launch_bounds__(256, 2) void out_proj_kernel(const float* __restrict__ q) {
    extern __shared__ unsigned ps[];
    unsigned* Ah = ps;              // [128][36] (O rows, head-gathered)
    unsigned* Bh = Ah + 128*36;     // [128][36] (WoT rows)

    const unsigned* WoT = g_wtw + 3 * (size_t)DD * (DD/2);

    const int row0 = blockIdx.y * 128, col0 = blockIdx.x * 128;
    const int tid = threadIdx.x, lane = tid & 31, warp = tid >> 5;
    const int g = lane >> 2, t = lane & 3;
    const int wm = warp & 3, wn = warp >> 2;

    const int bidx = row0 >> 11, srow0 = row0 & 2047;

    const int fr = tid >> 3;
    const int fw = (tid & 7) << 2;

    float acc[2][8][4] = {};

    for (int c = 0; c < 8; c++) {
        const int kw0 = c * 32;
        __syncthreads();
        #pragma unroll
        for (int sw = 0; sw < 4; sw++) {
            int r = fr + sw * 32;
            *(uint4*)(Ah + r*36 + fw) = *(const uint4*)(g_ohw +
                (((size_t)(bidx * HH + c) * SS + srow0 + r) << 5) + fw);
            *(uint4*)(Bh + r*36 + fw) =
                *(const uint4*)(WoT + (size_t)(col0 + r) * (DD/2) + kw0 + fw);
        }
        __syncthreads();
        #pragma unroll
        for (int s = 0; s < 4; s++) {
            const int kw = s * 8;
            unsigned a[2][4];
            #pragma unroll
            for (int mt = 0; mt < 2; mt++) {
                int r = wm * 32 + mt * 16 + g;
                a[mt][0] = Ah[r*36 + kw + t];       a[mt][1] = Ah[(r+8)*36 + kw + t];
                a[mt][2] = Ah[r*36 + kw + t + 4];   a[mt][3] = Ah[(r+8)*36 + kw + t + 4];
            }
            #pragma unroll
            for (int nt = 0; nt < 8; nt++) {
                int cc = wn * 64 + nt * 8 + g;
                unsigned b0 = Bh[cc*36 + kw + t], b1 = Bh[cc*36 + kw + t + 4];
                #pragma unroll
                for (int mt = 0; mt < 2; mt++)
                    mma_fp16(acc[mt][nt], a[mt][0], a[mt][1], a[mt][2], a[mt][3], b0, b1);
            }
        }
    }
    #pragma unroll
    for (int mt = 0; mt < 2; mt++) {
        int r0 = row0 + wm * 32 + mt * 16 + g;
        #pragma unroll
        for (int nt = 0; nt < 8; nt++) {
            int col = col0 + wn * 64 + nt * 8 + 2 * t;
            size_t off0 = (size_t)r0 * DD + col;
            size_t off1 = (size_t)(r0 + 8) * DD + col;
            float2 q0 = *(const float2*)(q + off0);
            float2 q1 = *(const float2*)(q + off1);
            *(float2*)(g_y + off0) = make_float2(acc[mt][nt][0] + q0.x, acc[mt][nt][1] + q0.y);
            *(float2*)(g_y + off1) = make_float2(acc[mt][nt][2] + q1.x, acc[mt][nt][3] + q1.y);
        }
    }
}

// ---------------- kernel 4: LayerNorm ---------------------------------------
__global__ void ln_kernel(const float* __restrict__ gamma, const float* __restrict__ beta,
                          float* __restrict__ out) {
    const int row = blockIdx.x;
    const float* x = g_y + (size_t)row * DD;
    const int t = threadIdx.x;

    float v0 = x[t], v1 = x[t + 256];
    float s  = v0 + v1;
    float sq = v0 * v0 + v1 * v1;

    __shared__ float ssum[8], ssq[8];
    #pragma unroll
    for (int off = 16; off > 0; off >>= 1) {
        s  += __shfl_down_sync(0xffffffffu, s,  off);
        sq += __shfl_down_sync(0xffffffffu, sq, off);
    }
    if ((t & 31) == 0) { ssum[t >> 5] = s; ssq[t >> 5] = sq; }
    __syncthreads();
    if (t < 32) {
        float a = (t < 8) ? ssum[t] : 0.f;
        float b = (t < 8) ? ssq[t]  : 0.f;
        #pragma unroll
        for (int off = 4; off > 0; off >>= 1) {
            a += __shfl_down_sync(0xffffffffu, a, off);
            b += __shfl_down_sync(0xffffffffu, b, off);
        }
        if (t == 0) { ssum[0] = a; ssq[0] = b; }
    }
    __syncthreads();
    float mean = ssum[0] * (1.0f / DD);
    float var  = ssq[0]  * (1.0f / DD) - mean * mean;
    float rs   = rsqrtf(var + 1e-6f);

    out[(size_t)row * DD + t]       = (v0 - mean) * rs * gamma[t]       + beta[t];
    out[(size_t)row * DD + t + 256] = (v1 - mean) * rs * gamma[t + 256] + beta[t + 256];
}

// ---------------- launch -----------------------------------------------------
extern "C" void kernel_launch(void* const* d_in, const int* in_sizes, int n_in,
                              void* d_out, int out_size) {
    const float* q     = (const float*)d_in[0];
    const float* k     = (const float*)d_in[1];
    const float* v     = (const float*)d_in[2];
    const int*   mask  = (const int*)  d_in[3];
    const float* Wq    = (const float*)d_in[4];
    const float* Wk    = (const float*)d_in[5];
    const float* Wv    = (const float*)d_in[6];
    const float* Wo    = (const float*)d_in[7];
    const float* gamma = (const float*)d_in[8];
    const float* beta  = (const float*)d_in[9];

    float* out  = (float*)d_out;                  // [B,S,D]
    float* attn = out + (size_t)BB * SS * DD;     // [B,H,S,S]

    cudaFuncSetAttribute(attn_kernel, cudaFuncAttributeMaxDynamicSharedMemorySize, ATTN_SMEM);
    cudaFuncSetAttribute(proj_kernel, cudaFuncAttributeMaxDynamicSharedMemorySize, PJ_SMEM);
    cudaFuncSetAttribute(out_proj_kernel, cudaFuncAttributeMaxDynamicSharedMemorySize, PJ_SMEM);

    wtrans_kernel<<<dim3(16, 16, 4), 256>>>(Wq, Wk, Wv, Wo);
    proj_kernel<<<dim3(DD/128, BSN/128, 3), 256, PJ_SMEM>>>(q, k, v);
    attn_kernel<<<dim3(SS/128, BH), 256, ATTN_SMEM>>>(mask, attn);
    out_proj_kernel<<<dim3(DD/128, BSN/128), 256, PJ_SMEM>>>(q);
    ln_kernel<<<BSN, 256>>>(gamma, beta, out);
}